// round 1
// baseline (speedup 1.0000x reference)
#include <cuda_runtime.h>
#include <math.h>

#define E_N     20000
#define KSEL    20
#define D_      128
#define F1_     512
#define F2_     128
#define NT_     2
#define NNODES  200000
#define NEDGES  500000
#define EPSV    1e-5f

// Scratch (allocation-free rule: __device__ globals)
static __device__ float g_Pn[(size_t)NNODES * F1_];   // memory @ fc1_w[0:128]
static __device__ float g_Pe[(size_t)NEDGES * F1_];   // edge_tbl @ fc1_w[128:256]
static __device__ float g_g [(size_t)NT_ * E_N * F1_]; // weighted relu(LN(h1)) per (branch,e)
static __device__ float g_flag[NT_ * E_N];             // ws>0 indicator

// ---------------------------------------------------------------------------
// C[N,512] = A[N,128] @ W (W row-stride 512). which: 0 -> g_Pn, 1 -> g_Pe
// Tiled SGEMM: BM=64, BN=64, BK=32, 256 threads, 4x4 microtile, float4 smem.
// ---------------------------------------------------------------------------
__global__ void __launch_bounds__(256) k_pre(const float* __restrict__ A,
                                             const float* __restrict__ W,
                                             int N, int which) {
    __shared__ float As[32][68];  // [k][m], pad 68 keeps float4 alignment (272B)
    __shared__ float Bs[32][68];  // [k][n]
    float* __restrict__ C = which ? g_Pe : g_Pn;
    const int tid = threadIdx.x;
    const int m0 = blockIdx.x * 64;
    const int n0 = blockIdx.y * 64;
    const int ty = tid >> 4, tx = tid & 15;

    float acc[4][4];
#pragma unroll
    for (int i = 0; i < 4; i++)
#pragma unroll
        for (int j = 0; j < 4; j++) acc[i][j] = 0.f;

    for (int kc = 0; kc < 128; kc += 32) {
#pragma unroll
        for (int it = 0; it < 2; it++) {            // A tile: 64 rows x 32 k
            int i = tid + it * 256;
            int r = i >> 3, q = i & 7;
            int grow = m0 + r;
            float4 v = make_float4(0.f, 0.f, 0.f, 0.f);
            if (grow < N) v = *(const float4*)(A + (size_t)grow * 128 + kc + q * 4);
            As[q * 4 + 0][r] = v.x;
            As[q * 4 + 1][r] = v.y;
            As[q * 4 + 2][r] = v.z;
            As[q * 4 + 3][r] = v.w;
        }
#pragma unroll
        for (int it = 0; it < 2; it++) {            // B tile: 32 k x 64 n
            int i = tid + it * 256;
            int kk = i >> 4, q = i & 15;
            float4 v = *(const float4*)(W + (size_t)(kc + kk) * 512 + n0 + q * 4);
            *(float4*)&Bs[kk][q * 4] = v;
        }
        __syncthreads();
#pragma unroll
        for (int k = 0; k < 32; k++) {
            float4 a4 = *(const float4*)&As[k][ty * 4];
            float4 b4 = *(const float4*)&Bs[k][tx * 4];
            float a_[4] = {a4.x, a4.y, a4.z, a4.w};
            float b_[4] = {b4.x, b4.y, b4.z, b4.w};
#pragma unroll
            for (int i = 0; i < 4; i++)
#pragma unroll
                for (int j = 0; j < 4; j++) acc[i][j] += a_[i] * b_[j];
        }
        __syncthreads();
    }
#pragma unroll
    for (int i = 0; i < 4; i++) {
        int grow = m0 + ty * 4 + i;
        if (grow < N)
            *(float4*)(C + (size_t)grow * 512 + n0 + tx * 4) =
                make_float4(acc[i][0], acc[i][1], acc[i][2], acc[i][3]);
    }
}

// ---------------------------------------------------------------------------
// Per (branch, e): h1 = Pn[node] + Pe[edge] + te@W1t + b1 ; LN ; relu ;
// g[e,:] = sum_k wnorm_k * relu_h_k.   One block per (e, branch), 256 threads,
// each thread owns 2 of the 512 columns across all K=20 rows.
// ---------------------------------------------------------------------------
__global__ void __launch_bounds__(256) k_branch(
    const float* __restrict__ sel_dt, const float* __restrict__ sel_w,
    const float* __restrict__ time_w, const float* __restrict__ time_b,
    const float* __restrict__ fc1_w, const float* __restrict__ fc1_b,
    const float* __restrict__ ln1_g, const float* __restrict__ ln1_b,
    const int* __restrict__ sel_nodes, const int* __restrict__ sel_edges) {
    const int e = blockIdx.x, br = blockIdx.y;
    const int tid = threadIdx.x;
    __shared__ float te[KSEL][100];           // 100*4B rows -> float4-aligned
    __shared__ float tw[100], tb[100];
    __shared__ float dt_s[KSEL], wn[KSEL];
    __shared__ int   nd_s[KSEL], ed_s[KSEL];
    __shared__ float red_s[KSEL][8], red_q[KSEL][8];
    __shared__ float mu_s[KSEL], rs_s[KSEL];
    __shared__ float ws_s, flag_s;

    const size_t base = ((size_t)br * E_N + e) * KSEL;
    if (tid < 100) { tw[tid] = time_w[tid]; tb[tid] = time_b[tid]; }
    if (tid >= 128 && tid < 128 + KSEL) {
        int k = tid - 128;
        dt_s[k] = sel_dt[base + k];
        wn[k]   = sel_w[base + k];
        nd_s[k] = sel_nodes[base + k];
        ed_s[k] = sel_edges[base + k];
    }
    __syncthreads();
    if (tid == 0) {
        float ws = 0.f;
        for (int k = 0; k < KSEL; k++) ws += wn[k];
        ws_s = ws;
        flag_s = (ws > 0.f) ? 1.f : 0.f;
    }
    for (int i = tid; i < KSEL * 100; i += 256) {
        int k = i / 100, j = i - k * 100;
        te[k][j] = __cosf(dt_s[k] * tw[j] + tb[j]);
    }
    __syncthreads();
    if (tid < KSEL) wn[tid] = (flag_s > 0.f) ? wn[tid] / ws_s : 0.f;

    const int c0 = tid * 2;
    float2 acc[KSEL];
    const float2 b1v = *(const float2*)(fc1_b + c0);
#pragma unroll
    for (int k = 0; k < KSEL; k++) {
        float2 pn = *(const float2*)(g_Pn + (size_t)nd_s[k] * 512 + c0);
        float2 pe = *(const float2*)(g_Pe + (size_t)ed_s[k] * 512 + c0);
        acc[k].x = pn.x + pe.x + b1v.x;
        acc[k].y = pn.y + pe.y + b1v.y;
    }
    const float* __restrict__ W1t = fc1_w + (size_t)256 * 512;
    for (int j = 0; j < 100; j += 4) {
        float2 w0 = *(const float2*)(W1t + (size_t)(j + 0) * 512 + c0);
        float2 w1 = *(const float2*)(W1t + (size_t)(j + 1) * 512 + c0);
        float2 w2 = *(const float2*)(W1t + (size_t)(j + 2) * 512 + c0);
        float2 w3 = *(const float2*)(W1t + (size_t)(j + 3) * 512 + c0);
#pragma unroll
        for (int k = 0; k < KSEL; k++) {
            float4 t = *(const float4*)&te[k][j];
            acc[k].x += t.x * w0.x + t.y * w1.x + t.z * w2.x + t.w * w3.x;
            acc[k].y += t.x * w0.y + t.y * w1.y + t.z * w2.y + t.w * w3.y;
        }
    }
    // LayerNorm stats per row (sum & sumsq over the 512 cols)
    const int lane = tid & 31, warp = tid >> 5;
#pragma unroll
    for (int k = 0; k < KSEL; k++) {
        float s = acc[k].x + acc[k].y;
        float q = acc[k].x * acc[k].x + acc[k].y * acc[k].y;
#pragma unroll
        for (int o = 16; o > 0; o >>= 1) {
            s += __shfl_down_sync(0xffffffffu, s, o);
            q += __shfl_down_sync(0xffffffffu, q, o);
        }
        if (lane == 0) { red_s[k][warp] = s; red_q[k][warp] = q; }
    }
    __syncthreads();
    if (tid < KSEL) {
        float s = 0.f, q = 0.f;
#pragma unroll
        for (int w = 0; w < 8; w++) { s += red_s[tid][w]; q += red_q[tid][w]; }
        float mu = s * (1.f / 512.f);
        float var = q * (1.f / 512.f) - mu * mu;
        mu_s[tid] = mu;
        rs_s[tid] = rsqrtf(var + EPSV);
    }
    __syncthreads();
    const float lg0 = ln1_g[c0], lg1 = ln1_g[c0 + 1];
    const float lb0 = ln1_b[c0], lb1 = ln1_b[c0 + 1];
    float o0 = 0.f, o1 = 0.f;
#pragma unroll
    for (int k = 0; k < KSEL; k++) {
        float h0 = fmaxf((acc[k].x - mu_s[k]) * rs_s[k] * lg0 + lb0, 0.f);
        float h1 = fmaxf((acc[k].y - mu_s[k]) * rs_s[k] * lg1 + lb1, 0.f);
        o0 += wn[k] * h0;
        o1 += wn[k] * h1;
    }
    *(float2*)(g_g + ((size_t)br * E_N + e) * 512 + c0) = make_float2(o0, o1);
    if (tid == 0) g_flag[br * E_N + e] = flag_s;
}

// ---------------------------------------------------------------------------
// Source branch: mem[src] @ fc1s_w -> BN(eval) -> relu -> @ fc2s_w.
// 16 rows per block, fully fused through shared memory.
// ---------------------------------------------------------------------------
__global__ void __launch_bounds__(256) k_src(
    const float* __restrict__ memory,
    const float* __restrict__ fc1s_w, const float* __restrict__ fc1s_b,
    const float* __restrict__ bn_g, const float* __restrict__ bn_b,
    const float* __restrict__ bn_m, const float* __restrict__ bn_v,
    const float* __restrict__ fc2s_w, const float* __restrict__ fc2s_b,
    const int* __restrict__ src, float* __restrict__ out) {
    __shared__ float A[16][128];
    __shared__ float H[16][512];
    __shared__ int nd[16];
    const int tid = threadIdx.x;
    const int e0 = blockIdx.x * 16;
    if (tid < 16) nd[tid] = src[e0 + tid];
    __syncthreads();
    for (int i = tid; i < 16 * 32; i += 256) {
        int r = i >> 5, q = i & 31;
        *(float4*)&A[r][q * 4] = *(const float4*)(memory + (size_t)nd[r] * 128 + q * 4);
    }
    __syncthreads();

    const int c0 = tid * 2;
    float2 acc[16];
#pragma unroll
    for (int r = 0; r < 16; r++) acc[r] = make_float2(0.f, 0.f);
    for (int k = 0; k < 128; k += 4) {
        float2 w0 = *(const float2*)(fc1s_w + (size_t)(k + 0) * 512 + c0);
        float2 w1 = *(const float2*)(fc1s_w + (size_t)(k + 1) * 512 + c0);
        float2 w2 = *(const float2*)(fc1s_w + (size_t)(k + 2) * 512 + c0);
        float2 w3 = *(const float2*)(fc1s_w + (size_t)(k + 3) * 512 + c0);
#pragma unroll
        for (int r = 0; r < 16; r++) {
            float4 a = *(const float4*)&A[r][k];
            acc[r].x += a.x * w0.x + a.y * w1.x + a.z * w2.x + a.w * w3.x;
            acc[r].y += a.x * w0.y + a.y * w1.y + a.z * w2.y + a.w * w3.y;
        }
    }
    const float b0 = fc1s_b[c0], b1 = fc1s_b[c0 + 1];
    const float s0 = bn_g[c0] * rsqrtf(bn_v[c0] + EPSV);
    const float s1 = bn_g[c0 + 1] * rsqrtf(bn_v[c0 + 1] + EPSV);
    const float m0 = bn_m[c0], m1 = bn_m[c0 + 1];
    const float bb0 = bn_b[c0], bb1 = bn_b[c0 + 1];
#pragma unroll
    for (int r = 0; r < 16; r++) {
        H[r][c0]     = fmaxf((acc[r].x + b0 - m0) * s0 + bb0, 0.f);
        H[r][c0 + 1] = fmaxf((acc[r].y + b1 - m1) * s1 + bb1, 0.f);
    }
    __syncthreads();

    const int col = tid & 127, rg = tid >> 7;
    float o[8];
#pragma unroll
    for (int r = 0; r < 8; r++) o[r] = 0.f;
    for (int k = 0; k < 512; k += 4) {
        float w0 = fc2s_w[(size_t)(k + 0) * 128 + col];
        float w1 = fc2s_w[(size_t)(k + 1) * 128 + col];
        float w2 = fc2s_w[(size_t)(k + 2) * 128 + col];
        float w3 = fc2s_w[(size_t)(k + 3) * 128 + col];
#pragma unroll
        for (int r = 0; r < 8; r++) {
            float4 h = *(const float4*)&H[rg * 8 + r][k];
            o[r] += h.x * w0 + h.y * w1 + h.z * w2 + h.w * w3;
        }
    }
    const float bc = fc2s_b[col];
#pragma unroll
    for (int r = 0; r < 8; r++) {
        int e = e0 + rg * 8 + r;
        out[(size_t)e * 384 + col] = o[r] + bc;
    }
}

// ---------------------------------------------------------------------------
// Branch output: out_branch = g @ fc2_w + fc2_b * flag. 16 rows per block.
// ---------------------------------------------------------------------------
__global__ void __launch_bounds__(256) k_out(
    const float* __restrict__ fc2_w, const float* __restrict__ fc2_b,
    float* __restrict__ out) {
    const int br = blockIdx.y;
    const int e0 = blockIdx.x * 16;
    __shared__ float gs[16][512];
    const int tid = threadIdx.x;
    for (int i = tid; i < 16 * 128; i += 256) {
        int r = i >> 7, q = i & 127;
        *(float4*)&gs[r][q * 4] =
            *(const float4*)(g_g + ((size_t)br * E_N + e0 + r) * 512 + q * 4);
    }
    __syncthreads();
    const int col = tid & 127, rg = tid >> 7;
    float o[8];
#pragma unroll
    for (int r = 0; r < 8; r++) o[r] = 0.f;
    for (int k = 0; k < 512; k += 4) {
        float w0 = fc2_w[(size_t)(k + 0) * 128 + col];
        float w1 = fc2_w[(size_t)(k + 1) * 128 + col];
        float w2 = fc2_w[(size_t)(k + 2) * 128 + col];
        float w3 = fc2_w[(size_t)(k + 3) * 128 + col];
#pragma unroll
        for (int r = 0; r < 8; r++) {
            float4 g4 = *(const float4*)&gs[rg * 8 + r][k];
            o[r] += g4.x * w0 + g4.y * w1 + g4.z * w2 + g4.w * w3;
        }
    }
    const float bc = fc2_b[col];
#pragma unroll
    for (int r = 0; r < 8; r++) {
        int e = e0 + rg * 8 + r;
        out[(size_t)e * 384 + 128 + br * 128 + col] = o[r] + bc * g_flag[br * E_N + e];
    }
}

// ---------------------------------------------------------------------------
extern "C" void kernel_launch(void* const* d_in, const int* in_sizes, int n_in,
                              void* d_out, int out_size) {
    const float* memory    = (const float*)d_in[0];
    const float* edge_feat = (const float*)d_in[1];
    const float* sel_dt    = (const float*)d_in[2];
    const float* sel_w     = (const float*)d_in[3];
    const float* time_w    = (const float*)d_in[4];
    const float* time_b    = (const float*)d_in[5];
    const float* fc1_w     = (const float*)d_in[6];
    const float* fc1_b     = (const float*)d_in[7];
    const float* ln1_g     = (const float*)d_in[8];
    const float* ln1_b     = (const float*)d_in[9];
    const float* fc2_w     = (const float*)d_in[10];
    const float* fc2_b     = (const float*)d_in[11];
    const float* fc1s_w    = (const float*)d_in[12];
    const float* fc1s_b    = (const float*)d_in[13];
    const float* bn_g      = (const float*)d_in[14];
    const float* bn_b      = (const float*)d_in[15];
    const float* bn_m      = (const float*)d_in[16];
    const float* bn_v      = (const float*)d_in[17];
    const float* fc2s_w    = (const float*)d_in[18];
    const float* fc2s_b    = (const float*)d_in[19];
    const int* source_nodes = (const int*)d_in[20];
    const int* sel_nodes    = (const int*)d_in[21];
    const int* sel_edges    = (const int*)d_in[22];
    float* out = (float*)d_out;

    // Precompute node/edge projections through fc1 (shared across branches)
    k_pre<<<dim3((NNODES + 63) / 64, 8), 256>>>(memory, fc1_w, NNODES, 0);
    k_pre<<<dim3((NEDGES + 63) / 64, 8), 256>>>(edge_feat, fc1_w + (size_t)128 * 512,
                                                NEDGES, 1);
    // Source branch (independent)
    k_src<<<E_N / 16, 256>>>(memory, fc1s_w, fc1s_b, bn_g, bn_b, bn_m, bn_v,
                             fc2s_w, fc2s_b, source_nodes, out);
    // TPPR branches: gather + time GEMM + LN + relu + weighted K-reduce
    k_branch<<<dim3(E_N, NT_), 256>>>(sel_dt, sel_w, time_w, time_b,
                                      fc1_w, fc1_b, ln1_g, ln1_b,
                                      sel_nodes, sel_edges);
    // Branch fc2 + bias (with zero-weight-row handling) into output
    k_out<<<dim3(E_N / 16, NT_), 256>>>(fc2_w, fc2_b, out);
}

// round 4
// speedup vs baseline: 1.3771x; 1.3771x over previous
#include <cuda_runtime.h>
#include <math.h>
#include <cstdint>

#define E_N     20000
#define KSEL    20
#define D_      128
#define F1_     512
#define F2_     128
#define NT_     2
#define NNODES  200000
#define NEDGES  500000
#define EPSV    1e-5f

// Scratch (allocation-free rule: __device__ globals)
static __device__ float g_Pn[(size_t)NNODES * F1_];   // memory @ fc1_w[0:128]
static __device__ float g_Pe[(size_t)NEDGES * F1_];   // edge_tbl @ fc1_w[128:256]
static __device__ float g_g [(size_t)NT_ * E_N * F1_];
static __device__ float g_flag[NT_ * E_N];

__device__ __forceinline__ float to_tf32(float x) {
    float r;
    asm("cvt.rna.tf32.f32 %0, %1;" : "=f"(r) : "f"(x));
    return r;
}
__device__ __forceinline__ void mma_tf32(float* c, const uint32_t* a, const uint32_t* b) {
    asm volatile("mma.sync.aligned.m16n8k8.row.col.f32.tf32.tf32.f32 "
                 "{%0,%1,%2,%3}, {%4,%5,%6,%7}, {%8,%9}, {%0,%1,%2,%3};"
                 : "+f"(c[0]), "+f"(c[1]), "+f"(c[2]), "+f"(c[3])
                 : "r"(a[0]), "r"(a[1]), "r"(a[2]), "r"(a[3]),
                   "r"(b[0]), "r"(b[1]));
}

// ---------------------------------------------------------------------------
// Tensor-core (mma.sync tf32) k_pre:
// C[N,512] tile (64m x 128n) = A[64,128] @ W[128, n-tile 128].
// K=128 fully resident in SMEM. 8 warps = 2(M) x 4(N); warp tile 32x32.
// A smem stride 132, B smem stride 136 -> conflict-free fragment loads.
// 103.4 KB smem -> 2 CTAs/SM for load/compute overlap across CTAs.
// ---------------------------------------------------------------------------
#define PRE_SMEM (64 * 132 * 4 + 128 * 136 * 4)

__global__ void __launch_bounds__(256, 2) k_pre_mma(const float* __restrict__ A,
                                                    const float* __restrict__ W,
                                                    int N, int which) {
    extern __shared__ char smem[];
    float (*As)[132] = (float(*)[132])smem;
    float (*Bs)[136] = (float(*)[136])(smem + 64 * 132 * sizeof(float));
    float* __restrict__ C = which ? g_Pe : g_Pn;
    const int tid = threadIdx.x;
    const int m0 = blockIdx.x * 64;
    const int n0 = blockIdx.y * 128;

    // Load A tile 64x128 (zero-fill out-of-range rows), tf32-round
#pragma unroll
    for (int it = 0; it < 8; it++) {
        int idx = tid + it * 256;
        int r = idx >> 5, q = idx & 31;
        float4 v = make_float4(0.f, 0.f, 0.f, 0.f);
        if (m0 + r < N) v = *(const float4*)(A + (size_t)(m0 + r) * 128 + q * 4);
        v.x = to_tf32(v.x); v.y = to_tf32(v.y);
        v.z = to_tf32(v.z); v.w = to_tf32(v.w);
        *(float4*)&As[r][q * 4] = v;
    }
    // Load B tile 128x128: rows k (weight rows), cols n0..n0+127
#pragma unroll
    for (int it = 0; it < 16; it++) {
        int idx = tid + it * 256;
        int r = idx >> 5, q = idx & 31;
        float4 v = *(const float4*)(W + (size_t)r * 512 + n0 + q * 4);
        v.x = to_tf32(v.x); v.y = to_tf32(v.y);
        v.z = to_tf32(v.z); v.w = to_tf32(v.w);
        *(float4*)&Bs[r][q * 4] = v;
    }
    __syncthreads();

    const int lane = tid & 31, wid = tid >> 5;
    const int wm = wid >> 2, wn = wid & 3;      // warp grid 2(M) x 4(N)
    const int g = lane >> 2, c = lane & 3;
    float acc[2][4][4] = {};

#pragma unroll
    for (int ks = 0; ks < 16; ks++) {
        const int k0 = ks * 8;
        uint32_t af[2][4], bf[4][2];
#pragma unroll
        for (int mt = 0; mt < 2; mt++) {
            int r = wm * 32 + mt * 16 + g;
            af[mt][0] = __float_as_uint(As[r][k0 + c]);
            af[mt][1] = __float_as_uint(As[r + 8][k0 + c]);
            af[mt][2] = __float_as_uint(As[r][k0 + c + 4]);
            af[mt][3] = __float_as_uint(As[r + 8][k0 + c + 4]);
        }
#pragma unroll
        for (int nt = 0; nt < 4; nt++) {
            int col = wn * 32 + nt * 8 + g;
            bf[nt][0] = __float_as_uint(Bs[k0 + c][col]);
            bf[nt][1] = __float_as_uint(Bs[k0 + c + 4][col]);
        }
#pragma unroll
        for (int mt = 0; mt < 2; mt++)
#pragma unroll
            for (int nt = 0; nt < 4; nt++)
                mma_tf32(acc[mt][nt], af[mt], bf[nt]);
    }

    // Epilogue: float2 stores, 32B-sector aligned groups
#pragma unroll
    for (int mt = 0; mt < 2; mt++) {
#pragma unroll
        for (int nt = 0; nt < 4; nt++) {
            int r = m0 + wm * 32 + mt * 16 + g;
            int col = n0 + wn * 32 + nt * 8 + c * 2;
            if (r < N)
                *(float2*)(C + (size_t)r * 512 + col) =
                    make_float2(acc[mt][nt][0], acc[mt][nt][1]);
            if (r + 8 < N)
                *(float2*)(C + (size_t)(r + 8) * 512 + col) =
                    make_float2(acc[mt][nt][2], acc[mt][nt][3]);
        }
    }
}

// ---------------------------------------------------------------------------
// Per (branch, e): h1 = Pn[node] + Pe[edge] + te@W1t + b1 ; LN ; relu ;
// g[e,:] = sum_k wnorm_k * relu_h_k.
// ---------------------------------------------------------------------------
__global__ void __launch_bounds__(256) k_branch(
    const float* __restrict__ sel_dt, const float* __restrict__ sel_w,
    const float* __restrict__ time_w, const float* __restrict__ time_b,
    const float* __restrict__ fc1_w, const float* __restrict__ fc1_b,
    const float* __restrict__ ln1_g, const float* __restrict__ ln1_b,
    const int* __restrict__ sel_nodes, const int* __restrict__ sel_edges) {
    const int e = blockIdx.x, br = blockIdx.y;
    const int tid = threadIdx.x;
    __shared__ float te[KSEL][100];
    __shared__ float tw[100], tb[100];
    __shared__ float dt_s[KSEL], wn[KSEL];
    __shared__ int   nd_s[KSEL], ed_s[KSEL];
    __shared__ float red_s[KSEL][8], red_q[KSEL][8];
    __shared__ float mu_s[KSEL], rs_s[KSEL];
    __shared__ float ws_s, flag_s;

    const size_t base = ((size_t)br * E_N + e) * KSEL;
    if (tid < 100) { tw[tid] = time_w[tid]; tb[tid] = time_b[tid]; }
    if (tid >= 128 && tid < 128 + KSEL) {
        int k = tid - 128;
        dt_s[k] = sel_dt[base + k];
        wn[k]   = sel_w[base + k];
        nd_s[k] = sel_nodes[base + k];
        ed_s[k] = sel_edges[base + k];
    }
    __syncthreads();
    if (tid == 0) {
        float ws = 0.f;
        for (int k = 0; k < KSEL; k++) ws += wn[k];
        ws_s = ws;
        flag_s = (ws > 0.f) ? 1.f : 0.f;
    }
    for (int i = tid; i < KSEL * 100; i += 256) {
        int k = i / 100, j = i - k * 100;
        te[k][j] = __cosf(dt_s[k] * tw[j] + tb[j]);
    }
    __syncthreads();
    if (tid < KSEL) wn[tid] = (flag_s > 0.f) ? wn[tid] / ws_s : 0.f;

    const int c0 = tid * 2;
    float2 acc[KSEL];
    const float2 b1v = *(const float2*)(fc1_b + c0);
#pragma unroll
    for (int k = 0; k < KSEL; k++) {
        float2 pn = *(const float2*)(g_Pn + (size_t)nd_s[k] * 512 + c0);
        float2 pe = *(const float2*)(g_Pe + (size_t)ed_s[k] * 512 + c0);
        acc[k].x = pn.x + pe.x + b1v.x;
        acc[k].y = pn.y + pe.y + b1v.y;
    }
    const float* __restrict__ W1t = fc1_w + (size_t)256 * 512;
    for (int j = 0; j < 100; j += 4) {
        float2 w0 = *(const float2*)(W1t + (size_t)(j + 0) * 512 + c0);
        float2 w1 = *(const float2*)(W1t + (size_t)(j + 1) * 512 + c0);
        float2 w2 = *(const float2*)(W1t + (size_t)(j + 2) * 512 + c0);
        float2 w3 = *(const float2*)(W1t + (size_t)(j + 3) * 512 + c0);
#pragma unroll
        for (int k = 0; k < KSEL; k++) {
            float4 t = *(const float4*)&te[k][j];
            acc[k].x += t.x * w0.x + t.y * w1.x + t.z * w2.x + t.w * w3.x;
            acc[k].y += t.x * w0.y + t.y * w1.y + t.z * w2.y + t.w * w3.y;
        }
    }
    const int lane = tid & 31, warp = tid >> 5;
#pragma unroll
    for (int k = 0; k < KSEL; k++) {
        float s = acc[k].x + acc[k].y;
        float q = acc[k].x * acc[k].x + acc[k].y * acc[k].y;
#pragma unroll
        for (int o = 16; o > 0; o >>= 1) {
            s += __shfl_down_sync(0xffffffffu, s, o);
            q += __shfl_down_sync(0xffffffffu, q, o);
        }
        if (lane == 0) { red_s[k][warp] = s; red_q[k][warp] = q; }
    }
    __syncthreads();
    if (tid < KSEL) {
        float s = 0.f, q = 0.f;
#pragma unroll
        for (int w = 0; w < 8; w++) { s += red_s[tid][w]; q += red_q[tid][w]; }
        float mu = s * (1.f / 512.f);
        float var = q * (1.f / 512.f) - mu * mu;
        mu_s[tid] = mu;
        rs_s[tid] = rsqrtf(var + EPSV);
    }
    __syncthreads();
    const float lg0 = ln1_g[c0], lg1 = ln1_g[c0 + 1];
    const float lb0 = ln1_b[c0], lb1 = ln1_b[c0 + 1];
    float o0 = 0.f, o1 = 0.f;
#pragma unroll
    for (int k = 0; k < KSEL; k++) {
        float h0 = fmaxf((acc[k].x - mu_s[k]) * rs_s[k] * lg0 + lb0, 0.f);
        float h1 = fmaxf((acc[k].y - mu_s[k]) * rs_s[k] * lg1 + lb1, 0.f);
        o0 += wn[k] * h0;
        o1 += wn[k] * h1;
    }
    *(float2*)(g_g + ((size_t)br * E_N + e) * 512 + c0) = make_float2(o0, o1);
    if (tid == 0) g_flag[br * E_N + e] = flag_s;
}

// ---------------------------------------------------------------------------
// Source branch (unchanged from R1)
// ---------------------------------------------------------------------------
__global__ void __launch_bounds__(256) k_src(
    const float* __restrict__ memory,
    const float* __restrict__ fc1s_w, const float* __restrict__ fc1s_b,
    const float* __restrict__ bn_g, const float* __restrict__ bn_b,
    const float* __restrict__ bn_m, const float* __restrict__ bn_v,
    const float* __restrict__ fc2s_w, const float* __restrict__ fc2s_b,
    const int* __restrict__ src, float* __restrict__ out) {
    __shared__ float A[16][128];
    __shared__ float H[16][512];
    __shared__ int nd[16];
    const int tid = threadIdx.x;
    const int e0 = blockIdx.x * 16;
    if (tid < 16) nd[tid] = src[e0 + tid];
    __syncthreads();
    for (int i = tid; i < 16 * 32; i += 256) {
        int r = i >> 5, q = i & 31;
        *(float4*)&A[r][q * 4] = *(const float4*)(memory + (size_t)nd[r] * 128 + q * 4);
    }
    __syncthreads();

    const int c0 = tid * 2;
    float2 acc[16];
#pragma unroll
    for (int r = 0; r < 16; r++) acc[r] = make_float2(0.f, 0.f);
    for (int k = 0; k < 128; k += 4) {
        float2 w0 = *(const float2*)(fc1s_w + (size_t)(k + 0) * 512 + c0);
        float2 w1 = *(const float2*)(fc1s_w + (size_t)(k + 1) * 512 + c0);
        float2 w2 = *(const float2*)(fc1s_w + (size_t)(k + 2) * 512 + c0);
        float2 w3 = *(const float2*)(fc1s_w + (size_t)(k + 3) * 512 + c0);
#pragma unroll
        for (int r = 0; r < 16; r++) {
            float4 a = *(const float4*)&A[r][k];
            acc[r].x += a.x * w0.x + a.y * w1.x + a.z * w2.x + a.w * w3.x;
            acc[r].y += a.x * w0.y + a.y * w1.y + a.z * w2.y + a.w * w3.y;
        }
    }
    const float b0 = fc1s_b[c0], b1 = fc1s_b[c0 + 1];
    const float s0 = bn_g[c0] * rsqrtf(bn_v[c0] + EPSV);
    const float s1 = bn_g[c0 + 1] * rsqrtf(bn_v[c0 + 1] + EPSV);
    const float m0 = bn_m[c0], m1 = bn_m[c0 + 1];
    const float bb0 = bn_b[c0], bb1 = bn_b[c0 + 1];
#pragma unroll
    for (int r = 0; r < 16; r++) {
        H[r][c0]     = fmaxf((acc[r].x + b0 - m0) * s0 + bb0, 0.f);
        H[r][c0 + 1] = fmaxf((acc[r].y + b1 - m1) * s1 + bb1, 0.f);
    }
    __syncthreads();

    const int col = tid & 127, rg = tid >> 7;
    float o[8];
#pragma unroll
    for (int r = 0; r < 8; r++) o[r] = 0.f;
    for (int k = 0; k < 512; k += 4) {
        float w0 = fc2s_w[(size_t)(k + 0) * 128 + col];
        float w1 = fc2s_w[(size_t)(k + 1) * 128 + col];
        float w2 = fc2s_w[(size_t)(k + 2) * 128 + col];
        float w3 = fc2s_w[(size_t)(k + 3) * 128 + col];
#pragma unroll
        for (int r = 0; r < 8; r++) {
            float4 h = *(const float4*)&H[rg * 8 + r][k];
            o[r] += h.x * w0 + h.y * w1 + h.z * w2 + h.w * w3;
        }
    }
    const float bc = fc2s_b[col];
#pragma unroll
    for (int r = 0; r < 8; r++) {
        int e = e0 + rg * 8 + r;
        out[(size_t)e * 384 + col] = o[r] + bc;
    }
}

// ---------------------------------------------------------------------------
// Branch output GEMM (unchanged from R1)
// ---------------------------------------------------------------------------
__global__ void __launch_bounds__(256) k_out(
    const float* __restrict__ fc2_w, const float* __restrict__ fc2_b,
    float* __restrict__ out) {
    const int br = blockIdx.y;
    const int e0 = blockIdx.x * 16;
    __shared__ float gs[16][512];
    const int tid = threadIdx.x;
    for (int i = tid; i < 16 * 128; i += 256) {
        int r = i >> 7, q = i & 127;
        *(float4*)&gs[r][q * 4] =
            *(const float4*)(g_g + ((size_t)br * E_N + e0 + r) * 512 + q * 4);
    }
    __syncthreads();
    const int col = tid & 127, rg = tid >> 7;
    float o[8];
#pragma unroll
    for (int r = 0; r < 8; r++) o[r] = 0.f;
    for (int k = 0; k < 512; k += 4) {
        float w0 = fc2_w[(size_t)(k + 0) * 128 + col];
        float w1 = fc2_w[(size_t)(k + 1) * 128 + col];
        float w2 = fc2_w[(size_t)(k + 2) * 128 + col];
        float w3 = fc2_w[(size_t)(k + 3) * 128 + col];
#pragma unroll
        for (int r = 0; r < 8; r++) {
            float4 g4 = *(const float4*)&gs[rg * 8 + r][k];
            o[r] += g4.x * w0 + g4.y * w1 + g4.z * w2 + g4.w * w3;
        }
    }
    const float bc = fc2_b[col];
#pragma unroll
    for (int r = 0; r < 8; r++) {
        int e = e0 + rg * 8 + r;
        out[(size_t)e * 384 + 128 + br * 128 + col] = o[r] + bc * g_flag[br * E_N + e];
    }
}

// ---------------------------------------------------------------------------
extern "C" void kernel_launch(void* const* d_in, const int* in_sizes, int n_in,
                              void* d_out, int out_size) {
    const float* memory    = (const float*)d_in[0];
    const float* edge_feat = (const float*)d_in[1];
    const float* sel_dt    = (const float*)d_in[2];
    const float* sel_w     = (const float*)d_in[3];
    const float* time_w    = (const float*)d_in[4];
    const float* time_b    = (const float*)d_in[5];
    const float* fc1_w     = (const float*)d_in[6];
    const float* fc1_b     = (const float*)d_in[7];
    const float* ln1_g     = (const float*)d_in[8];
    const float* ln1_b     = (const float*)d_in[9];
    const float* fc2_w     = (const float*)d_in[10];
    const float* fc2_b     = (const float*)d_in[11];
    const float* fc1s_w    = (const float*)d_in[12];
    const float* fc1s_b    = (const float*)d_in[13];
    const float* bn_g      = (const float*)d_in[14];
    const float* bn_b      = (const float*)d_in[15];
    const float* bn_m      = (const float*)d_in[16];
    const float* bn_v      = (const float*)d_in[17];
    const float* fc2s_w    = (const float*)d_in[18];
    const float* fc2s_b    = (const float*)d_in[19];
    const int* source_nodes = (const int*)d_in[20];
    const int* sel_nodes    = (const int*)d_in[21];
    const int* sel_edges    = (const int*)d_in[22];
    float* out = (float*)d_out;

    cudaFuncSetAttribute(k_pre_mma, cudaFuncAttributeMaxDynamicSharedMemorySize,
                         PRE_SMEM);

    // Tensor-core (tf32 mma.sync) precompute of node/edge fc1 projections.
    k_pre_mma<<<dim3((NNODES + 63) / 64, 4), 256, PRE_SMEM>>>(memory, fc1_w, NNODES, 0);
    k_pre_mma<<<dim3((NEDGES + 63) / 64, 4), 256, PRE_SMEM>>>(edge_feat,
                                                              fc1_w + (size_t)128 * 512,
                                                              NEDGES, 1);
    // Source branch (independent)
    k_src<<<E_N / 16, 256>>>(memory, fc1s_w, fc1s_b, bn_g, bn_b, bn_m, bn_v,
                             fc2s_w, fc2s_b, source_nodes, out);
    // TPPR branches
    k_branch<<<dim3(E_N, NT_), 256>>>(sel_dt, sel_w, time_w, time_b,
                                      fc1_w, fc1_b, ln1_g, ln1_b,
                                      sel_nodes, sel_edges);
    k_out<<<dim3(E_N / 16, NT_), 256>>>(fc2_w, fc2_b, out);
}

// round 5
// speedup vs baseline: 2.0760x; 1.5075x over previous
#include <cuda_runtime.h>
#include <math.h>
#include <cstdint>

#define E_N     20000
#define KSEL    20
#define D_      128
#define F1_     512
#define F2_     128
#define NT_     2
#define NNODES  200000
#define NEDGES  500000
#define EPSV    1e-5f
#define PCH     16          // Chebyshev degree for the time-encoding map

// Scratch (allocation-free rule: __device__ globals)
static __device__ float g_Pn[(size_t)NNODES * F1_];   // memory @ fc1_w[0:128]
static __device__ float g_Pe[(size_t)NEDGES * F1_];   // edge_tbl @ fc1_w[128:256]
static __device__ float g_g [(size_t)NT_ * E_N * F1_];
static __device__ float g_flag[NT_ * E_N];
static __device__ float g_G[PCH * F1_];               // Chebyshev coeff rows of dt -> te@W1t

__device__ __forceinline__ float to_tf32(float x) {
    float r;
    asm("cvt.rna.tf32.f32 %0, %1;" : "=f"(r) : "f"(x));
    return r;
}
__device__ __forceinline__ void mma_tf32(float* c, const uint32_t* a, const uint32_t* b) {
    asm volatile("mma.sync.aligned.m16n8k8.row.col.f32.tf32.tf32.f32 "
                 "{%0,%1,%2,%3}, {%4,%5,%6,%7}, {%8,%9}, {%0,%1,%2,%3};"
                 : "+f"(c[0]), "+f"(c[1]), "+f"(c[2]), "+f"(c[3])
                 : "r"(a[0]), "r"(a[1]), "r"(a[2]), "r"(a[3]),
                   "r"(b[0]), "r"(b[1]));
}

// ---------------------------------------------------------------------------
// Chebyshev prolog: G[p,n] such that (te(dt) @ W1t)[n] ~= sum_p T_p(2dt-1) G[p,n].
// Interpolation at 16 Chebyshev nodes; error ~J_16(|tw|/2) < 1e-12 for any
// plausible tw. One block, 512 threads (one per output column).
// ---------------------------------------------------------------------------
__global__ void __launch_bounds__(512) k_cheb(const float* __restrict__ time_w,
                                              const float* __restrict__ time_b,
                                              const float* __restrict__ fc1_w) {
    __shared__ float teq[PCH][100];
    const int tid = threadIdx.x;
    for (int i = tid; i < PCH * 100; i += 512) {
        int q = i / 100, j = i - q * 100;
        float xq  = cospif((q + 0.5f) / (float)PCH);   // Chebyshev node in [-1,1]
        float dtq = 0.5f * (xq + 1.0f);                // mapped to [0,1]
        teq[q][j] = cosf(dtq * time_w[j] + time_b[j]);
    }
    __syncthreads();
    const float* __restrict__ W1t = fc1_w + (size_t)256 * 512;
    float M[PCH];
#pragma unroll
    for (int q = 0; q < PCH; q++) M[q] = 0.f;
    for (int j = 0; j < 100; j++) {
        float w = W1t[(size_t)j * 512 + tid];
#pragma unroll
        for (int q = 0; q < PCH; q++) M[q] += teq[q][j] * w;
    }
#pragma unroll
    for (int p = 0; p < PCH; p++) {
        float s = 0.f;
#pragma unroll
        for (int q = 0; q < PCH; q++)
            s += cospif(p * (q + 0.5f) / (float)PCH) * M[q];
        g_G[p * 512 + tid] = s * ((p == 0 ? 1.0f : 2.0f) / (float)PCH);
    }
}

// ---------------------------------------------------------------------------
// Tensor-core (mma.sync tf32) k_pre (unchanged from R4)
// ---------------------------------------------------------------------------
#define PRE_SMEM (64 * 132 * 4 + 128 * 136 * 4)

__global__ void __launch_bounds__(256, 2) k_pre_mma(const float* __restrict__ A,
                                                    const float* __restrict__ W,
                                                    int N, int which) {
    extern __shared__ char smem[];
    float (*As)[132] = (float(*)[132])smem;
    float (*Bs)[136] = (float(*)[136])(smem + 64 * 132 * sizeof(float));
    float* __restrict__ C = which ? g_Pe : g_Pn;
    const int tid = threadIdx.x;
    const int m0 = blockIdx.x * 64;
    const int n0 = blockIdx.y * 128;

#pragma unroll
    for (int it = 0; it < 8; it++) {
        int idx = tid + it * 256;
        int r = idx >> 5, q = idx & 31;
        float4 v = make_float4(0.f, 0.f, 0.f, 0.f);
        if (m0 + r < N) v = *(const float4*)(A + (size_t)(m0 + r) * 128 + q * 4);
        v.x = to_tf32(v.x); v.y = to_tf32(v.y);
        v.z = to_tf32(v.z); v.w = to_tf32(v.w);
        *(float4*)&As[r][q * 4] = v;
    }
#pragma unroll
    for (int it = 0; it < 16; it++) {
        int idx = tid + it * 256;
        int r = idx >> 5, q = idx & 31;
        float4 v = *(const float4*)(W + (size_t)r * 512 + n0 + q * 4);
        v.x = to_tf32(v.x); v.y = to_tf32(v.y);
        v.z = to_tf32(v.z); v.w = to_tf32(v.w);
        *(float4*)&Bs[r][q * 4] = v;
    }
    __syncthreads();

    const int lane = tid & 31, wid = tid >> 5;
    const int wm = wid >> 2, wn = wid & 3;
    const int g = lane >> 2, c = lane & 3;
    float acc[2][4][4] = {};

#pragma unroll
    for (int ks = 0; ks < 16; ks++) {
        const int k0 = ks * 8;
        uint32_t af[2][4], bf[4][2];
#pragma unroll
        for (int mt = 0; mt < 2; mt++) {
            int r = wm * 32 + mt * 16 + g;
            af[mt][0] = __float_as_uint(As[r][k0 + c]);
            af[mt][1] = __float_as_uint(As[r + 8][k0 + c]);
            af[mt][2] = __float_as_uint(As[r][k0 + c + 4]);
            af[mt][3] = __float_as_uint(As[r + 8][k0 + c + 4]);
        }
#pragma unroll
        for (int nt = 0; nt < 4; nt++) {
            int col = wn * 32 + nt * 8 + g;
            bf[nt][0] = __float_as_uint(Bs[k0 + c][col]);
            bf[nt][1] = __float_as_uint(Bs[k0 + c + 4][col]);
        }
#pragma unroll
        for (int mt = 0; mt < 2; mt++)
#pragma unroll
            for (int nt = 0; nt < 4; nt++)
                mma_tf32(acc[mt][nt], af[mt], bf[nt]);
    }

#pragma unroll
    for (int mt = 0; mt < 2; mt++) {
#pragma unroll
        for (int nt = 0; nt < 4; nt++) {
            int r = m0 + wm * 32 + mt * 16 + g;
            int col = n0 + wn * 32 + nt * 8 + c * 2;
            if (r < N)
                *(float2*)(C + (size_t)r * 512 + col) =
                    make_float2(acc[mt][nt][0], acc[mt][nt][1]);
            if (r + 8 < N)
                *(float2*)(C + (size_t)(r + 8) * 512 + col) =
                    make_float2(acc[mt][nt][2], acc[mt][nt][3]);
        }
    }
}

// ---------------------------------------------------------------------------
// Per (branch, e): h1 = Pn[node] + Pe[edge] + b1 + sum_p T_p(2dt-1) G[p,:] ;
// LN ; relu ; g[e,:] = sum_k wnorm_k * relu_h_k.  K=16 Chebyshev basis
// replaces the K=100 time GEMM.
// ---------------------------------------------------------------------------
__global__ void __launch_bounds__(256) k_branch(
    const float* __restrict__ sel_dt, const float* __restrict__ sel_w,
    const float* __restrict__ fc1_b,
    const float* __restrict__ ln1_g, const float* __restrict__ ln1_b,
    const int* __restrict__ sel_nodes, const int* __restrict__ sel_edges) {
    const int e = blockIdx.x, br = blockIdx.y;
    const int tid = threadIdx.x;
    __shared__ float ct[KSEL][PCH];
    __shared__ float wn[KSEL];
    __shared__ int   nd_s[KSEL], ed_s[KSEL];
    __shared__ float red_s[KSEL][8], red_q[KSEL][8];
    __shared__ float mu_s[KSEL], rs_s[KSEL];
    __shared__ float flag_s;

    const size_t base = ((size_t)br * E_N + e) * KSEL;
    if (tid < KSEL) {
        int k = tid;
        float dt = sel_dt[base + k];
        wn[k]   = sel_w[base + k];
        nd_s[k] = sel_nodes[base + k];
        ed_s[k] = sel_edges[base + k];
        // Chebyshev basis T_p(2dt-1), p = 0..15
        float x = 2.f * dt - 1.f;
        float t0 = 1.f, t1 = x;
        ct[k][0] = t0; ct[k][1] = t1;
#pragma unroll
        for (int p = 2; p < PCH; p++) {
            float t2 = 2.f * x * t1 - t0;
            ct[k][p] = t2;
            t0 = t1; t1 = t2;
        }
    }
    __syncthreads();
    if (tid == 0) {
        float ws = 0.f;
#pragma unroll
        for (int k = 0; k < KSEL; k++) ws += wn[k];
        float fl = (ws > 0.f) ? 1.f : 0.f;
        flag_s = fl;
        float inv = fl > 0.f ? 1.f / ws : 0.f;
#pragma unroll
        for (int k = 0; k < KSEL; k++) wn[k] *= inv;
    }

    const int c0 = tid * 2;
    // This thread's 2-column slice of the Chebyshev coefficient matrix
    float2 Gf[PCH];
#pragma unroll
    for (int p = 0; p < PCH; p++)
        Gf[p] = *(const float2*)(g_G + p * 512 + c0);

    float2 acc[KSEL];
    const float2 b1v = *(const float2*)(fc1_b + c0);
    __syncthreads();
#pragma unroll
    for (int k = 0; k < KSEL; k++) {
        float2 pn = *(const float2*)(g_Pn + (size_t)nd_s[k] * 512 + c0);
        float2 pe = *(const float2*)(g_Pe + (size_t)ed_s[k] * 512 + c0);
        acc[k].x = pn.x + pe.x + b1v.x;
        acc[k].y = pn.y + pe.y + b1v.y;
    }
#pragma unroll
    for (int k = 0; k < KSEL; k++) {
#pragma unroll
        for (int p = 0; p < PCH; p += 4) {
            float4 t = *(const float4*)&ct[k][p];
            acc[k].x += t.x * Gf[p].x + t.y * Gf[p + 1].x
                      + t.z * Gf[p + 2].x + t.w * Gf[p + 3].x;
            acc[k].y += t.x * Gf[p].y + t.y * Gf[p + 1].y
                      + t.z * Gf[p + 2].y + t.w * Gf[p + 3].y;
        }
    }
    const int lane = tid & 31, warp = tid >> 5;
#pragma unroll
    for (int k = 0; k < KSEL; k++) {
        float s = acc[k].x + acc[k].y;
        float q = acc[k].x * acc[k].x + acc[k].y * acc[k].y;
#pragma unroll
        for (int o = 16; o > 0; o >>= 1) {
            s += __shfl_down_sync(0xffffffffu, s, o);
            q += __shfl_down_sync(0xffffffffu, q, o);
        }
        if (lane == 0) { red_s[k][warp] = s; red_q[k][warp] = q; }
    }
    __syncthreads();
    if (tid < KSEL) {
        float s = 0.f, q = 0.f;
#pragma unroll
        for (int w = 0; w < 8; w++) { s += red_s[tid][w]; q += red_q[tid][w]; }
        float mu = s * (1.f / 512.f);
        float var = q * (1.f / 512.f) - mu * mu;
        mu_s[tid] = mu;
        rs_s[tid] = rsqrtf(var + EPSV);
    }
    __syncthreads();
    const float lg0 = ln1_g[c0], lg1 = ln1_g[c0 + 1];
    const float lb0 = ln1_b[c0], lb1 = ln1_b[c0 + 1];
    float o0 = 0.f, o1 = 0.f;
#pragma unroll
    for (int k = 0; k < KSEL; k++) {
        float h0 = fmaxf((acc[k].x - mu_s[k]) * rs_s[k] * lg0 + lb0, 0.f);
        float h1 = fmaxf((acc[k].y - mu_s[k]) * rs_s[k] * lg1 + lb1, 0.f);
        o0 += wn[k] * h0;
        o1 += wn[k] * h1;
    }
    *(float2*)(g_g + ((size_t)br * E_N + e) * 512 + c0) = make_float2(o0, o1);
    if (tid == 0) g_flag[br * E_N + e] = flag_s;
}

// ---------------------------------------------------------------------------
// Source branch (unchanged)
// ---------------------------------------------------------------------------
__global__ void __launch_bounds__(256) k_src(
    const float* __restrict__ memory,
    const float* __restrict__ fc1s_w, const float* __restrict__ fc1s_b,
    const float* __restrict__ bn_g, const float* __restrict__ bn_b,
    const float* __restrict__ bn_m, const float* __restrict__ bn_v,
    const float* __restrict__ fc2s_w, const float* __restrict__ fc2s_b,
    const int* __restrict__ src, float* __restrict__ out) {
    __shared__ float A[16][128];
    __shared__ float H[16][512];
    __shared__ int nd[16];
    const int tid = threadIdx.x;
    const int e0 = blockIdx.x * 16;
    if (tid < 16) nd[tid] = src[e0 + tid];
    __syncthreads();
    for (int i = tid; i < 16 * 32; i += 256) {
        int r = i >> 5, q = i & 31;
        *(float4*)&A[r][q * 4] = *(const float4*)(memory + (size_t)nd[r] * 128 + q * 4);
    }
    __syncthreads();

    const int c0 = tid * 2;
    float2 acc[16];
#pragma unroll
    for (int r = 0; r < 16; r++) acc[r] = make_float2(0.f, 0.f);
    for (int k = 0; k < 128; k += 4) {
        float2 w0 = *(const float2*)(fc1s_w + (size_t)(k + 0) * 512 + c0);
        float2 w1 = *(const float2*)(fc1s_w + (size_t)(k + 1) * 512 + c0);
        float2 w2 = *(const float2*)(fc1s_w + (size_t)(k + 2) * 512 + c0);
        float2 w3 = *(const float2*)(fc1s_w + (size_t)(k + 3) * 512 + c0);
#pragma unroll
        for (int r = 0; r < 16; r++) {
            float4 a = *(const float4*)&A[r][k];
            acc[r].x += a.x * w0.x + a.y * w1.x + a.z * w2.x + a.w * w3.x;
            acc[r].y += a.x * w0.y + a.y * w1.y + a.z * w2.y + a.w * w3.y;
        }
    }
    const float b0 = fc1s_b[c0], b1 = fc1s_b[c0 + 1];
    const float s0 = bn_g[c0] * rsqrtf(bn_v[c0] + EPSV);
    const float s1 = bn_g[c0 + 1] * rsqrtf(bn_v[c0 + 1] + EPSV);
    const float m0 = bn_m[c0], m1 = bn_m[c0 + 1];
    const float bb0 = bn_b[c0], bb1 = bn_b[c0 + 1];
#pragma unroll
    for (int r = 0; r < 16; r++) {
        H[r][c0]     = fmaxf((acc[r].x + b0 - m0) * s0 + bb0, 0.f);
        H[r][c0 + 1] = fmaxf((acc[r].y + b1 - m1) * s1 + bb1, 0.f);
    }
    __syncthreads();

    const int col = tid & 127, rg = tid >> 7;
    float o[8];
#pragma unroll
    for (int r = 0; r < 8; r++) o[r] = 0.f;
    for (int k = 0; k < 512; k += 4) {
        float w0 = fc2s_w[(size_t)(k + 0) * 128 + col];
        float w1 = fc2s_w[(size_t)(k + 1) * 128 + col];
        float w2 = fc2s_w[(size_t)(k + 2) * 128 + col];
        float w3 = fc2s_w[(size_t)(k + 3) * 128 + col];
#pragma unroll
        for (int r = 0; r < 8; r++) {
            float4 h = *(const float4*)&H[rg * 8 + r][k];
            o[r] += h.x * w0 + h.y * w1 + h.z * w2 + h.w * w3;
        }
    }
    const float bc = fc2s_b[col];
#pragma unroll
    for (int r = 0; r < 8; r++) {
        int e = e0 + rg * 8 + r;
        out[(size_t)e * 384 + col] = o[r] + bc;
    }
}

// ---------------------------------------------------------------------------
// Branch output GEMM (unchanged)
// ---------------------------------------------------------------------------
__global__ void __launch_bounds__(256) k_out(
    const float* __restrict__ fc2_w, const float* __restrict__ fc2_b,
    float* __restrict__ out) {
    const int br = blockIdx.y;
    const int e0 = blockIdx.x * 16;
    __shared__ float gs[16][512];
    const int tid = threadIdx.x;
    for (int i = tid; i < 16 * 128; i += 256) {
        int r = i >> 7, q = i & 127;
        *(float4*)&gs[r][q * 4] =
            *(const float4*)(g_g + ((size_t)br * E_N + e0 + r) * 512 + q * 4);
    }
    __syncthreads();
    const int col = tid & 127, rg = tid >> 7;
    float o[8];
#pragma unroll
    for (int r = 0; r < 8; r++) o[r] = 0.f;
    for (int k = 0; k < 512; k += 4) {
        float w0 = fc2_w[(size_t)(k + 0) * 128 + col];
        float w1 = fc2_w[(size_t)(k + 1) * 128 + col];
        float w2 = fc2_w[(size_t)(k + 2) * 128 + col];
        float w3 = fc2_w[(size_t)(k + 3) * 128 + col];
#pragma unroll
        for (int r = 0; r < 8; r++) {
            float4 g4 = *(const float4*)&gs[rg * 8 + r][k];
            o[r] += g4.x * w0 + g4.y * w1 + g4.z * w2 + g4.w * w3;
        }
    }
    const float bc = fc2_b[col];
#pragma unroll
    for (int r = 0; r < 8; r++) {
        int e = e0 + rg * 8 + r;
        out[(size_t)e * 384 + 128 + br * 128 + col] = o[r] + bc * g_flag[br * E_N + e];
    }
}

// ---------------------------------------------------------------------------
extern "C" void kernel_launch(void* const* d_in, const int* in_sizes, int n_in,
                              void* d_out, int out_size) {
    const float* memory    = (const float*)d_in[0];
    const float* edge_feat = (const float*)d_in[1];
    const float* sel_dt    = (const float*)d_in[2];
    const float* sel_w     = (const float*)d_in[3];
    const float* time_w    = (const float*)d_in[4];
    const float* time_b    = (const float*)d_in[5];
    const float* fc1_w     = (const float*)d_in[6];
    const float* fc1_b     = (const float*)d_in[7];
    const float* ln1_g     = (const float*)d_in[8];
    const float* ln1_b     = (const float*)d_in[9];
    const float* fc2_w     = (const float*)d_in[10];
    const float* fc2_b     = (const float*)d_in[11];
    const float* fc1s_w    = (const float*)d_in[12];
    const float* fc1s_b    = (const float*)d_in[13];
    const float* bn_g      = (const float*)d_in[14];
    const float* bn_b      = (const float*)d_in[15];
    const float* bn_m      = (const float*)d_in[16];
    const float* bn_v      = (const float*)d_in[17];
    const float* fc2s_w    = (const float*)d_in[18];
    const float* fc2s_b    = (const float*)d_in[19];
    const int* source_nodes = (const int*)d_in[20];
    const int* sel_nodes    = (const int*)d_in[21];
    const int* sel_edges    = (const int*)d_in[22];
    float* out = (float*)d_out;

    cudaFuncSetAttribute(k_pre_mma, cudaFuncAttributeMaxDynamicSharedMemorySize,
                         PRE_SMEM);

    // Chebyshev compression of the time-encoding map (tiny, one block)
    k_cheb<<<1, 512>>>(time_w, time_b, fc1_w);
    // Tensor-core (tf32 mma.sync) precompute of node/edge fc1 projections.
    k_pre_mma<<<dim3((NNODES + 63) / 64, 4), 256, PRE_SMEM>>>(memory, fc1_w, NNODES, 0);
    k_pre_mma<<<dim3((NEDGES + 63) / 64, 4), 256, PRE_SMEM>>>(edge_feat,
                                                              fc1_w + (size_t)128 * 512,
                                                              NEDGES, 1);
    // Source branch (independent)
    k_src<<<E_N / 16, 256>>>(memory, fc1s_w, fc1s_b, bn_g, bn_b, bn_m, bn_v,
                             fc2s_w, fc2s_b, source_nodes, out);
    // TPPR branches: gather + Chebyshev time encoding + LN + weighted reduce
    k_branch<<<dim3(E_N, NT_), 256>>>(sel_dt, sel_w, fc1_b, ln1_g, ln1_b,
                                      sel_nodes, sel_edges);
    k_out<<<dim3(E_N / 16, NT_), 256>>>(fc2_w, fc2_b, out);
}

// round 6
// speedup vs baseline: 2.3895x; 1.1510x over previous
#include <cuda_runtime.h>
#include <math.h>
#include <cstdint>

#define E_N     20000
#define KSEL    20
#define D_      128
#define F1_     512
#define F2_     128
#define NT_     2
#define NNODES  200000
#define NEDGES  500000
#define EPSV    1e-5f
#define PCH     16          // Chebyshev degree for the time-encoding map

// Scratch (allocation-free rule: __device__ globals)
static __device__ float g_Pn[(size_t)NNODES * F1_];
static __device__ float g_Pe[(size_t)NEDGES * F1_];
static __device__ float g_g [(size_t)NT_ * E_N * F1_];
static __device__ float g_H [(size_t)E_N * F1_];      // src branch hidden (post BN+ReLU)
static __device__ float g_flag[NT_ * E_N];
static __device__ float g_G[PCH * F1_];

__device__ __forceinline__ float to_tf32(float x) {
    float r;
    asm("cvt.rna.tf32.f32 %0, %1;" : "=f"(r) : "f"(x));
    return r;
}
__device__ __forceinline__ void mma_tf32(float* c, const uint32_t* a, const uint32_t* b) {
    asm volatile("mma.sync.aligned.m16n8k8.row.col.f32.tf32.tf32.f32 "
                 "{%0,%1,%2,%3}, {%4,%5,%6,%7}, {%8,%9}, {%0,%1,%2,%3};"
                 : "+f"(c[0]), "+f"(c[1]), "+f"(c[2]), "+f"(c[3])
                 : "r"(a[0]), "r"(a[1]), "r"(a[2]), "r"(a[3]),
                   "r"(b[0]), "r"(b[1]));
}

// ---------------------------------------------------------------------------
// Chebyshev prolog (unchanged from R5)
// ---------------------------------------------------------------------------
__global__ void __launch_bounds__(512) k_cheb(const float* __restrict__ time_w,
                                              const float* __restrict__ time_b,
                                              const float* __restrict__ fc1_w) {
    __shared__ float teq[PCH][100];
    const int tid = threadIdx.x;
    for (int i = tid; i < PCH * 100; i += 512) {
        int q = i / 100, j = i - q * 100;
        float xq  = cospif((q + 0.5f) / (float)PCH);
        float dtq = 0.5f * (xq + 1.0f);
        teq[q][j] = cosf(dtq * time_w[j] + time_b[j]);
    }
    __syncthreads();
    const float* __restrict__ W1t = fc1_w + (size_t)256 * 512;
    float M[PCH];
#pragma unroll
    for (int q = 0; q < PCH; q++) M[q] = 0.f;
    for (int j = 0; j < 100; j++) {
        float w = W1t[(size_t)j * 512 + tid];
#pragma unroll
        for (int q = 0; q < PCH; q++) M[q] += teq[q][j] * w;
    }
#pragma unroll
    for (int p = 0; p < PCH; p++) {
        float s = 0.f;
#pragma unroll
        for (int q = 0; q < PCH; q++)
            s += cospif(p * (q + 0.5f) / (float)PCH) * M[q];
        g_G[p * 512 + tid] = s * ((p == 0 ? 1.0f : 2.0f) / (float)PCH);
    }
}

// ---------------------------------------------------------------------------
// Tensor-core k_pre (unchanged from R4/R5)
// ---------------------------------------------------------------------------
#define PRE_SMEM (64 * 132 * 4 + 128 * 136 * 4)

__global__ void __launch_bounds__(256, 2) k_pre_mma(const float* __restrict__ A,
                                                    const float* __restrict__ W,
                                                    int N, int which) {
    extern __shared__ char smem[];
    float (*As)[132] = (float(*)[132])smem;
    float (*Bs)[136] = (float(*)[136])(smem + 64 * 132 * sizeof(float));
    float* __restrict__ C = which ? g_Pe : g_Pn;
    const int tid = threadIdx.x;
    const int m0 = blockIdx.x * 64;
    const int n0 = blockIdx.y * 128;

#pragma unroll
    for (int it = 0; it < 8; it++) {
        int idx = tid + it * 256;
        int r = idx >> 5, q = idx & 31;
        float4 v = make_float4(0.f, 0.f, 0.f, 0.f);
        if (m0 + r < N) v = *(const float4*)(A + (size_t)(m0 + r) * 128 + q * 4);
        v.x = to_tf32(v.x); v.y = to_tf32(v.y);
        v.z = to_tf32(v.z); v.w = to_tf32(v.w);
        *(float4*)&As[r][q * 4] = v;
    }
#pragma unroll
    for (int it = 0; it < 16; it++) {
        int idx = tid + it * 256;
        int r = idx >> 5, q = idx & 31;
        float4 v = *(const float4*)(W + (size_t)r * 512 + n0 + q * 4);
        v.x = to_tf32(v.x); v.y = to_tf32(v.y);
        v.z = to_tf32(v.z); v.w = to_tf32(v.w);
        *(float4*)&Bs[r][q * 4] = v;
    }
    __syncthreads();

    const int lane = tid & 31, wid = tid >> 5;
    const int wm = wid >> 2, wn = wid & 3;
    const int g = lane >> 2, c = lane & 3;
    float acc[2][4][4] = {};

#pragma unroll
    for (int ks = 0; ks < 16; ks++) {
        const int k0 = ks * 8;
        uint32_t af[2][4], bf[4][2];
#pragma unroll
        for (int mt = 0; mt < 2; mt++) {
            int r = wm * 32 + mt * 16 + g;
            af[mt][0] = __float_as_uint(As[r][k0 + c]);
            af[mt][1] = __float_as_uint(As[r + 8][k0 + c]);
            af[mt][2] = __float_as_uint(As[r][k0 + c + 4]);
            af[mt][3] = __float_as_uint(As[r + 8][k0 + c + 4]);
        }
#pragma unroll
        for (int nt = 0; nt < 4; nt++) {
            int col = wn * 32 + nt * 8 + g;
            bf[nt][0] = __float_as_uint(Bs[k0 + c][col]);
            bf[nt][1] = __float_as_uint(Bs[k0 + c + 4][col]);
        }
#pragma unroll
        for (int mt = 0; mt < 2; mt++)
#pragma unroll
            for (int nt = 0; nt < 4; nt++)
                mma_tf32(acc[mt][nt], af[mt], bf[nt]);
    }

#pragma unroll
    for (int mt = 0; mt < 2; mt++) {
#pragma unroll
        for (int nt = 0; nt < 4; nt++) {
            int r = m0 + wm * 32 + mt * 16 + g;
            int col = n0 + wn * 32 + nt * 8 + c * 2;
            if (r < N)
                *(float2*)(C + (size_t)r * 512 + col) =
                    make_float2(acc[mt][nt][0], acc[mt][nt][1]);
            if (r + 8 < N)
                *(float2*)(C + (size_t)(r + 8) * 512 + col) =
                    make_float2(acc[mt][nt][2], acc[mt][nt][3]);
        }
    }
}

// ---------------------------------------------------------------------------
// Src branch GEMM1 (tensor): H = relu(BN(memory[src] @ fc1s_w + b)).
// Gathered A rows; 64 rows x 128-col n-tile per CTA; grid (313, 4).
// ---------------------------------------------------------------------------
__global__ void __launch_bounds__(256, 2) k_src1_mma(
    const float* __restrict__ memory, const float* __restrict__ fc1s_w,
    const float* __restrict__ fc1s_b,
    const float* __restrict__ bn_g, const float* __restrict__ bn_b,
    const float* __restrict__ bn_m, const float* __restrict__ bn_v,
    const int* __restrict__ src) {
    extern __shared__ char smem[];
    float (*As)[132] = (float(*)[132])smem;
    float (*Bs)[136] = (float(*)[136])(smem + 64 * 132 * sizeof(float));
    __shared__ int nd[64];
    const int tid = threadIdx.x;
    const int m0 = blockIdx.x * 64;
    const int n0 = blockIdx.y * 128;

    if (tid < 64) nd[tid] = (m0 + tid < E_N) ? src[m0 + tid] : 0;
    __syncthreads();
#pragma unroll
    for (int it = 0; it < 8; it++) {
        int idx = tid + it * 256;
        int r = idx >> 5, q = idx & 31;
        float4 v = make_float4(0.f, 0.f, 0.f, 0.f);
        if (m0 + r < E_N) v = *(const float4*)(memory + (size_t)nd[r] * 128 + q * 4);
        v.x = to_tf32(v.x); v.y = to_tf32(v.y);
        v.z = to_tf32(v.z); v.w = to_tf32(v.w);
        *(float4*)&As[r][q * 4] = v;
    }
#pragma unroll
    for (int it = 0; it < 16; it++) {
        int idx = tid + it * 256;
        int r = idx >> 5, q = idx & 31;
        float4 v = *(const float4*)(fc1s_w + (size_t)r * 512 + n0 + q * 4);
        v.x = to_tf32(v.x); v.y = to_tf32(v.y);
        v.z = to_tf32(v.z); v.w = to_tf32(v.w);
        *(float4*)&Bs[r][q * 4] = v;
    }
    __syncthreads();

    const int lane = tid & 31, wid = tid >> 5;
    const int wm = wid >> 2, wn = wid & 3;
    const int g = lane >> 2, c = lane & 3;
    float acc[2][4][4] = {};
#pragma unroll
    for (int ks = 0; ks < 16; ks++) {
        const int k0 = ks * 8;
        uint32_t af[2][4], bf[4][2];
#pragma unroll
        for (int mt = 0; mt < 2; mt++) {
            int r = wm * 32 + mt * 16 + g;
            af[mt][0] = __float_as_uint(As[r][k0 + c]);
            af[mt][1] = __float_as_uint(As[r + 8][k0 + c]);
            af[mt][2] = __float_as_uint(As[r][k0 + c + 4]);
            af[mt][3] = __float_as_uint(As[r + 8][k0 + c + 4]);
        }
#pragma unroll
        for (int nt = 0; nt < 4; nt++) {
            int col = wn * 32 + nt * 8 + g;
            bf[nt][0] = __float_as_uint(Bs[k0 + c][col]);
            bf[nt][1] = __float_as_uint(Bs[k0 + c + 4][col]);
        }
#pragma unroll
        for (int mt = 0; mt < 2; mt++)
#pragma unroll
            for (int nt = 0; nt < 4; nt++)
                mma_tf32(acc[mt][nt], af[mt], bf[nt]);
    }

    // Epilogue: BN(eval) + ReLU, store to g_H
#pragma unroll
    for (int nt = 0; nt < 4; nt++) {
        int col = n0 + wn * 32 + nt * 8 + c * 2;
        float s0 = bn_g[col]     * rsqrtf(bn_v[col]     + EPSV);
        float s1 = bn_g[col + 1] * rsqrtf(bn_v[col + 1] + EPSV);
        float o0 = fc1s_b[col]     - bn_m[col];
        float o1 = fc1s_b[col + 1] - bn_m[col + 1];
        float bb0 = bn_b[col], bb1 = bn_b[col + 1];
#pragma unroll
        for (int mt = 0; mt < 2; mt++) {
            int r = m0 + wm * 32 + mt * 16 + g;
            if (r < E_N)
                *(float2*)(g_H + (size_t)r * 512 + col) = make_float2(
                    fmaxf((acc[mt][nt][0] + o0) * s0 + bb0, 0.f),
                    fmaxf((acc[mt][nt][1] + o1) * s1 + bb1, 0.f));
            if (r + 8 < E_N)
                *(float2*)(g_H + (size_t)(r + 8) * 512 + col) = make_float2(
                    fmaxf((acc[mt][nt][2] + o0) * s0 + bb0, 0.f),
                    fmaxf((acc[mt][nt][3] + o1) * s1 + bb1, 0.f));
        }
    }
}

// ---------------------------------------------------------------------------
// Generic second GEMM (tensor): C[R,128] = A[R,512] @ W[512,128] + bias.
// mode 0: A = g_H, R = E_N,      out[e*384 + col]            = acc + b[col]
// mode 1: A = g_g, R = 2*E_N,    out[e*384 + 128 + br*128+col]= acc + b[col]*flag
// 64 rows per CTA; K looped in 4 chunks of 128.
// ---------------------------------------------------------------------------
__global__ void __launch_bounds__(256, 2) k_gemm2(
    const float* __restrict__ W, const float* __restrict__ bias,
    float* __restrict__ out, int R, int mode) {
    extern __shared__ char smem[];
    float (*As)[132] = (float(*)[132])smem;
    float (*Bs)[136] = (float(*)[136])(smem + 64 * 132 * sizeof(float));
    const float* __restrict__ A = mode ? g_g : g_H;
    const int tid = threadIdx.x;
    const int m0 = blockIdx.x * 64;

    const int lane = tid & 31, wid = tid >> 5;
    const int wm = wid >> 2, wn = wid & 3;
    const int g = lane >> 2, c = lane & 3;
    float acc[2][4][4] = {};

    for (int kc = 0; kc < 4; kc++) {
#pragma unroll
        for (int it = 0; it < 8; it++) {
            int idx = tid + it * 256;
            int r = idx >> 5, q = idx & 31;
            float4 v = make_float4(0.f, 0.f, 0.f, 0.f);
            if (m0 + r < R)
                v = *(const float4*)(A + (size_t)(m0 + r) * 512 + kc * 128 + q * 4);
            v.x = to_tf32(v.x); v.y = to_tf32(v.y);
            v.z = to_tf32(v.z); v.w = to_tf32(v.w);
            *(float4*)&As[r][q * 4] = v;
        }
#pragma unroll
        for (int it = 0; it < 16; it++) {
            int idx = tid + it * 256;
            int r = idx >> 5, q = idx & 31;
            float4 v = *(const float4*)(W + (size_t)(kc * 128 + r) * 128 + q * 4);
            v.x = to_tf32(v.x); v.y = to_tf32(v.y);
            v.z = to_tf32(v.z); v.w = to_tf32(v.w);
            *(float4*)&Bs[r][q * 4] = v;
        }
        __syncthreads();
#pragma unroll
        for (int ks = 0; ks < 16; ks++) {
            const int k0 = ks * 8;
            uint32_t af[2][4], bf[4][2];
#pragma unroll
            for (int mt = 0; mt < 2; mt++) {
                int r = wm * 32 + mt * 16 + g;
                af[mt][0] = __float_as_uint(As[r][k0 + c]);
                af[mt][1] = __float_as_uint(As[r + 8][k0 + c]);
                af[mt][2] = __float_as_uint(As[r][k0 + c + 4]);
                af[mt][3] = __float_as_uint(As[r + 8][k0 + c + 4]);
            }
#pragma unroll
            for (int nt = 0; nt < 4; nt++) {
                int col = wn * 32 + nt * 8 + g;
                bf[nt][0] = __float_as_uint(Bs[k0 + c][col]);
                bf[nt][1] = __float_as_uint(Bs[k0 + c + 4][col]);
            }
#pragma unroll
            for (int mt = 0; mt < 2; mt++)
#pragma unroll
                for (int nt = 0; nt < 4; nt++)
                    mma_tf32(acc[mt][nt], af[mt], bf[nt]);
        }
        __syncthreads();
    }

#pragma unroll
    for (int mt = 0; mt < 2; mt++) {
#pragma unroll
        for (int nt = 0; nt < 4; nt++) {
            int col = wn * 32 + nt * 8 + c * 2;
            float b0 = bias[col], b1 = bias[col + 1];
#pragma unroll
            for (int half = 0; half < 2; half++) {
                int r = m0 + wm * 32 + mt * 16 + g + half * 8;
                if (r >= R) continue;
                float v0 = acc[mt][nt][half * 2 + 0];
                float v1 = acc[mt][nt][half * 2 + 1];
                if (mode == 0) {
                    *(float2*)(out + (size_t)r * 384 + col) =
                        make_float2(v0 + b0, v1 + b1);
                } else {
                    int br = r / E_N, e = r - br * E_N;
                    float fl = g_flag[r];
                    *(float2*)(out + (size_t)e * 384 + 128 + br * 128 + col) =
                        make_float2(v0 + b0 * fl, v1 + b1 * fl);
                }
            }
        }
    }
}

// ---------------------------------------------------------------------------
// k_branch (unchanged from R5)
// ---------------------------------------------------------------------------
__global__ void __launch_bounds__(256) k_branch(
    const float* __restrict__ sel_dt, const float* __restrict__ sel_w,
    const float* __restrict__ fc1_b,
    const float* __restrict__ ln1_g, const float* __restrict__ ln1_b,
    const int* __restrict__ sel_nodes, const int* __restrict__ sel_edges) {
    const int e = blockIdx.x, br = blockIdx.y;
    const int tid = threadIdx.x;
    __shared__ float ct[KSEL][PCH];
    __shared__ float wn[KSEL];
    __shared__ int   nd_s[KSEL], ed_s[KSEL];
    __shared__ float red_s[KSEL][8], red_q[KSEL][8];
    __shared__ float mu_s[KSEL], rs_s[KSEL];
    __shared__ float flag_s;

    const size_t base = ((size_t)br * E_N + e) * KSEL;
    if (tid < KSEL) {
        int k = tid;
        float dt = sel_dt[base + k];
        wn[k]   = sel_w[base + k];
        nd_s[k] = sel_nodes[base + k];
        ed_s[k] = sel_edges[base + k];
        float x = 2.f * dt - 1.f;
        float t0 = 1.f, t1 = x;
        ct[k][0] = t0; ct[k][1] = t1;
#pragma unroll
        for (int p = 2; p < PCH; p++) {
            float t2 = 2.f * x * t1 - t0;
            ct[k][p] = t2;
            t0 = t1; t1 = t2;
        }
    }
    __syncthreads();
    if (tid == 0) {
        float ws = 0.f;
#pragma unroll
        for (int k = 0; k < KSEL; k++) ws += wn[k];
        float fl = (ws > 0.f) ? 1.f : 0.f;
        flag_s = fl;
        float inv = fl > 0.f ? 1.f / ws : 0.f;
#pragma unroll
        for (int k = 0; k < KSEL; k++) wn[k] *= inv;
    }

    const int c0 = tid * 2;
    float2 Gf[PCH];
#pragma unroll
    for (int p = 0; p < PCH; p++)
        Gf[p] = *(const float2*)(g_G + p * 512 + c0);

    float2 acc[KSEL];
    const float2 b1v = *(const float2*)(fc1_b + c0);
    __syncthreads();
#pragma unroll
    for (int k = 0; k < KSEL; k++) {
        float2 pn = *(const float2*)(g_Pn + (size_t)nd_s[k] * 512 + c0);
        float2 pe = *(const float2*)(g_Pe + (size_t)ed_s[k] * 512 + c0);
        acc[k].x = pn.x + pe.x + b1v.x;
        acc[k].y = pn.y + pe.y + b1v.y;
    }
#pragma unroll
    for (int k = 0; k < KSEL; k++) {
#pragma unroll
        for (int p = 0; p < PCH; p += 4) {
            float4 t = *(const float4*)&ct[k][p];
            acc[k].x += t.x * Gf[p].x + t.y * Gf[p + 1].x
                      + t.z * Gf[p + 2].x + t.w * Gf[p + 3].x;
            acc[k].y += t.x * Gf[p].y + t.y * Gf[p + 1].y
                      + t.z * Gf[p + 2].y + t.w * Gf[p + 3].y;
        }
    }
    const int lane = tid & 31, warp = tid >> 5;
#pragma unroll
    for (int k = 0; k < KSEL; k++) {
        float s = acc[k].x + acc[k].y;
        float q = acc[k].x * acc[k].x + acc[k].y * acc[k].y;
#pragma unroll
        for (int o = 16; o > 0; o >>= 1) {
            s += __shfl_down_sync(0xffffffffu, s, o);
            q += __shfl_down_sync(0xffffffffu, q, o);
        }
        if (lane == 0) { red_s[k][warp] = s; red_q[k][warp] = q; }
    }
    __syncthreads();
    if (tid < KSEL) {
        float s = 0.f, q = 0.f;
#pragma unroll
        for (int w = 0; w < 8; w++) { s += red_s[tid][w]; q += red_q[tid][w]; }
        float mu = s * (1.f / 512.f);
        float var = q * (1.f / 512.f) - mu * mu;
        mu_s[tid] = mu;
        rs_s[tid] = rsqrtf(var + EPSV);
    }
    __syncthreads();
    const float lg0 = ln1_g[c0], lg1 = ln1_g[c0 + 1];
    const float lb0 = ln1_b[c0], lb1 = ln1_b[c0 + 1];
    float o0 = 0.f, o1 = 0.f;
#pragma unroll
    for (int k = 0; k < KSEL; k++) {
        float h0 = fmaxf((acc[k].x - mu_s[k]) * rs_s[k] * lg0 + lb0, 0.f);
        float h1 = fmaxf((acc[k].y - mu_s[k]) * rs_s[k] * lg1 + lb1, 0.f);
        o0 += wn[k] * h0;
        o1 += wn[k] * h1;
    }
    *(float2*)(g_g + ((size_t)br * E_N + e) * 512 + c0) = make_float2(o0, o1);
    if (tid == 0) g_flag[br * E_N + e] = flag_s;
}

// ---------------------------------------------------------------------------
extern "C" void kernel_launch(void* const* d_in, const int* in_sizes, int n_in,
                              void* d_out, int out_size) {
    const float* memory    = (const float*)d_in[0];
    const float* edge_feat = (const float*)d_in[1];
    const float* sel_dt    = (const float*)d_in[2];
    const float* sel_w     = (const float*)d_in[3];
    const float* time_w    = (const float*)d_in[4];
    const float* time_b    = (const float*)d_in[5];
    const float* fc1_w     = (const float*)d_in[6];
    const float* fc1_b     = (const float*)d_in[7];
    const float* ln1_g     = (const float*)d_in[8];
    const float* ln1_b     = (const float*)d_in[9];
    const float* fc2_w     = (const float*)d_in[10];
    const float* fc2_b     = (const float*)d_in[11];
    const float* fc1s_w    = (const float*)d_in[12];
    const float* fc1s_b    = (const float*)d_in[13];
    const float* bn_g      = (const float*)d_in[14];
    const float* bn_b      = (const float*)d_in[15];
    const float* bn_m      = (const float*)d_in[16];
    const float* bn_v      = (const float*)d_in[17];
    const float* fc2s_w    = (const float*)d_in[18];
    const float* fc2s_b    = (const float*)d_in[19];
    const int* source_nodes = (const int*)d_in[20];
    const int* sel_nodes    = (const int*)d_in[21];
    const int* sel_edges    = (const int*)d_in[22];
    float* out = (float*)d_out;

    cudaFuncSetAttribute(k_pre_mma,  cudaFuncAttributeMaxDynamicSharedMemorySize, PRE_SMEM);
    cudaFuncSetAttribute(k_src1_mma, cudaFuncAttributeMaxDynamicSharedMemorySize, PRE_SMEM);
    cudaFuncSetAttribute(k_gemm2,    cudaFuncAttributeMaxDynamicSharedMemorySize, PRE_SMEM);

    // Chebyshev compression of the time-encoding map
    k_cheb<<<1, 512>>>(time_w, time_b, fc1_w);
    // Tensor-core precompute of node/edge fc1 projections
    k_pre_mma<<<dim3((NNODES + 63) / 64, 4), 256, PRE_SMEM>>>(memory, fc1_w, NNODES, 0);
    k_pre_mma<<<dim3((NEDGES + 63) / 64, 4), 256, PRE_SMEM>>>(edge_feat,
                                                              fc1_w + (size_t)128 * 512,
                                                              NEDGES, 1);
    // Source branch: GEMM1 (+BN+ReLU) then GEMM2, both tensor-core
    k_src1_mma<<<dim3((E_N + 63) / 64, 4), 256, PRE_SMEM>>>(
        memory, fc1s_w, fc1s_b, bn_g, bn_b, bn_m, bn_v, source_nodes);
    k_gemm2<<<(E_N + 63) / 64, 256, PRE_SMEM>>>(fc2s_w, fc2s_b, out, E_N, 0);
    // TPPR branches: gather + Chebyshev time encoding + LN + weighted reduce
    k_branch<<<dim3(E_N, NT_), 256>>>(sel_dt, sel_w, fc1_b, ln1_g, ln1_b,
                                      sel_nodes, sel_edges);
    // Branch fc2 (tensor-core) into output
    k_gemm2<<<(NT_ * E_N + 63) / 64, 256, PRE_SMEM>>>(fc2_w, fc2_b, out,
                                                      NT_ * E_N, 1);
}

// round 7
// speedup vs baseline: 2.4921x; 1.0429x over previous
#include <cuda_runtime.h>
#include <cuda_fp16.h>
#include <math.h>
#include <cstdint>

#define E_N     20000
#define KSEL    20
#define D_      128
#define F1_     512
#define F2_     128
#define NT_     2
#define NNODES  200000
#define NEDGES  500000
#define EPSV    1e-5f
#define PCH     16          // Chebyshev degree for the time-encoding map

// Scratch (allocation-free rule: __device__ globals)
static __device__ __half g_Pn[(size_t)NNODES * F1_];  // fp16: halves gather traffic
static __device__ __half g_Pe[(size_t)NEDGES * F1_];
static __device__ float  g_g [(size_t)NT_ * E_N * F1_];
static __device__ float  g_H [(size_t)E_N * F1_];
static __device__ float  g_flag[NT_ * E_N];
static __device__ float  g_G[PCH * F1_];

__device__ __forceinline__ float to_tf32(float x) {
    float r;
    asm("cvt.rna.tf32.f32 %0, %1;" : "=f"(r) : "f"(x));
    return r;
}
__device__ __forceinline__ void mma_tf32(float* c, const uint32_t* a, const uint32_t* b) {
    asm volatile("mma.sync.aligned.m16n8k8.row.col.f32.tf32.tf32.f32 "
                 "{%0,%1,%2,%3}, {%4,%5,%6,%7}, {%8,%9}, {%0,%1,%2,%3};"
                 : "+f"(c[0]), "+f"(c[1]), "+f"(c[2]), "+f"(c[3])
                 : "r"(a[0]), "r"(a[1]), "r"(a[2]), "r"(a[3]),
                   "r"(b[0]), "r"(b[1]));
}

// ---------------------------------------------------------------------------
// Chebyshev prolog (unchanged)
// ---------------------------------------------------------------------------
__global__ void __launch_bounds__(512) k_cheb(const float* __restrict__ time_w,
                                              const float* __restrict__ time_b,
                                              const float* __restrict__ fc1_w) {
    __shared__ float teq[PCH][100];
    const int tid = threadIdx.x;
    for (int i = tid; i < PCH * 100; i += 512) {
        int q = i / 100, j = i - q * 100;
        float xq  = cospif((q + 0.5f) / (float)PCH);
        float dtq = 0.5f * (xq + 1.0f);
        teq[q][j] = cosf(dtq * time_w[j] + time_b[j]);
    }
    __syncthreads();
    const float* __restrict__ W1t = fc1_w + (size_t)256 * 512;
    float M[PCH];
#pragma unroll
    for (int q = 0; q < PCH; q++) M[q] = 0.f;
    for (int j = 0; j < 100; j++) {
        float w = W1t[(size_t)j * 512 + tid];
#pragma unroll
        for (int q = 0; q < PCH; q++) M[q] += teq[q][j] * w;
    }
#pragma unroll
    for (int p = 0; p < PCH; p++) {
        float s = 0.f;
#pragma unroll
        for (int q = 0; q < PCH; q++)
            s += cospif(p * (q + 0.5f) / (float)PCH) * M[q];
        g_G[p * 512 + tid] = s * ((p == 0 ? 1.0f : 2.0f) / (float)PCH);
    }
}

// ---------------------------------------------------------------------------
// Tensor-core k_pre -> fp16 output
// ---------------------------------------------------------------------------
#define PRE_SMEM (64 * 132 * 4 + 128 * 136 * 4)

__global__ void __launch_bounds__(256, 2) k_pre_mma(const float* __restrict__ A,
                                                    const float* __restrict__ W,
                                                    int N, int which) {
    extern __shared__ char smem[];
    float (*As)[132] = (float(*)[132])smem;
    float (*Bs)[136] = (float(*)[136])(smem + 64 * 132 * sizeof(float));
    __half* __restrict__ C = which ? g_Pe : g_Pn;
    const int tid = threadIdx.x;
    const int m0 = blockIdx.x * 64;
    const int n0 = blockIdx.y * 128;

#pragma unroll
    for (int it = 0; it < 8; it++) {
        int idx = tid + it * 256;
        int r = idx >> 5, q = idx & 31;
        float4 v = make_float4(0.f, 0.f, 0.f, 0.f);
        if (m0 + r < N) v = *(const float4*)(A + (size_t)(m0 + r) * 128 + q * 4);
        v.x = to_tf32(v.x); v.y = to_tf32(v.y);
        v.z = to_tf32(v.z); v.w = to_tf32(v.w);
        *(float4*)&As[r][q * 4] = v;
    }
#pragma unroll
    for (int it = 0; it < 16; it++) {
        int idx = tid + it * 256;
        int r = idx >> 5, q = idx & 31;
        float4 v = *(const float4*)(W + (size_t)r * 512 + n0 + q * 4);
        v.x = to_tf32(v.x); v.y = to_tf32(v.y);
        v.z = to_tf32(v.z); v.w = to_tf32(v.w);
        *(float4*)&Bs[r][q * 4] = v;
    }
    __syncthreads();

    const int lane = tid & 31, wid = tid >> 5;
    const int wm = wid >> 2, wn = wid & 3;
    const int g = lane >> 2, c = lane & 3;
    float acc[2][4][4] = {};

#pragma unroll
    for (int ks = 0; ks < 16; ks++) {
        const int k0 = ks * 8;
        uint32_t af[2][4], bf[4][2];
#pragma unroll
        for (int mt = 0; mt < 2; mt++) {
            int r = wm * 32 + mt * 16 + g;
            af[mt][0] = __float_as_uint(As[r][k0 + c]);
            af[mt][1] = __float_as_uint(As[r + 8][k0 + c]);
            af[mt][2] = __float_as_uint(As[r][k0 + c + 4]);
            af[mt][3] = __float_as_uint(As[r + 8][k0 + c + 4]);
        }
#pragma unroll
        for (int nt = 0; nt < 4; nt++) {
            int col = wn * 32 + nt * 8 + g;
            bf[nt][0] = __float_as_uint(Bs[k0 + c][col]);
            bf[nt][1] = __float_as_uint(Bs[k0 + c + 4][col]);
        }
#pragma unroll
        for (int mt = 0; mt < 2; mt++)
#pragma unroll
            for (int nt = 0; nt < 4; nt++)
                mma_tf32(acc[mt][nt], af[mt], bf[nt]);
    }

    // Epilogue: fp16 stores (half2 per 2 cols)
#pragma unroll
    for (int mt = 0; mt < 2; mt++) {
#pragma unroll
        for (int nt = 0; nt < 4; nt++) {
            int r = m0 + wm * 32 + mt * 16 + g;
            int col = n0 + wn * 32 + nt * 8 + c * 2;
            if (r < N)
                *(__half2*)(C + (size_t)r * 512 + col) =
                    __floats2half2_rn(acc[mt][nt][0], acc[mt][nt][1]);
            if (r + 8 < N)
                *(__half2*)(C + (size_t)(r + 8) * 512 + col) =
                    __floats2half2_rn(acc[mt][nt][2], acc[mt][nt][3]);
        }
    }
}

// ---------------------------------------------------------------------------
// Src branch GEMM1 (tensor, unchanged)
// ---------------------------------------------------------------------------
__global__ void __launch_bounds__(256, 2) k_src1_mma(
    const float* __restrict__ memory, const float* __restrict__ fc1s_w,
    const float* __restrict__ fc1s_b,
    const float* __restrict__ bn_g, const float* __restrict__ bn_b,
    const float* __restrict__ bn_m, const float* __restrict__ bn_v,
    const int* __restrict__ src) {
    extern __shared__ char smem[];
    float (*As)[132] = (float(*)[132])smem;
    float (*Bs)[136] = (float(*)[136])(smem + 64 * 132 * sizeof(float));
    __shared__ int nd[64];
    const int tid = threadIdx.x;
    const int m0 = blockIdx.x * 64;
    const int n0 = blockIdx.y * 128;

    if (tid < 64) nd[tid] = (m0 + tid < E_N) ? src[m0 + tid] : 0;
    __syncthreads();
#pragma unroll
    for (int it = 0; it < 8; it++) {
        int idx = tid + it * 256;
        int r = idx >> 5, q = idx & 31;
        float4 v = make_float4(0.f, 0.f, 0.f, 0.f);
        if (m0 + r < E_N) v = *(const float4*)(memory + (size_t)nd[r] * 128 + q * 4);
        v.x = to_tf32(v.x); v.y = to_tf32(v.y);
        v.z = to_tf32(v.z); v.w = to_tf32(v.w);
        *(float4*)&As[r][q * 4] = v;
    }
#pragma unroll
    for (int it = 0; it < 16; it++) {
        int idx = tid + it * 256;
        int r = idx >> 5, q = idx & 31;
        float4 v = *(const float4*)(fc1s_w + (size_t)r * 512 + n0 + q * 4);
        v.x = to_tf32(v.x); v.y = to_tf32(v.y);
        v.z = to_tf32(v.z); v.w = to_tf32(v.w);
        *(float4*)&Bs[r][q * 4] = v;
    }
    __syncthreads();

    const int lane = tid & 31, wid = tid >> 5;
    const int wm = wid >> 2, wn = wid & 3;
    const int g = lane >> 2, c = lane & 3;
    float acc[2][4][4] = {};
#pragma unroll
    for (int ks = 0; ks < 16; ks++) {
        const int k0 = ks * 8;
        uint32_t af[2][4], bf[4][2];
#pragma unroll
        for (int mt = 0; mt < 2; mt++) {
            int r = wm * 32 + mt * 16 + g;
            af[mt][0] = __float_as_uint(As[r][k0 + c]);
            af[mt][1] = __float_as_uint(As[r + 8][k0 + c]);
            af[mt][2] = __float_as_uint(As[r][k0 + c + 4]);
            af[mt][3] = __float_as_uint(As[r + 8][k0 + c + 4]);
        }
#pragma unroll
        for (int nt = 0; nt < 4; nt++) {
            int col = wn * 32 + nt * 8 + g;
            bf[nt][0] = __float_as_uint(Bs[k0 + c][col]);
            bf[nt][1] = __float_as_uint(Bs[k0 + c + 4][col]);
        }
#pragma unroll
        for (int mt = 0; mt < 2; mt++)
#pragma unroll
            for (int nt = 0; nt < 4; nt++)
                mma_tf32(acc[mt][nt], af[mt], bf[nt]);
    }

#pragma unroll
    for (int nt = 0; nt < 4; nt++) {
        int col = n0 + wn * 32 + nt * 8 + c * 2;
        float s0 = bn_g[col]     * rsqrtf(bn_v[col]     + EPSV);
        float s1 = bn_g[col + 1] * rsqrtf(bn_v[col + 1] + EPSV);
        float o0 = fc1s_b[col]     - bn_m[col];
        float o1 = fc1s_b[col + 1] - bn_m[col + 1];
        float bb0 = bn_b[col], bb1 = bn_b[col + 1];
#pragma unroll
        for (int mt = 0; mt < 2; mt++) {
            int r = m0 + wm * 32 + mt * 16 + g;
            if (r < E_N)
                *(float2*)(g_H + (size_t)r * 512 + col) = make_float2(
                    fmaxf((acc[mt][nt][0] + o0) * s0 + bb0, 0.f),
                    fmaxf((acc[mt][nt][1] + o1) * s1 + bb1, 0.f));
            if (r + 8 < E_N)
                *(float2*)(g_H + (size_t)(r + 8) * 512 + col) = make_float2(
                    fmaxf((acc[mt][nt][2] + o0) * s0 + bb0, 0.f),
                    fmaxf((acc[mt][nt][3] + o1) * s1 + bb1, 0.f));
        }
    }
}

// ---------------------------------------------------------------------------
// Generic second GEMM (tensor, unchanged)
// ---------------------------------------------------------------------------
__global__ void __launch_bounds__(256, 2) k_gemm2(
    const float* __restrict__ W, const float* __restrict__ bias,
    float* __restrict__ out, int R, int mode) {
    extern __shared__ char smem[];
    float (*As)[132] = (float(*)[132])smem;
    float (*Bs)[136] = (float(*)[136])(smem + 64 * 132 * sizeof(float));
    const float* __restrict__ A = mode ? g_g : g_H;
    const int tid = threadIdx.x;
    const int m0 = blockIdx.x * 64;

    const int lane = tid & 31, wid = tid >> 5;
    const int wm = wid >> 2, wn = wid & 3;
    const int g = lane >> 2, c = lane & 3;
    float acc[2][4][4] = {};

    for (int kc = 0; kc < 4; kc++) {
#pragma unroll
        for (int it = 0; it < 8; it++) {
            int idx = tid + it * 256;
            int r = idx >> 5, q = idx & 31;
            float4 v = make_float4(0.f, 0.f, 0.f, 0.f);
            if (m0 + r < R)
                v = *(const float4*)(A + (size_t)(m0 + r) * 512 + kc * 128 + q * 4);
            v.x = to_tf32(v.x); v.y = to_tf32(v.y);
            v.z = to_tf32(v.z); v.w = to_tf32(v.w);
            *(float4*)&As[r][q * 4] = v;
        }
#pragma unroll
        for (int it = 0; it < 16; it++) {
            int idx = tid + it * 256;
            int r = idx >> 5, q = idx & 31;
            float4 v = *(const float4*)(W + (size_t)(kc * 128 + r) * 128 + q * 4);
            v.x = to_tf32(v.x); v.y = to_tf32(v.y);
            v.z = to_tf32(v.z); v.w = to_tf32(v.w);
            *(float4*)&Bs[r][q * 4] = v;
        }
        __syncthreads();
#pragma unroll
        for (int ks = 0; ks < 16; ks++) {
            const int k0 = ks * 8;
            uint32_t af[2][4], bf[4][2];
#pragma unroll
            for (int mt = 0; mt < 2; mt++) {
                int r = wm * 32 + mt * 16 + g;
                af[mt][0] = __float_as_uint(As[r][k0 + c]);
                af[mt][1] = __float_as_uint(As[r + 8][k0 + c]);
                af[mt][2] = __float_as_uint(As[r][k0 + c + 4]);
                af[mt][3] = __float_as_uint(As[r + 8][k0 + c + 4]);
            }
#pragma unroll
            for (int nt = 0; nt < 4; nt++) {
                int col = wn * 32 + nt * 8 + g;
                bf[nt][0] = __float_as_uint(Bs[k0 + c][col]);
                bf[nt][1] = __float_as_uint(Bs[k0 + c + 4][col]);
            }
#pragma unroll
            for (int mt = 0; mt < 2; mt++)
#pragma unroll
                for (int nt = 0; nt < 4; nt++)
                    mma_tf32(acc[mt][nt], af[mt], bf[nt]);
        }
        __syncthreads();
    }

#pragma unroll
    for (int mt = 0; mt < 2; mt++) {
#pragma unroll
        for (int nt = 0; nt < 4; nt++) {
            int col = wn * 32 + nt * 8 + c * 2;
            float b0 = bias[col], b1 = bias[col + 1];
#pragma unroll
            for (int half = 0; half < 2; half++) {
                int r = m0 + wm * 32 + mt * 16 + g + half * 8;
                if (r >= R) continue;
                float v0 = acc[mt][nt][half * 2 + 0];
                float v1 = acc[mt][nt][half * 2 + 1];
                if (mode == 0) {
                    *(float2*)(out + (size_t)r * 384 + col) =
                        make_float2(v0 + b0, v1 + b1);
                } else {
                    int br = r / E_N, e = r - br * E_N;
                    float fl = g_flag[r];
                    *(float2*)(out + (size_t)e * 384 + 128 + br * 128 + col) =
                        make_float2(v0 + b0 * fl, v1 + b1 * fl);
                }
            }
        }
    }
}

// ---------------------------------------------------------------------------
// k_branch: fp16 gathers of Pn/Pe
// ---------------------------------------------------------------------------
__global__ void __launch_bounds__(256) k_branch(
    const float* __restrict__ sel_dt, const float* __restrict__ sel_w,
    const float* __restrict__ fc1_b,
    const float* __restrict__ ln1_g, const float* __restrict__ ln1_b,
    const int* __restrict__ sel_nodes, const int* __restrict__ sel_edges) {
    const int e = blockIdx.x, br = blockIdx.y;
    const int tid = threadIdx.x;
    __shared__ float ct[KSEL][PCH];
    __shared__ float wn[KSEL];
    __shared__ int   nd_s[KSEL], ed_s[KSEL];
    __shared__ float red_s[KSEL][8], red_q[KSEL][8];
    __shared__ float mu_s[KSEL], rs_s[KSEL];
    __shared__ float flag_s;

    const size_t base = ((size_t)br * E_N + e) * KSEL;
    if (tid < KSEL) {
        int k = tid;
        float dt = sel_dt[base + k];
        wn[k]   = sel_w[base + k];
        nd_s[k] = sel_nodes[base + k];
        ed_s[k] = sel_edges[base + k];
        float x = 2.f * dt - 1.f;
        float t0 = 1.f, t1 = x;
        ct[k][0] = t0; ct[k][1] = t1;
#pragma unroll
        for (int p = 2; p < PCH; p++) {
            float t2 = 2.f * x * t1 - t0;
            ct[k][p] = t2;
            t0 = t1; t1 = t2;
        }
    }
    __syncthreads();
    if (tid == 0) {
        float ws = 0.f;
#pragma unroll
        for (int k = 0; k < KSEL; k++) ws += wn[k];
        float fl = (ws > 0.f) ? 1.f : 0.f;
        flag_s = fl;
        float inv = fl > 0.f ? 1.f / ws : 0.f;
#pragma unroll
        for (int k = 0; k < KSEL; k++) wn[k] *= inv;
    }

    const int c0 = tid * 2;
    float2 Gf[PCH];
#pragma unroll
    for (int p = 0; p < PCH; p++)
        Gf[p] = *(const float2*)(g_G + p * 512 + c0);

    float2 acc[KSEL];
    const float2 b1v = *(const float2*)(fc1_b + c0);
    __syncthreads();
#pragma unroll
    for (int k = 0; k < KSEL; k++) {
        float2 pn = __half22float2(*(const __half2*)(g_Pn + (size_t)nd_s[k] * 512 + c0));
        float2 pe = __half22float2(*(const __half2*)(g_Pe + (size_t)ed_s[k] * 512 + c0));
        acc[k].x = pn.x + pe.x + b1v.x;
        acc[k].y = pn.y + pe.y + b1v.y;
    }
#pragma unroll
    for (int k = 0; k < KSEL; k++) {
#pragma unroll
        for (int p = 0; p < PCH; p += 4) {
            float4 t = *(const float4*)&ct[k][p];
            acc[k].x += t.x * Gf[p].x + t.y * Gf[p + 1].x
                      + t.z * Gf[p + 2].x + t.w * Gf[p + 3].x;
            acc[k].y += t.x * Gf[p].y + t.y * Gf[p + 1].y
                      + t.z * Gf[p + 2].y + t.w * Gf[p + 3].y;
        }
    }
    const int lane = tid & 31, warp = tid >> 5;
#pragma unroll
    for (int k = 0; k < KSEL; k++) {
        float s = acc[k].x + acc[k].y;
        float q = acc[k].x * acc[k].x + acc[k].y * acc[k].y;
#pragma unroll
        for (int o = 16; o > 0; o >>= 1) {
            s += __shfl_down_sync(0xffffffffu, s, o);
            q += __shfl_down_sync(0xffffffffu, q, o);
        }
        if (lane == 0) { red_s[k][warp] = s; red_q[k][warp] = q; }
    }
    __syncthreads();
    if (tid < KSEL) {
        float s = 0.f, q = 0.f;
#pragma unroll
        for (int w = 0; w < 8; w++) { s += red_s[tid][w]; q += red_q[tid][w]; }
        float mu = s * (1.f / 512.f);
        float var = q * (1.f / 512.f) - mu * mu;
        mu_s[tid] = mu;
        rs_s[tid] = rsqrtf(var + EPSV);
    }
    __syncthreads();
    const float lg0 = ln1_g[c0], lg1 = ln1_g[c0 + 1];
    const float lb0 = ln1_b[c0], lb1 = ln1_b[c0 + 1];
    float o0 = 0.f, o1 = 0.f;
#pragma unroll
    for (int k = 0; k < KSEL; k++) {
        float h0 = fmaxf((acc[k].x - mu_s[k]) * rs_s[k] * lg0 + lb0, 0.f);
        float h1 = fmaxf((acc[k].y - mu_s[k]) * rs_s[k] * lg1 + lb1, 0.f);
        o0 += wn[k] * h0;
        o1 += wn[k] * h1;
    }
    *(float2*)(g_g + ((size_t)br * E_N + e) * 512 + c0) = make_float2(o0, o1);
    if (tid == 0) g_flag[br * E_N + e] = flag_s;
}

// ---------------------------------------------------------------------------
extern "C" void kernel_launch(void* const* d_in, const int* in_sizes, int n_in,
                              void* d_out, int out_size) {
    const float* memory    = (const float*)d_in[0];
    const float* edge_feat = (const float*)d_in[1];
    const float* sel_dt    = (const float*)d_in[2];
    const float* sel_w     = (const float*)d_in[3];
    const float* time_w    = (const float*)d_in[4];
    const float* time_b    = (const float*)d_in[5];
    const float* fc1_w     = (const float*)d_in[6];
    const float* fc1_b     = (const float*)d_in[7];
    const float* ln1_g     = (const float*)d_in[8];
    const float* ln1_b     = (const float*)d_in[9];
    const float* fc2_w     = (const float*)d_in[10];
    const float* fc2_b     = (const float*)d_in[11];
    const float* fc1s_w    = (const float*)d_in[12];
    const float* fc1s_b    = (const float*)d_in[13];
    const float* bn_g      = (const float*)d_in[14];
    const float* bn_b      = (const float*)d_in[15];
    const float* bn_m      = (const float*)d_in[16];
    const float* bn_v      = (const float*)d_in[17];
    const float* fc2s_w    = (const float*)d_in[18];
    const float* fc2s_b    = (const float*)d_in[19];
    const int* source_nodes = (const int*)d_in[20];
    const int* sel_nodes    = (const int*)d_in[21];
    const int* sel_edges    = (const int*)d_in[22];
    float* out = (float*)d_out;

    cudaFuncSetAttribute(k_pre_mma,  cudaFuncAttributeMaxDynamicSharedMemorySize, PRE_SMEM);
    cudaFuncSetAttribute(k_src1_mma, cudaFuncAttributeMaxDynamicSharedMemorySize, PRE_SMEM);
    cudaFuncSetAttribute(k_gemm2,    cudaFuncAttributeMaxDynamicSharedMemorySize, PRE_SMEM);

    k_cheb<<<1, 512>>>(time_w, time_b, fc1_w);
    k_pre_mma<<<dim3((NNODES + 63) / 64, 4), 256, PRE_SMEM>>>(memory, fc1_w, NNODES, 0);
    k_pre_mma<<<dim3((NEDGES + 63) / 64, 4), 256, PRE_SMEM>>>(edge_feat,
                                                              fc1_w + (size_t)128 * 512,
                                                              NEDGES, 1);
    k_src1_mma<<<dim3((E_N + 63) / 64, 4), 256, PRE_SMEM>>>(
        memory, fc1s_w, fc1s_b, bn_g, bn_b, bn_m, bn_v, source_nodes);
    k_gemm2<<<(E_N + 63) / 64, 256, PRE_SMEM>>>(fc2s_w, fc2s_b, out, E_N, 0);
    k_branch<<<dim3(E_N, NT_), 256>>>(sel_dt, sel_w, fc1_b, ln1_g, ln1_b,
                                      sel_nodes, sel_edges);
    k_gemm2<<<(NT_ * E_N + 63) / 64, 256, PRE_SMEM>>>(fc2_w, fc2_b, out,
                                                      NT_ * E_N, 1);
}

// round 8
// speedup vs baseline: 3.1405x; 1.2602x over previous
#include <cuda_runtime.h>
#include <cuda_fp16.h>
#include <math.h>
#include <cstdint>

#define E_N     20000
#define KSEL    20
#define D_      128
#define F1_     512
#define F2_     128
#define NT_     2
#define NNODES  200000
#define NEDGES  500000
#define EPSV    1e-5f
#define PCH     16

// Scratch (allocation-free rule: __device__ globals)
static __device__ __half g_Pn[(size_t)NNODES * F1_];
static __device__ __half g_Pe[(size_t)NEDGES * F1_];
static __device__ __half g_g [(size_t)NT_ * E_N * F1_];
static __device__ __half g_H [(size_t)E_N * F1_];
static __device__ float  g_flag[NT_ * E_N];
static __device__ float  g_G[PCH * F1_];
// fp16 weight panels, [n 128][k 128] with row stride 136 halfs (pad), per
// (matrix m, panel p). m: 0=fc1 node, 1=fc1 edge, 2=fc1s, 3=fc2s, 4=fc2.
#define PANEL_H 17408            // 128*136 halfs
static __device__ __align__(16) __half g_img[5][4][PANEL_H];

__device__ __forceinline__ void mma_f16(float* c, const uint32_t* a, const uint32_t* b) {
    asm volatile("mma.sync.aligned.m16n8k16.row.col.f32.f16.f16.f32 "
                 "{%0,%1,%2,%3}, {%4,%5,%6,%7}, {%8,%9}, {%0,%1,%2,%3};"
                 : "+f"(c[0]), "+f"(c[1]), "+f"(c[2]), "+f"(c[3])
                 : "r"(a[0]), "r"(a[1]), "r"(a[2]), "r"(a[3]),
                   "r"(b[0]), "r"(b[1]));
}
__device__ __forceinline__ uint32_t smem_u32(const void* p) {
    uint32_t a;
    asm("{ .reg .u64 t; cvta.to.shared.u64 t, %1; cvt.u32.u64 %0, t; }" : "=r"(a) : "l"(p));
    return a;
}

// ---------------------------------------------------------------------------
// Weight prep: bake fp16 [n][k] panels (stride 136) for all 5 weight matrices.
// ---------------------------------------------------------------------------
__global__ void k_prep(const float* __restrict__ fc1_w,
                       const float* __restrict__ fc1s_w,
                       const float* __restrict__ fc2s_w,
                       const float* __restrict__ fc2_w) {
    int idx = blockIdx.x * 256 + threadIdx.x;    // 5*4*128*128 = 327680
    int k = idx & 127;
    int n = (idx >> 7) & 127;
    int p = (idx >> 14) & 3;
    int m = idx >> 16;
    float v;
    if      (m == 0) v = fc1_w [(size_t)k          * 512 + p * 128 + n];
    else if (m == 1) v = fc1_w [(size_t)(128 + k)  * 512 + p * 128 + n];
    else if (m == 2) v = fc1s_w[(size_t)k          * 512 + p * 128 + n];
    else if (m == 3) v = fc2s_w[(size_t)(p * 128 + k) * 128 + n];
    else             v = fc2_w [(size_t)(p * 128 + k) * 128 + n];
    g_img[m][p][n * 136 + k] = __float2half(v);
}

// ---------------------------------------------------------------------------
// Chebyshev prolog (unchanged)
// ---------------------------------------------------------------------------
__global__ void __launch_bounds__(512) k_cheb(const float* __restrict__ time_w,
                                              const float* __restrict__ time_b,
                                              const float* __restrict__ fc1_w) {
    __shared__ float teq[PCH][100];
    const int tid = threadIdx.x;
    for (int i = tid; i < PCH * 100; i += 512) {
        int q = i / 100, j = i - q * 100;
        float xq  = cospif((q + 0.5f) / (float)PCH);
        float dtq = 0.5f * (xq + 1.0f);
        teq[q][j] = cosf(dtq * time_w[j] + time_b[j]);
    }
    __syncthreads();
    const float* __restrict__ W1t = fc1_w + (size_t)256 * 512;
    float M[PCH];
#pragma unroll
    for (int q = 0; q < PCH; q++) M[q] = 0.f;
    for (int j = 0; j < 100; j++) {
        float w = W1t[(size_t)j * 512 + tid];
#pragma unroll
        for (int q = 0; q < PCH; q++) M[q] += teq[q][j] * w;
    }
#pragma unroll
    for (int p = 0; p < PCH; p++) {
        float s = 0.f;
#pragma unroll
        for (int q = 0; q < PCH; q++)
            s += cospif(p * (q + 0.5f) / (float)PCH) * M[q];
        g_G[p * 512 + tid] = s * ((p == 0 ? 1.0f : 2.0f) / (float)PCH);
    }
}

// ===========================================================================
// fp16 mma tile machinery: CTA 64m x 128n, K=128 per chunk, 8 warps (2x4),
// warp tile 32x32 via 2x4 m16n8k16.
// As[64][136] half, Bs[128][136] half ([n][k]); conflict-free fragments.
// ===========================================================================
#define SMEM_H (64 * 136 * 2 + 128 * 136 * 2)

#define FP16_MAINLOOP(As, Bs, acc, wm, wn, g, c)                               \
    _Pragma("unroll")                                                          \
    for (int ks = 0; ks < 8; ks++) {                                           \
        const int k0 = ks * 16;                                                \
        uint32_t af[2][4], bf[4][2];                                           \
        _Pragma("unroll")                                                      \
        for (int mt = 0; mt < 2; mt++) {                                       \
            int r = wm * 32 + mt * 16 + g;                                     \
            af[mt][0] = *(const uint32_t*)&As[r][k0 + 2 * c];                  \
            af[mt][1] = *(const uint32_t*)&As[r + 8][k0 + 2 * c];              \
            af[mt][2] = *(const uint32_t*)&As[r][k0 + 2 * c + 8];              \
            af[mt][3] = *(const uint32_t*)&As[r + 8][k0 + 2 * c + 8];          \
        }                                                                      \
        _Pragma("unroll")                                                      \
        for (int nt = 0; nt < 4; nt++) {                                       \
            int n = wn * 32 + nt * 8 + g;                                      \
            bf[nt][0] = *(const uint32_t*)&Bs[n][k0 + 2 * c];                  \
            bf[nt][1] = *(const uint32_t*)&Bs[n][k0 + 2 * c + 8];              \
        }                                                                      \
        _Pragma("unroll")                                                      \
        for (int mt = 0; mt < 2; mt++)                                         \
            _Pragma("unroll")                                                  \
            for (int nt = 0; nt < 4; nt++)                                     \
                mma_f16(acc[mt][nt], af[mt], bf[nt]);                          \
    }

// ---------------------------------------------------------------------------
// k_pre: P = A[N,128] @ W panel -> fp16. grid (ceil(N/64), 4).
// ---------------------------------------------------------------------------
__global__ void __launch_bounds__(256, 3) k_pre_h(const float* __restrict__ A,
                                                  int N, int which) {
    extern __shared__ char smem[];
    __half (*As)[136] = (__half(*)[136])smem;
    __half (*Bs)[136] = (__half(*)[136])(smem + 64 * 136 * 2);
    __half* __restrict__ C = which ? g_Pe : g_Pn;
    const int tid = threadIdx.x;
    const int m0 = blockIdx.x * 64;

#pragma unroll
    for (int it = 0; it < 8; it++) {
        int idx = tid + it * 256;
        int r = idx >> 5, q = idx & 31;
        float4 v = make_float4(0.f, 0.f, 0.f, 0.f);
        if (m0 + r < N) v = *(const float4*)(A + (size_t)(m0 + r) * 128 + q * 4);
        __half2 h01 = __floats2half2_rn(v.x, v.y);
        __half2 h23 = __floats2half2_rn(v.z, v.w);
        *(uint2*)&As[r][q * 4] = make_uint2(*(uint32_t*)&h01, *(uint32_t*)&h23);
    }
    {
        const uint4* src = (const uint4*)g_img[which][blockIdx.y];
        uint4* dst = (uint4*)Bs;
        for (int i = tid; i < PANEL_H / 8; i += 256) dst[i] = src[i];
    }
    __syncthreads();

    const int lane = tid & 31, wid = tid >> 5;
    const int wm = wid >> 2, wn = wid & 3;
    const int g = lane >> 2, c = lane & 3;
    float acc[2][4][4] = {};
    FP16_MAINLOOP(As, Bs, acc, wm, wn, g, c)

    const int n0 = blockIdx.y * 128;
#pragma unroll
    for (int mt = 0; mt < 2; mt++) {
#pragma unroll
        for (int nt = 0; nt < 4; nt++) {
            int r = m0 + wm * 32 + mt * 16 + g;
            int col = n0 + wn * 32 + nt * 8 + c * 2;
            if (r < N)
                *(__half2*)(C + (size_t)r * 512 + col) =
                    __floats2half2_rn(acc[mt][nt][0], acc[mt][nt][1]);
            if (r + 8 < N)
                *(__half2*)(C + (size_t)(r + 8) * 512 + col) =
                    __floats2half2_rn(acc[mt][nt][2], acc[mt][nt][3]);
        }
    }
}

// ---------------------------------------------------------------------------
// Src GEMM1: g_H = relu(BN(memory[src] @ fc1s_w + b)). grid (ceil(E/64), 4).
// ---------------------------------------------------------------------------
__global__ void __launch_bounds__(256, 3) k_src1_h(
    const float* __restrict__ memory, const float* __restrict__ fc1s_b,
    const float* __restrict__ bn_g, const float* __restrict__ bn_b,
    const float* __restrict__ bn_m, const float* __restrict__ bn_v,
    const int* __restrict__ src) {
    extern __shared__ char smem[];
    __half (*As)[136] = (__half(*)[136])smem;
    __half (*Bs)[136] = (__half(*)[136])(smem + 64 * 136 * 2);
    __shared__ int nd[64];
    const int tid = threadIdx.x;
    const int m0 = blockIdx.x * 64;

    if (tid < 64) nd[tid] = (m0 + tid < E_N) ? src[m0 + tid] : 0;
    __syncthreads();
#pragma unroll
    for (int it = 0; it < 8; it++) {
        int idx = tid + it * 256;
        int r = idx >> 5, q = idx & 31;
        float4 v = make_float4(0.f, 0.f, 0.f, 0.f);
        if (m0 + r < E_N) v = *(const float4*)(memory + (size_t)nd[r] * 128 + q * 4);
        __half2 h01 = __floats2half2_rn(v.x, v.y);
        __half2 h23 = __floats2half2_rn(v.z, v.w);
        *(uint2*)&As[r][q * 4] = make_uint2(*(uint32_t*)&h01, *(uint32_t*)&h23);
    }
    {
        const uint4* src4 = (const uint4*)g_img[2][blockIdx.y];
        uint4* dst = (uint4*)Bs;
        for (int i = tid; i < PANEL_H / 8; i += 256) dst[i] = src4[i];
    }
    __syncthreads();

    const int lane = tid & 31, wid = tid >> 5;
    const int wm = wid >> 2, wn = wid & 3;
    const int g = lane >> 2, c = lane & 3;
    float acc[2][4][4] = {};
    FP16_MAINLOOP(As, Bs, acc, wm, wn, g, c)

    const int n0 = blockIdx.y * 128;
#pragma unroll
    for (int nt = 0; nt < 4; nt++) {
        int col = n0 + wn * 32 + nt * 8 + c * 2;
        float s0 = bn_g[col]     * rsqrtf(bn_v[col]     + EPSV);
        float s1 = bn_g[col + 1] * rsqrtf(bn_v[col + 1] + EPSV);
        float o0 = fc1s_b[col]     - bn_m[col];
        float o1 = fc1s_b[col + 1] - bn_m[col + 1];
        float bb0 = bn_b[col], bb1 = bn_b[col + 1];
#pragma unroll
        for (int mt = 0; mt < 2; mt++) {
            int r = m0 + wm * 32 + mt * 16 + g;
            if (r < E_N)
                *(__half2*)(g_H + (size_t)r * 512 + col) = __floats2half2_rn(
                    fmaxf((acc[mt][nt][0] + o0) * s0 + bb0, 0.f),
                    fmaxf((acc[mt][nt][1] + o1) * s1 + bb1, 0.f));
            if (r + 8 < E_N)
                *(__half2*)(g_H + (size_t)(r + 8) * 512 + col) = __floats2half2_rn(
                    fmaxf((acc[mt][nt][2] + o0) * s0 + bb0, 0.f),
                    fmaxf((acc[mt][nt][3] + o1) * s1 + bb1, 0.f));
        }
    }
}

// ---------------------------------------------------------------------------
// Second GEMM: C[R,128] = A[R,512](fp16) @ W[512,128] + bias.
// mode 0: A=g_H -> out[:, 0:128); mode 1: A=g_g -> out[:, 128+br*128)
// ---------------------------------------------------------------------------
__global__ void __launch_bounds__(256, 3) k_gemm2_h(
    const float* __restrict__ bias, float* __restrict__ out, int R, int mode) {
    extern __shared__ char smem[];
    __half (*As)[136] = (__half(*)[136])smem;
    __half (*Bs)[136] = (__half(*)[136])(smem + 64 * 136 * 2);
    const __half* __restrict__ A = mode ? g_g : g_H;
    const int wimg = mode ? 4 : 3;
    const int tid = threadIdx.x;
    const int m0 = blockIdx.x * 64;

    const int lane = tid & 31, wid = tid >> 5;
    const int wm = wid >> 2, wn = wid & 3;
    const int g = lane >> 2, c = lane & 3;
    float acc[2][4][4] = {};

    for (int kc = 0; kc < 4; kc++) {
#pragma unroll
        for (int it = 0; it < 8; it++) {
            int idx = tid + it * 256;
            int r = idx >> 5, q = idx & 31;
            uint2 v = make_uint2(0u, 0u);
            if (m0 + r < R)
                v = *(const uint2*)(A + (size_t)(m0 + r) * 512 + kc * 128 + q * 4);
            *(uint2*)&As[r][q * 4] = v;
        }
        {
            const uint4* src4 = (const uint4*)g_img[wimg][kc];
            uint4* dst = (uint4*)Bs;
            for (int i = tid; i < PANEL_H / 8; i += 256) dst[i] = src4[i];
        }
        __syncthreads();
        FP16_MAINLOOP(As, Bs, acc, wm, wn, g, c)
        __syncthreads();
    }

#pragma unroll
    for (int mt = 0; mt < 2; mt++) {
#pragma unroll
        for (int nt = 0; nt < 4; nt++) {
            int col = wn * 32 + nt * 8 + c * 2;
            float b0 = bias[col], b1 = bias[col + 1];
#pragma unroll
            for (int half = 0; half < 2; half++) {
                int r = m0 + wm * 32 + mt * 16 + g + half * 8;
                if (r >= R) continue;
                float v0 = acc[mt][nt][half * 2 + 0];
                float v1 = acc[mt][nt][half * 2 + 1];
                if (mode == 0) {
                    *(float2*)(out + (size_t)r * 384 + col) =
                        make_float2(v0 + b0, v1 + b1);
                } else {
                    int br = r / E_N, e = r - br * E_N;
                    float fl = g_flag[r];
                    *(float2*)(out + (size_t)e * 384 + 128 + br * 128 + col) =
                        make_float2(v0 + b0 * fl, v1 + b1 * fl);
                }
            }
        }
    }
}

// ---------------------------------------------------------------------------
// k_branch: fp16 gathers + packed f32x2 Chebyshev contraction.
// ---------------------------------------------------------------------------
__global__ void __launch_bounds__(256) k_branch(
    const float* __restrict__ sel_dt, const float* __restrict__ sel_w,
    const float* __restrict__ fc1_b,
    const float* __restrict__ ln1_g, const float* __restrict__ ln1_b,
    const int* __restrict__ sel_nodes, const int* __restrict__ sel_edges) {
    const int e = blockIdx.x, br = blockIdx.y;
    const int tid = threadIdx.x;
    __shared__ float ctd[KSEL][PCH * 2];   // duplicated pairs: (T_p, T_p)
    __shared__ float wn[KSEL];
    __shared__ int   nd_s[KSEL], ed_s[KSEL];
    __shared__ float red_s[KSEL][8], red_q[KSEL][8];
    __shared__ float mu_s[KSEL], rs_s[KSEL];
    __shared__ float flag_s;

    const size_t base = ((size_t)br * E_N + e) * KSEL;
    if (tid < KSEL) {
        int k = tid;
        float dt = sel_dt[base + k];
        wn[k]   = sel_w[base + k];
        nd_s[k] = sel_nodes[base + k];
        ed_s[k] = sel_edges[base + k];
        float x = 2.f * dt - 1.f;
        float t0 = 1.f, t1 = x;
        ctd[k][0] = t0; ctd[k][1] = t0;
        ctd[k][2] = t1; ctd[k][3] = t1;
#pragma unroll
        for (int p = 2; p < PCH; p++) {
            float t2 = 2.f * x * t1 - t0;
            ctd[k][2 * p] = t2; ctd[k][2 * p + 1] = t2;
            t0 = t1; t1 = t2;
        }
    }
    __syncthreads();
    if (tid == 0) {
        float ws = 0.f;
#pragma unroll
        for (int k = 0; k < KSEL; k++) ws += wn[k];
        float fl = (ws > 0.f) ? 1.f : 0.f;
        flag_s = fl;
        float inv = fl > 0.f ? 1.f / ws : 0.f;
#pragma unroll
        for (int k = 0; k < KSEL; k++) wn[k] *= inv;
    }

    const int c0 = tid * 2;
    unsigned long long Gd[PCH];
#pragma unroll
    for (int p = 0; p < PCH; p++)
        Gd[p] = *(const unsigned long long*)(g_G + p * 512 + c0);

    unsigned long long acc[KSEL];
    const float2 b1v = *(const float2*)(fc1_b + c0);
    const uint32_t ctd_base = smem_u32(ctd);
    __syncthreads();
#pragma unroll
    for (int k = 0; k < KSEL; k++) {
        float2 pn = __half22float2(*(const __half2*)(g_Pn + (size_t)nd_s[k] * 512 + c0));
        float2 pe = __half22float2(*(const __half2*)(g_Pe + (size_t)ed_s[k] * 512 + c0));
        float2 a = make_float2(pn.x + pe.x + b1v.x, pn.y + pe.y + b1v.y);
        acc[k] = *(unsigned long long*)&a;
    }
#pragma unroll
    for (int k = 0; k < KSEL; k++) {
        uint32_t row = ctd_base + k * (PCH * 2 * 4);
#pragma unroll
        for (int p = 0; p < PCH; p += 2) {
            unsigned long long t0, t1;
            asm("ld.shared.v2.b64 {%0, %1}, [%2];"
                : "=l"(t0), "=l"(t1) : "r"(row + p * 8));
            asm("fma.rn.f32x2 %0, %1, %2, %0;" : "+l"(acc[k]) : "l"(t0), "l"(Gd[p]));
            asm("fma.rn.f32x2 %0, %1, %2, %0;" : "+l"(acc[k]) : "l"(t1), "l"(Gd[p + 1]));
        }
    }
    const int lane = tid & 31, warp = tid >> 5;
#pragma unroll
    for (int k = 0; k < KSEL; k++) {
        float2 a = *(float2*)&acc[k];
        float s = a.x + a.y;
        float q = a.x * a.x + a.y * a.y;
#pragma unroll
        for (int o = 16; o > 0; o >>= 1) {
            s += __shfl_down_sync(0xffffffffu, s, o);
            q += __shfl_down_sync(0xffffffffu, q, o);
        }
        if (lane == 0) { red_s[k][warp] = s; red_q[k][warp] = q; }
    }
    __syncthreads();
    if (tid < KSEL) {
        float s = 0.f, q = 0.f;
#pragma unroll
        for (int w = 0; w < 8; w++) { s += red_s[tid][w]; q += red_q[tid][w]; }
        float mu = s * (1.f / 512.f);
        float var = q * (1.f / 512.f) - mu * mu;
        mu_s[tid] = mu;
        rs_s[tid] = rsqrtf(var + EPSV);
    }
    __syncthreads();
    const float lg0 = ln1_g[c0], lg1 = ln1_g[c0 + 1];
    const float lb0 = ln1_b[c0], lb1 = ln1_b[c0 + 1];
    float o0 = 0.f, o1 = 0.f;
#pragma unroll
    for (int k = 0; k < KSEL; k++) {
        float2 a = *(float2*)&acc[k];
        float h0 = fmaxf((a.x - mu_s[k]) * rs_s[k] * lg0 + lb0, 0.f);
        float h1 = fmaxf((a.y - mu_s[k]) * rs_s[k] * lg1 + lb1, 0.f);
        o0 += wn[k] * h0;
        o1 += wn[k] * h1;
    }
    *(__half2*)(g_g + ((size_t)br * E_N + e) * 512 + c0) = __floats2half2_rn(o0, o1);
    if (tid == 0) g_flag[br * E_N + e] = flag_s;
}

// ---------------------------------------------------------------------------
extern "C" void kernel_launch(void* const* d_in, const int* in_sizes, int n_in,
                              void* d_out, int out_size) {
    const float* memory    = (const float*)d_in[0];
    const float* edge_feat = (const float*)d_in[1];
    const float* sel_dt    = (const float*)d_in[2];
    const float* sel_w     = (const float*)d_in[3];
    const float* time_w    = (const float*)d_in[4];
    const float* time_b    = (const float*)d_in[5];
    const float* fc1_w     = (const float*)d_in[6];
    const float* fc1_b     = (const float*)d_in[7];
    const float* ln1_g     = (const float*)d_in[8];
    const float* ln1_b     = (const float*)d_in[9];
    const float* fc2_w     = (const float*)d_in[10];
    const float* fc2_b     = (const float*)d_in[11];
    const float* fc1s_w    = (const float*)d_in[12];
    const float* fc1s_b    = (const float*)d_in[13];
    const float* bn_g      = (const float*)d_in[14];
    const float* bn_b      = (const float*)d_in[15];
    const float* bn_m      = (const float*)d_in[16];
    const float* bn_v      = (const float*)d_in[17];
    const float* fc2s_w    = (const float*)d_in[18];
    const float* fc2s_b    = (const float*)d_in[19];
    const int* source_nodes = (const int*)d_in[20];
    const int* sel_nodes    = (const int*)d_in[21];
    const int* sel_edges    = (const int*)d_in[22];
    float* out = (float*)d_out;

    cudaFuncSetAttribute(k_pre_h,   cudaFuncAttributeMaxDynamicSharedMemorySize, SMEM_H);
    cudaFuncSetAttribute(k_src1_h,  cudaFuncAttributeMaxDynamicSharedMemorySize, SMEM_H);
    cudaFuncSetAttribute(k_gemm2_h, cudaFuncAttributeMaxDynamicSharedMemorySize, SMEM_H);

    // Bake fp16 weight panels + Chebyshev compression
    k_prep<<<1280, 256>>>(fc1_w, fc1s_w, fc2s_w, fc2_w);
    k_cheb<<<1, 512>>>(time_w, time_b, fc1_w);
    // fp16 tensor-core precompute of node/edge fc1 projections
    k_pre_h<<<dim3((NNODES + 63) / 64, 4), 256, SMEM_H>>>(memory, NNODES, 0);
    k_pre_h<<<dim3((NEDGES + 63) / 64, 4), 256, SMEM_H>>>(edge_feat, NEDGES, 1);
    // Source branch
    k_src1_h<<<dim3((E_N + 63) / 64, 4), 256, SMEM_H>>>(
        memory, fc1s_b, bn_g, bn_b, bn_m, bn_v, source_nodes);
    k_gemm2_h<<<(E_N + 63) / 64, 256, SMEM_H>>>(fc2s_b, out, E_N, 0);
    // TPPR branches
    k_branch<<<dim3(E_N, NT_), 256>>>(sel_dt, sel_w, fc1_b, ln1_g, ln1_b,
                                      sel_nodes, sel_edges);
    k_gemm2_h<<<(NT_ * E_N + 63) / 64, 256, SMEM_H>>>(fc2_b, out, NT_ * E_N, 1);
}

// round 9
// speedup vs baseline: 3.5444x; 1.1286x over previous
#include <cuda_runtime.h>
#include <cuda_fp16.h>
#include <math.h>
#include <cstdint>

#define E_N     20000
#define KSEL    20
#define D_      128
#define F1_     512
#define F2_     128
#define NT_     2
#define NNODES  200000
#define NEDGES  500000
#define EPSV    1e-5f
#define PCH     16

// Scratch (allocation-free rule: __device__ globals)
static __device__ __half g_Pn[(size_t)NNODES * F1_];
static __device__ __half g_Pe[(size_t)NEDGES * F1_];
static __device__ __half g_g [(size_t)NT_ * E_N * F1_];
static __device__ __half g_H [(size_t)E_N * F1_];
static __device__ float  g_flag[NT_ * E_N];
static __device__ float  g_G[PCH * F1_];
// fp16 weight panels, [n 128][k 128] stride 136, per (matrix m, panel p).
// m: 0=fc1 node, 1=fc1 edge, 2=fc1s, 3=fc2s, 4=fc2.
#define PANEL_H 17408
static __device__ __align__(16) __half g_img[5][4][PANEL_H];

__device__ __forceinline__ void mma_f16(float* c, const uint32_t* a, const uint32_t* b) {
    asm volatile("mma.sync.aligned.m16n8k16.row.col.f32.f16.f16.f32 "
                 "{%0,%1,%2,%3}, {%4,%5,%6,%7}, {%8,%9}, {%0,%1,%2,%3};"
                 : "+f"(c[0]), "+f"(c[1]), "+f"(c[2]), "+f"(c[3])
                 : "r"(a[0]), "r"(a[1]), "r"(a[2]), "r"(a[3]),
                   "r"(b[0]), "r"(b[1]));
}
__device__ __forceinline__ uint32_t smem_u32(const void* p) {
    uint32_t a;
    asm("{ .reg .u64 t; cvta.to.shared.u64 t, %1; cvt.u32.u64 %0, t; }" : "=r"(a) : "l"(p));
    return a;
}

// ---------------------------------------------------------------------------
// Weight prep (unchanged)
// ---------------------------------------------------------------------------
__global__ void k_prep(const float* __restrict__ fc1_w,
                       const float* __restrict__ fc1s_w,
                       const float* __restrict__ fc2s_w,
                       const float* __restrict__ fc2_w) {
    int idx = blockIdx.x * 256 + threadIdx.x;
    int k = idx & 127;
    int n = (idx >> 7) & 127;
    int p = (idx >> 14) & 3;
    int m = idx >> 16;
    float v;
    if      (m == 0) v = fc1_w [(size_t)k          * 512 + p * 128 + n];
    else if (m == 1) v = fc1_w [(size_t)(128 + k)  * 512 + p * 128 + n];
    else if (m == 2) v = fc1s_w[(size_t)k          * 512 + p * 128 + n];
    else if (m == 3) v = fc2s_w[(size_t)(p * 128 + k) * 128 + n];
    else             v = fc2_w [(size_t)(p * 128 + k) * 128 + n];
    g_img[m][p][n * 136 + k] = __float2half(v);
}

// ---------------------------------------------------------------------------
// Chebyshev prolog (unchanged)
// ---------------------------------------------------------------------------
__global__ void __launch_bounds__(512) k_cheb(const float* __restrict__ time_w,
                                              const float* __restrict__ time_b,
                                              const float* __restrict__ fc1_w) {
    __shared__ float teq[PCH][100];
    const int tid = threadIdx.x;
    for (int i = tid; i < PCH * 100; i += 512) {
        int q = i / 100, j = i - q * 100;
        float xq  = cospif((q + 0.5f) / (float)PCH);
        float dtq = 0.5f * (xq + 1.0f);
        teq[q][j] = cosf(dtq * time_w[j] + time_b[j]);
    }
    __syncthreads();
    const float* __restrict__ W1t = fc1_w + (size_t)256 * 512;
    float M[PCH];
#pragma unroll
    for (int q = 0; q < PCH; q++) M[q] = 0.f;
    for (int j = 0; j < 100; j++) {
        float w = W1t[(size_t)j * 512 + tid];
#pragma unroll
        for (int q = 0; q < PCH; q++) M[q] += teq[q][j] * w;
    }
#pragma unroll
    for (int p = 0; p < PCH; p++) {
        float s = 0.f;
#pragma unroll
        for (int q = 0; q < PCH; q++)
            s += cospif(p * (q + 0.5f) / (float)PCH) * M[q];
        g_G[p * 512 + tid] = s * ((p == 0 ? 1.0f : 2.0f) / (float)PCH);
    }
}

// ===========================================================================
// fp16 mma machinery
// ===========================================================================
#define SMEM_64   (64 * 136 * 2 + 128 * 136 * 2)
#define SMEM_128  (128 * 136 * 2 + 128 * 136 * 2)

// 8 warps as 2(M) x 4(N); warp tile 32x32 (used by src1/gemm2)
#define FP16_MAINLOOP(As, Bs, acc, wm, wn, g, c)                               \
    _Pragma("unroll")                                                          \
    for (int ks = 0; ks < 8; ks++) {                                           \
        const int k0 = ks * 16;                                                \
        uint32_t af[2][4], bf[4][2];                                           \
        _Pragma("unroll")                                                      \
        for (int mt = 0; mt < 2; mt++) {                                       \
            int r = wm * 32 + mt * 16 + g;                                     \
            af[mt][0] = *(const uint32_t*)&As[r][k0 + 2 * c];                  \
            af[mt][1] = *(const uint32_t*)&As[r + 8][k0 + 2 * c];              \
            af[mt][2] = *(const uint32_t*)&As[r][k0 + 2 * c + 8];              \
            af[mt][3] = *(const uint32_t*)&As[r + 8][k0 + 2 * c + 8];          \
        }                                                                      \
        _Pragma("unroll")                                                      \
        for (int nt = 0; nt < 4; nt++) {                                       \
            int n = wn * 32 + nt * 8 + g;                                      \
            bf[nt][0] = *(const uint32_t*)&Bs[n][k0 + 2 * c];                  \
            bf[nt][1] = *(const uint32_t*)&Bs[n][k0 + 2 * c + 8];              \
        }                                                                      \
        _Pragma("unroll")                                                      \
        for (int mt = 0; mt < 2; mt++)                                         \
            _Pragma("unroll")                                                  \
            for (int nt = 0; nt < 4; nt++)                                     \
                mma_f16(acc[mt][nt], af[mt], bf[nt]);                          \
    }

// ---------------------------------------------------------------------------
// k_pre: one CTA = 128 rows x 512 cols. A loaded once; loop 4 B panels.
// 8 warps as 4(M) x 2(N); warp tile 32x64 (2x8 m16n8k16), acc 64 regs.
// ---------------------------------------------------------------------------
__global__ void __launch_bounds__(256, 2) k_pre_h(const float* __restrict__ A,
                                                  int N, int which) {
    extern __shared__ char smem[];
    __half (*As)[136] = (__half(*)[136])smem;
    __half (*Bs)[136] = (__half(*)[136])(smem + 128 * 136 * 2);
    __half* __restrict__ C = which ? g_Pe : g_Pn;
    const int tid = threadIdx.x;
    const int m0 = blockIdx.x * 128;

    // A tile 128x128 fp32 -> fp16 (single load for all 4 panels)
#pragma unroll
    for (int it = 0; it < 16; it++) {
        int idx = tid + it * 256;
        int r = idx >> 5, q = idx & 31;
        float4 v = make_float4(0.f, 0.f, 0.f, 0.f);
        if (m0 + r < N) v = *(const float4*)(A + (size_t)(m0 + r) * 128 + q * 4);
        __half2 h01 = __floats2half2_rn(v.x, v.y);
        __half2 h23 = __floats2half2_rn(v.z, v.w);
        *(uint2*)&As[r][q * 4] = make_uint2(*(uint32_t*)&h01, *(uint32_t*)&h23);
    }

    const int lane = tid & 31, wid = tid >> 5;
    const int wm = wid >> 1, wn = wid & 1;       // 4(M) x 2(N)
    const int g = lane >> 2, c = lane & 3;

    for (int p = 0; p < 4; p++) {
        // B panel copy (L2-resident source)
        {
            const uint4* src = (const uint4*)g_img[which][p];
            uint4* dst = (uint4*)Bs;
            for (int i = tid; i < PANEL_H / 8; i += 256) dst[i] = src[i];
        }
        __syncthreads();

        float acc[2][8][4] = {};
#pragma unroll
        for (int ks = 0; ks < 8; ks++) {
            const int k0 = ks * 16;
            uint32_t af[2][4], bf[8][2];
#pragma unroll
            for (int mt = 0; mt < 2; mt++) {
                int r = wm * 32 + mt * 16 + g;
                af[mt][0] = *(const uint32_t*)&As[r][k0 + 2 * c];
                af[mt][1] = *(const uint32_t*)&As[r + 8][k0 + 2 * c];
                af[mt][2] = *(const uint32_t*)&As[r][k0 + 2 * c + 8];
                af[mt][3] = *(const uint32_t*)&As[r + 8][k0 + 2 * c + 8];
            }
#pragma unroll
            for (int nt = 0; nt < 8; nt++) {
                int n = wn * 64 + nt * 8 + g;
                bf[nt][0] = *(const uint32_t*)&Bs[n][k0 + 2 * c];
                bf[nt][1] = *(const uint32_t*)&Bs[n][k0 + 2 * c + 8];
            }
#pragma unroll
            for (int mt = 0; mt < 2; mt++)
#pragma unroll
                for (int nt = 0; nt < 8; nt++)
                    mma_f16(acc[mt][nt], af[mt], bf[nt]);
        }

        const int n0 = p * 128;
#pragma unroll
        for (int mt = 0; mt < 2; mt++) {
#pragma unroll
            for (int nt = 0; nt < 8; nt++) {
                int r = m0 + wm * 32 + mt * 16 + g;
                int col = n0 + wn * 64 + nt * 8 + c * 2;
                if (r < N)
                    *(__half2*)(C + (size_t)r * 512 + col) =
                        __floats2half2_rn(acc[mt][nt][0], acc[mt][nt][1]);
                if (r + 8 < N)
                    *(__half2*)(C + (size_t)(r + 8) * 512 + col) =
                        __floats2half2_rn(acc[mt][nt][2], acc[mt][nt][3]);
            }
        }
        __syncthreads();   // Bs reused next panel
    }
}

// ---------------------------------------------------------------------------
// Src GEMM1 (unchanged from R8): g_H = relu(BN(memory[src] @ fc1s_w + b)).
// ---------------------------------------------------------------------------
__global__ void __launch_bounds__(256, 3) k_src1_h(
    const float* __restrict__ memory, const float* __restrict__ fc1s_b,
    const float* __restrict__ bn_g, const float* __restrict__ bn_b,
    const float* __restrict__ bn_m, const float* __restrict__ bn_v,
    const int* __restrict__ src) {
    extern __shared__ char smem[];
    __half (*As)[136] = (__half(*)[136])smem;
    __half (*Bs)[136] = (__half(*)[136])(smem + 64 * 136 * 2);
    __shared__ int nd[64];
    const int tid = threadIdx.x;
    const int m0 = blockIdx.x * 64;

    if (tid < 64) nd[tid] = (m0 + tid < E_N) ? src[m0 + tid] : 0;
    __syncthreads();
#pragma unroll
    for (int it = 0; it < 8; it++) {
        int idx = tid + it * 256;
        int r = idx >> 5, q = idx & 31;
        float4 v = make_float4(0.f, 0.f, 0.f, 0.f);
        if (m0 + r < E_N) v = *(const float4*)(memory + (size_t)nd[r] * 128 + q * 4);
        __half2 h01 = __floats2half2_rn(v.x, v.y);
        __half2 h23 = __floats2half2_rn(v.z, v.w);
        *(uint2*)&As[r][q * 4] = make_uint2(*(uint32_t*)&h01, *(uint32_t*)&h23);
    }
    {
        const uint4* src4 = (const uint4*)g_img[2][blockIdx.y];
        uint4* dst = (uint4*)Bs;
        for (int i = tid; i < PANEL_H / 8; i += 256) dst[i] = src4[i];
    }
    __syncthreads();

    const int lane = tid & 31, wid = tid >> 5;
    const int wm = wid >> 2, wn = wid & 3;
    const int g = lane >> 2, c = lane & 3;
    float acc[2][4][4] = {};
    FP16_MAINLOOP(As, Bs, acc, wm, wn, g, c)

    const int n0 = blockIdx.y * 128;
#pragma unroll
    for (int nt = 0; nt < 4; nt++) {
        int col = n0 + wn * 32 + nt * 8 + c * 2;
        float s0 = bn_g[col]     * rsqrtf(bn_v[col]     + EPSV);
        float s1 = bn_g[col + 1] * rsqrtf(bn_v[col + 1] + EPSV);
        float o0 = fc1s_b[col]     - bn_m[col];
        float o1 = fc1s_b[col + 1] - bn_m[col + 1];
        float bb0 = bn_b[col], bb1 = bn_b[col + 1];
#pragma unroll
        for (int mt = 0; mt < 2; mt++) {
            int r = m0 + wm * 32 + mt * 16 + g;
            if (r < E_N)
                *(__half2*)(g_H + (size_t)r * 512 + col) = __floats2half2_rn(
                    fmaxf((acc[mt][nt][0] + o0) * s0 + bb0, 0.f),
                    fmaxf((acc[mt][nt][1] + o1) * s1 + bb1, 0.f));
            if (r + 8 < E_N)
                *(__half2*)(g_H + (size_t)(r + 8) * 512 + col) = __floats2half2_rn(
                    fmaxf((acc[mt][nt][2] + o0) * s0 + bb0, 0.f),
                    fmaxf((acc[mt][nt][3] + o1) * s1 + bb1, 0.f));
        }
    }
}

// ---------------------------------------------------------------------------
// Second GEMM (unchanged from R8)
// ---------------------------------------------------------------------------
__global__ void __launch_bounds__(256, 3) k_gemm2_h(
    const float* __restrict__ bias, float* __restrict__ out, int R, int mode) {
    extern __shared__ char smem[];
    __half (*As)[136] = (__half(*)[136])smem;
    __half (*Bs)[136] = (__half(*)[136])(smem + 64 * 136 * 2);
    const __half* __restrict__ A = mode ? g_g : g_H;
    const int wimg = mode ? 4 : 3;
    const int tid = threadIdx.x;
    const int m0 = blockIdx.x * 64;

    const int lane = tid & 31, wid = tid >> 5;
    const int wm = wid >> 2, wn = wid & 3;
    const int g = lane >> 2, c = lane & 3;
    float acc[2][4][4] = {};

    for (int kc = 0; kc < 4; kc++) {
#pragma unroll
        for (int it = 0; it < 8; it++) {
            int idx = tid + it * 256;
            int r = idx >> 5, q = idx & 31;
            uint2 v = make_uint2(0u, 0u);
            if (m0 + r < R)
                v = *(const uint2*)(A + (size_t)(m0 + r) * 512 + kc * 128 + q * 4);
            *(uint2*)&As[r][q * 4] = v;
        }
        {
            const uint4* src4 = (const uint4*)g_img[wimg][kc];
            uint4* dst = (uint4*)Bs;
            for (int i = tid; i < PANEL_H / 8; i += 256) dst[i] = src4[i];
        }
        __syncthreads();
        FP16_MAINLOOP(As, Bs, acc, wm, wn, g, c)
        __syncthreads();
    }

#pragma unroll
    for (int mt = 0; mt < 2; mt++) {
#pragma unroll
        for (int nt = 0; nt < 4; nt++) {
            int col = wn * 32 + nt * 8 + c * 2;
            float b0 = bias[col], b1 = bias[col + 1];
#pragma unroll
            for (int half = 0; half < 2; half++) {
                int r = m0 + wm * 32 + mt * 16 + g + half * 8;
                if (r >= R) continue;
                float v0 = acc[mt][nt][half * 2 + 0];
                float v1 = acc[mt][nt][half * 2 + 1];
                if (mode == 0) {
                    *(float2*)(out + (size_t)r * 384 + col) =
                        make_float2(v0 + b0, v1 + b1);
                } else {
                    int br = r / E_N, e = r - br * E_N;
                    float fl = g_flag[r];
                    *(float2*)(out + (size_t)e * 384 + 128 + br * 128 + col) =
                        make_float2(v0 + b0 * fl, v1 + b1 * fl);
                }
            }
        }
    }
}

// ---------------------------------------------------------------------------
// k_branch (unchanged from R8)
// ---------------------------------------------------------------------------
__global__ void __launch_bounds__(256) k_branch(
    const float* __restrict__ sel_dt, const float* __restrict__ sel_w,
    const float* __restrict__ fc1_b,
    const float* __restrict__ ln1_g, const float* __restrict__ ln1_b,
    const int* __restrict__ sel_nodes, const int* __restrict__ sel_edges) {
    const int e = blockIdx.x, br = blockIdx.y;
    const int tid = threadIdx.x;
    __shared__ float ctd[KSEL][PCH * 2];
    __shared__ float wn[KSEL];
    __shared__ int   nd_s[KSEL], ed_s[KSEL];
    __shared__ float red_s[KSEL][8], red_q[KSEL][8];
    __shared__ float mu_s[KSEL], rs_s[KSEL];
    __shared__ float flag_s;

    const size_t base = ((size_t)br * E_N + e) * KSEL;
    if (tid < KSEL) {
        int k = tid;
        float dt = sel_dt[base + k];
        wn[k]   = sel_w[base + k];
        nd_s[k] = sel_nodes[base + k];
        ed_s[k] = sel_edges[base + k];
        float x = 2.f * dt - 1.f;
        float t0 = 1.f, t1 = x;
        ctd[k][0] = t0; ctd[k][1] = t0;
        ctd[k][2] = t1; ctd[k][3] = t1;
#pragma unroll
        for (int p = 2; p < PCH; p++) {
            float t2 = 2.f * x * t1 - t0;
            ctd[k][2 * p] = t2; ctd[k][2 * p + 1] = t2;
            t0 = t1; t1 = t2;
        }
    }
    __syncthreads();
    if (tid == 0) {
        float ws = 0.f;
#pragma unroll
        for (int k = 0; k < KSEL; k++) ws += wn[k];
        float fl = (ws > 0.f) ? 1.f : 0.f;
        flag_s = fl;
        float inv = fl > 0.f ? 1.f / ws : 0.f;
#pragma unroll
        for (int k = 0; k < KSEL; k++) wn[k] *= inv;
    }

    const int c0 = tid * 2;
    unsigned long long Gd[PCH];
#pragma unroll
    for (int p = 0; p < PCH; p++)
        Gd[p] = *(const unsigned long long*)(g_G + p * 512 + c0);

    unsigned long long acc[KSEL];
    const float2 b1v = *(const float2*)(fc1_b + c0);
    const uint32_t ctd_base = smem_u32(ctd);
    __syncthreads();
#pragma unroll
    for (int k = 0; k < KSEL; k++) {
        float2 pn = __half22float2(*(const __half2*)(g_Pn + (size_t)nd_s[k] * 512 + c0));
        float2 pe = __half22float2(*(const __half2*)(g_Pe + (size_t)ed_s[k] * 512 + c0));
        float2 a = make_float2(pn.x + pe.x + b1v.x, pn.y + pe.y + b1v.y);
        acc[k] = *(unsigned long long*)&a;
    }
#pragma unroll
    for (int k = 0; k < KSEL; k++) {
        uint32_t row = ctd_base + k * (PCH * 2 * 4);
#pragma unroll
        for (int p = 0; p < PCH; p += 2) {
            unsigned long long t0, t1;
            asm("ld.shared.v2.b64 {%0, %1}, [%2];"
                : "=l"(t0), "=l"(t1) : "r"(row + p * 8));
            asm("fma.rn.f32x2 %0, %1, %2, %0;" : "+l"(acc[k]) : "l"(t0), "l"(Gd[p]));
            asm("fma.rn.f32x2 %0, %1, %2, %0;" : "+l"(acc[k]) : "l"(t1), "l"(Gd[p + 1]));
        }
    }
    const int lane = tid & 31, warp = tid >> 5;
#pragma unroll
    for (int k = 0; k < KSEL; k++) {
        float2 a = *(float2*)&acc[k];
        float s = a.x + a.y;
        float q = a.x * a.x + a.y * a.y;
#pragma unroll
        for (int o = 16; o > 0; o >>= 1) {
            s += __shfl_down_sync(0xffffffffu, s, o);
            q += __shfl_down_sync(0xffffffffu, q, o);
        }
        if (lane == 0) { red_s[k][warp] = s; red_q[k][warp] = q; }
    }
    __syncthreads();
    if (tid < KSEL) {
        float s = 0.f, q = 0.f;
#pragma unroll
        for (int w = 0; w < 8; w++) { s += red_s[tid][w]; q += red_q[tid][w]; }
        float mu = s * (1.f / 512.f);
        float var = q * (1.f / 512.f) - mu * mu;
        mu_s[tid] = mu;
        rs_s[tid] = rsqrtf(var + EPSV);
    }
    __syncthreads();
    const float lg0 = ln1_g[c0], lg1 = ln1_g[c0 + 1];
    const float lb0 = ln1_b[c0], lb1 = ln1_b[c0 + 1];
    float o0 = 0.f, o1 = 0.f;
#pragma unroll
    for (int k = 0; k < KSEL; k++) {
        float2 a = *(float2*)&acc[k];
        float h0 = fmaxf((a.x - mu_s[k]) * rs_s[k] * lg0 + lb0, 0.f);
        float h1 = fmaxf((a.y - mu_s[k]) * rs_s[k] * lg1 + lb1, 0.f);
        o0 += wn[k] * h0;
        o1 += wn[k] * h1;
    }
    *(__half2*)(g_g + ((size_t)br * E_N + e) * 512 + c0) = __floats2half2_rn(o0, o1);
    if (tid == 0) g_flag[br * E_N + e] = flag_s;
}

// ---------------------------------------------------------------------------
extern "C" void kernel_launch(void* const* d_in, const int* in_sizes, int n_in,
                              void* d_out, int out_size) {
    const float* memory    = (const float*)d_in[0];
    const float* edge_feat = (const float*)d_in[1];
    const float* sel_dt    = (const float*)d_in[2];
    const float* sel_w     = (const float*)d_in[3];
    const float* time_w    = (const float*)d_in[4];
    const float* time_b    = (const float*)d_in[5];
    const float* fc1_w     = (const float*)d_in[6];
    const float* fc1_b     = (const float*)d_in[7];
    const float* ln1_g     = (const float*)d_in[8];
    const float* ln1_b     = (const float*)d_in[9];
    const float* fc2_w     = (const float*)d_in[10];
    const float* fc2_b     = (const float*)d_in[11];
    const float* fc1s_w    = (const float*)d_in[12];
    const float* fc1s_b    = (const float*)d_in[13];
    const float* bn_g      = (const float*)d_in[14];
    const float* bn_b      = (const float*)d_in[15];
    const float* bn_m      = (const float*)d_in[16];
    const float* bn_v      = (const float*)d_in[17];
    const float* fc2s_w    = (const float*)d_in[18];
    const float* fc2s_b    = (const float*)d_in[19];
    const int* source_nodes = (const int*)d_in[20];
    const int* sel_nodes    = (const int*)d_in[21];
    const int* sel_edges    = (const int*)d_in[22];
    float* out = (float*)d_out;

    cudaFuncSetAttribute(k_pre_h,   cudaFuncAttributeMaxDynamicSharedMemorySize, SMEM_128);
    cudaFuncSetAttribute(k_src1_h,  cudaFuncAttributeMaxDynamicSharedMemorySize, SMEM_64);
    cudaFuncSetAttribute(k_gemm2_h, cudaFuncAttributeMaxDynamicSharedMemorySize, SMEM_64);

    k_prep<<<1280, 256>>>(fc1_w, fc1s_w, fc2s_w, fc2_w);
    k_cheb<<<1, 512>>>(time_w, time_b, fc1_w);
    // fp16 tensor-core precompute: 128 rows x full 512 cols per CTA
    k_pre_h<<<(NNODES + 127) / 128, 256, SMEM_128>>>(memory, NNODES, 0);
    k_pre_h<<<(NEDGES + 127) / 128, 256, SMEM_128>>>(edge_feat, NEDGES, 1);
    // Source branch
    k_src1_h<<<dim3((E_N + 63) / 64, 4), 256, SMEM_64>>>(
        memory, fc1s_b, bn_g, bn_b, bn_m, bn_v, source_nodes);
    k_gemm2_h<<<(E_N + 63) / 64, 256, SMEM_64>>>(fc2s_b, out, E_N, 0);
    // TPPR branches
    k_branch<<<dim3(E_N, NT_), 256>>>(sel_dt, sel_w, fc1_b, ln1_g, ln1_b,
                                      sel_nodes, sel_edges);
    k_gemm2_h<<<(NT_ * E_N + 63) / 64, 256, SMEM_64>>>(fc2_b, out, NT_ * E_N, 1);
}

// round 10
// speedup vs baseline: 4.5302x; 1.2781x over previous
#include <cuda_runtime.h>
#include <cuda_fp16.h>
#include <math.h>
#include <cstdint>

#define E_N     20000
#define KSEL    20
#define D_      128
#define F1_     512
#define F2_     128
#define NT_     2
#define NNODES  200000
#define NEDGES  500000
#define EPSV    1e-5f
#define PCH     16

// Scratch (allocation-free rule: __device__ globals)
static __device__ __half g_Pn[(size_t)NNODES * F1_];
static __device__ __half g_Pe[(size_t)NEDGES * F1_];
static __device__ __half g_g [(size_t)NT_ * E_N * F1_];
static __device__ __half g_H [(size_t)E_N * F1_];
static __device__ float  g_flag[NT_ * E_N];
static __device__ float  g_G[PCH * F1_];
#define PANEL_H 17408
static __device__ __align__(16) __half g_img[5][4][PANEL_H];

__device__ __forceinline__ void mma_f16(float* c, const uint32_t* a, const uint32_t* b) {
    asm volatile("mma.sync.aligned.m16n8k16.row.col.f32.f16.f16.f32 "
                 "{%0,%1,%2,%3}, {%4,%5,%6,%7}, {%8,%9}, {%0,%1,%2,%3};"
                 : "+f"(c[0]), "+f"(c[1]), "+f"(c[2]), "+f"(c[3])
                 : "r"(a[0]), "r"(a[1]), "r"(a[2]), "r"(a[3]),
                   "r"(b[0]), "r"(b[1]));
}
__device__ __forceinline__ void ldsm_x4(uint32_t& r0, uint32_t& r1, uint32_t& r2,
                                        uint32_t& r3, uint32_t addr) {
    asm volatile("ldmatrix.sync.aligned.m8n8.x4.shared.b16 {%0,%1,%2,%3}, [%4];"
                 : "=r"(r0), "=r"(r1), "=r"(r2), "=r"(r3) : "r"(addr));
}
__device__ __forceinline__ uint32_t smem_u32(const void* p) {
    uint32_t a;
    asm("{ .reg .u64 t; cvta.to.shared.u64 t, %1; cvt.u32.u64 %0, t; }" : "=r"(a) : "l"(p));
    return a;
}
__device__ __forceinline__ unsigned long long pk2(float x, float y) {
    unsigned long long r;
    asm("mov.b64 %0, {%1, %2};" : "=l"(r) : "f"(x), "f"(y));
    return r;
}

// ---------------------------------------------------------------------------
// Weight prep (unchanged)
// ---------------------------------------------------------------------------
__global__ void k_prep(const float* __restrict__ fc1_w,
                       const float* __restrict__ fc1s_w,
                       const float* __restrict__ fc2s_w,
                       const float* __restrict__ fc2_w) {
    int idx = blockIdx.x * 256 + threadIdx.x;
    int k = idx & 127;
    int n = (idx >> 7) & 127;
    int p = (idx >> 14) & 3;
    int m = idx >> 16;
    float v;
    if      (m == 0) v = fc1_w [(size_t)k          * 512 + p * 128 + n];
    else if (m == 1) v = fc1_w [(size_t)(128 + k)  * 512 + p * 128 + n];
    else if (m == 2) v = fc1s_w[(size_t)k          * 512 + p * 128 + n];
    else if (m == 3) v = fc2s_w[(size_t)(p * 128 + k) * 128 + n];
    else             v = fc2_w [(size_t)(p * 128 + k) * 128 + n];
    g_img[m][p][n * 136 + k] = __float2half(v);
}

// ---------------------------------------------------------------------------
// Chebyshev prolog (unchanged)
// ---------------------------------------------------------------------------
__global__ void __launch_bounds__(512) k_cheb(const float* __restrict__ time_w,
                                              const float* __restrict__ time_b,
                                              const float* __restrict__ fc1_w) {
    __shared__ float teq[PCH][100];
    const int tid = threadIdx.x;
    for (int i = tid; i < PCH * 100; i += 512) {
        int q = i / 100, j = i - q * 100;
        float xq  = cospif((q + 0.5f) / (float)PCH);
        float dtq = 0.5f * (xq + 1.0f);
        teq[q][j] = cosf(dtq * time_w[j] + time_b[j]);
    }
    __syncthreads();
    const float* __restrict__ W1t = fc1_w + (size_t)256 * 512;
    float M[PCH];
#pragma unroll
    for (int q = 0; q < PCH; q++) M[q] = 0.f;
    for (int j = 0; j < 100; j++) {
        float w = W1t[(size_t)j * 512 + tid];
#pragma unroll
        for (int q = 0; q < PCH; q++) M[q] += teq[q][j] * w;
    }
#pragma unroll
    for (int p = 0; p < PCH; p++) {
        float s = 0.f;
#pragma unroll
        for (int q = 0; q < PCH; q++)
            s += cospif(p * (q + 0.5f) / (float)PCH) * M[q];
        g_G[p * 512 + tid] = s * ((p == 0 ? 1.0f : 2.0f) / (float)PCH);
    }
}

// ===========================================================================
// fp16 mma machinery (ldmatrix fragment loads)
// ===========================================================================
#define SMEM_64   (64 * 136 * 2 + 128 * 136 * 2)
#define SMEM_128  (128 * 136 * 2 + 128 * 136 * 2)

// 8 warps as 2(M) x 4(N); warp tile 32x32; ldmatrix fragments.
#define FP16_MAINLOOP_LDSM(AsU, BsU, acc, wm, wn)                              \
    {                                                                          \
        const int lane_ = threadIdx.x & 31;                                    \
        uint32_t a_ad[2], b_ad[2];                                             \
        _Pragma("unroll")                                                      \
        for (int mt = 0; mt < 2; mt++)                                         \
            a_ad[mt] = (AsU) + ((wm) * 32 + mt * 16 + (lane_ & 15)) * 272      \
                       + ((lane_ >> 4) & 1) * 16;                              \
        _Pragma("unroll")                                                      \
        for (int j = 0; j < 2; j++)                                            \
            b_ad[j] = (BsU) + ((wn) * 32 + j * 16 + ((lane_ >> 4) << 3)        \
                       + (lane_ & 7)) * 272 + ((lane_ >> 3) & 1) * 16;         \
        _Pragma("unroll")                                                      \
        for (int ks = 0; ks < 8; ks++) {                                       \
            const int kb = ks * 32;                                            \
            uint32_t af[2][4], bf[4][2];                                       \
            _Pragma("unroll")                                                  \
            for (int mt = 0; mt < 2; mt++)                                     \
                ldsm_x4(af[mt][0], af[mt][1], af[mt][2], af[mt][3],            \
                        a_ad[mt] + kb);                                        \
            _Pragma("unroll")                                                  \
            for (int j = 0; j < 2; j++)                                        \
                ldsm_x4(bf[2 * j][0], bf[2 * j][1], bf[2 * j + 1][0],          \
                        bf[2 * j + 1][1], b_ad[j] + kb);                       \
            _Pragma("unroll")                                                  \
            for (int mt = 0; mt < 2; mt++)                                     \
                _Pragma("unroll")                                              \
                for (int nt = 0; nt < 4; nt++)                                 \
                    mma_f16(acc[mt][nt], af[mt], bf[nt]);                      \
        }                                                                      \
    }

// ---------------------------------------------------------------------------
// k_pre: one CTA = 128 rows x 512 cols; 8 warps as 4(M) x 2(N), tile 32x64.
// ---------------------------------------------------------------------------
__global__ void __launch_bounds__(256, 2) k_pre_h(const float* __restrict__ A,
                                                  int N, int which) {
    extern __shared__ char smem[];
    __half (*As)[136] = (__half(*)[136])smem;
    __half (*Bs)[136] = (__half(*)[136])(smem + 128 * 136 * 2);
    __half* __restrict__ C = which ? g_Pe : g_Pn;
    const int tid = threadIdx.x;
    const int m0 = blockIdx.x * 128;

#pragma unroll
    for (int it = 0; it < 16; it++) {
        int idx = tid + it * 256;
        int r = idx >> 5, q = idx & 31;
        float4 v = make_float4(0.f, 0.f, 0.f, 0.f);
        if (m0 + r < N) v = *(const float4*)(A + (size_t)(m0 + r) * 128 + q * 4);
        __half2 h01 = __floats2half2_rn(v.x, v.y);
        __half2 h23 = __floats2half2_rn(v.z, v.w);
        *(uint2*)&As[r][q * 4] = make_uint2(*(uint32_t*)&h01, *(uint32_t*)&h23);
    }

    const int lane = tid & 31, wid = tid >> 5;
    const int wm = wid >> 1, wn = wid & 1;       // 4(M) x 2(N)
    const int g = lane >> 2, c = lane & 3;
    const uint32_t AsU = smem_u32(As), BsU = smem_u32(Bs);

    uint32_t a_ad[2], b_ad[4];
#pragma unroll
    for (int mt = 0; mt < 2; mt++)
        a_ad[mt] = AsU + (wm * 32 + mt * 16 + (lane & 15)) * 272
                   + ((lane >> 4) & 1) * 16;
#pragma unroll
    for (int j = 0; j < 4; j++)
        b_ad[j] = BsU + (wn * 64 + j * 16 + ((lane >> 4) << 3) + (lane & 7)) * 272
                  + ((lane >> 3) & 1) * 16;

    for (int p = 0; p < 4; p++) {
        {
            const uint4* src = (const uint4*)g_img[which][p];
            uint4* dst = (uint4*)Bs;
            for (int i = tid; i < PANEL_H / 8; i += 256) dst[i] = src[i];
        }
        __syncthreads();

        float acc[2][8][4] = {};
#pragma unroll
        for (int ks = 0; ks < 8; ks++) {
            const int kb = ks * 32;
            uint32_t af[2][4], bf[8][2];
#pragma unroll
            for (int mt = 0; mt < 2; mt++)
                ldsm_x4(af[mt][0], af[mt][1], af[mt][2], af[mt][3], a_ad[mt] + kb);
#pragma unroll
            for (int j = 0; j < 4; j++)
                ldsm_x4(bf[2 * j][0], bf[2 * j][1], bf[2 * j + 1][0],
                        bf[2 * j + 1][1], b_ad[j] + kb);
#pragma unroll
            for (int mt = 0; mt < 2; mt++)
#pragma unroll
                for (int nt = 0; nt < 8; nt++)
                    mma_f16(acc[mt][nt], af[mt], bf[nt]);
        }

        const int n0 = p * 128;
#pragma unroll
        for (int mt = 0; mt < 2; mt++) {
#pragma unroll
            for (int nt = 0; nt < 8; nt++) {
                int r = m0 + wm * 32 + mt * 16 + g;
                int col = n0 + wn * 64 + nt * 8 + c * 2;
                if (r < N)
                    *(__half2*)(C + (size_t)r * 512 + col) =
                        __floats2half2_rn(acc[mt][nt][0], acc[mt][nt][1]);
                if (r + 8 < N)
                    *(__half2*)(C + (size_t)(r + 8) * 512 + col) =
                        __floats2half2_rn(acc[mt][nt][2], acc[mt][nt][3]);
            }
        }
        __syncthreads();
    }
}

// ---------------------------------------------------------------------------
// Src GEMM1: g_H = relu(BN(memory[src] @ fc1s_w + b)).
// ---------------------------------------------------------------------------
__global__ void __launch_bounds__(256, 3) k_src1_h(
    const float* __restrict__ memory, const float* __restrict__ fc1s_b,
    const float* __restrict__ bn_g, const float* __restrict__ bn_b,
    const float* __restrict__ bn_m, const float* __restrict__ bn_v,
    const int* __restrict__ src) {
    extern __shared__ char smem[];
    __half (*As)[136] = (__half(*)[136])smem;
    __half (*Bs)[136] = (__half(*)[136])(smem + 64 * 136 * 2);
    __shared__ int nd[64];
    const int tid = threadIdx.x;
    const int m0 = blockIdx.x * 64;

    if (tid < 64) nd[tid] = (m0 + tid < E_N) ? src[m0 + tid] : 0;
    __syncthreads();
#pragma unroll
    for (int it = 0; it < 8; it++) {
        int idx = tid + it * 256;
        int r = idx >> 5, q = idx & 31;
        float4 v = make_float4(0.f, 0.f, 0.f, 0.f);
        if (m0 + r < E_N) v = *(const float4*)(memory + (size_t)nd[r] * 128 + q * 4);
        __half2 h01 = __floats2half2_rn(v.x, v.y);
        __half2 h23 = __floats2half2_rn(v.z, v.w);
        *(uint2*)&As[r][q * 4] = make_uint2(*(uint32_t*)&h01, *(uint32_t*)&h23);
    }
    {
        const uint4* src4 = (const uint4*)g_img[2][blockIdx.y];
        uint4* dst = (uint4*)Bs;
        for (int i = tid; i < PANEL_H / 8; i += 256) dst[i] = src4[i];
    }
    __syncthreads();

    const int lane = tid & 31, wid = tid >> 5;
    const int wm = wid >> 2, wn = wid & 3;
    const int g = lane >> 2, c = lane & 3;
    const uint32_t AsU = smem_u32(As), BsU = smem_u32(Bs);
    float acc[2][4][4] = {};
    FP16_MAINLOOP_LDSM(AsU, BsU, acc, wm, wn)

    const int n0 = blockIdx.y * 128;
#pragma unroll
    for (int nt = 0; nt < 4; nt++) {
        int col = n0 + wn * 32 + nt * 8 + c * 2;
        float s0 = bn_g[col]     * rsqrtf(bn_v[col]     + EPSV);
        float s1 = bn_g[col + 1] * rsqrtf(bn_v[col + 1] + EPSV);
        float o0 = fc1s_b[col]     - bn_m[col];
        float o1 = fc1s_b[col + 1] - bn_m[col + 1];
        float bb0 = bn_b[col], bb1 = bn_b[col + 1];
#pragma unroll
        for (int mt = 0; mt < 2; mt++) {
            int r = m0 + wm * 32 + mt * 16 + g;
            if (r < E_N)
                *(__half2*)(g_H + (size_t)r * 512 + col) = __floats2half2_rn(
                    fmaxf((acc[mt][nt][0] + o0) * s0 + bb0, 0.f),
                    fmaxf((acc[mt][nt][1] + o1) * s1 + bb1, 0.f));
            if (r + 8 < E_N)
                *(__half2*)(g_H + (size_t)(r + 8) * 512 + col) = __floats2half2_rn(
                    fmaxf((acc[mt][nt][2] + o0) * s0 + bb0, 0.f),
                    fmaxf((acc[mt][nt][3] + o1) * s1 + bb1, 0.f));
        }
    }
}

// ---------------------------------------------------------------------------
// Second GEMM: C[R,128] = A[R,512](fp16) @ W[512,128] + bias.
// ---------------------------------------------------------------------------
__global__ void __launch_bounds__(256, 3) k_gemm2_h(
    const float* __restrict__ bias, float* __restrict__ out, int R, int mode) {
    extern __shared__ char smem[];
    __half (*As)[136] = (__half(*)[136])smem;
    __half (*Bs)[136] = (__half(*)[136])(smem + 64 * 136 * 2);
    const __half* __restrict__ A = mode ? g_g : g_H;
    const int wimg = mode ? 4 : 3;
    const int tid = threadIdx.x;
    const int m0 = blockIdx.x * 64;

    const int lane = tid & 31, wid = tid >> 5;
    const int wm = wid >> 2, wn = wid & 3;
    const int g = lane >> 2, c = lane & 3;
    const uint32_t AsU = smem_u32(As), BsU = smem_u32(Bs);
    float acc[2][4][4] = {};

    for (int kc = 0; kc < 4; kc++) {
#pragma unroll
        for (int it = 0; it < 8; it++) {
            int idx = tid + it * 256;
            int r = idx >> 5, q = idx & 31;
            uint2 v = make_uint2(0u, 0u);
            if (m0 + r < R)
                v = *(const uint2*)(A + (size_t)(m0 + r) * 512 + kc * 128 + q * 4);
            *(uint2*)&As[r][q * 4] = v;
        }
        {
            const uint4* src4 = (const uint4*)g_img[wimg][kc];
            uint4* dst = (uint4*)Bs;
            for (int i = tid; i < PANEL_H / 8; i += 256) dst[i] = src4[i];
        }
        __syncthreads();
        FP16_MAINLOOP_LDSM(AsU, BsU, acc, wm, wn)
        __syncthreads();
    }

#pragma unroll
    for (int mt = 0; mt < 2; mt++) {
#pragma unroll
        for (int nt = 0; nt < 4; nt++) {
            int col = wn * 32 + nt * 8 + c * 2;
            float b0 = bias[col], b1 = bias[col + 1];
#pragma unroll
            for (int half = 0; half < 2; half++) {
                int r = m0 + wm * 32 + mt * 16 + g + half * 8;
                if (r >= R) continue;
                float v0 = acc[mt][nt][half * 2 + 0];
                float v1 = acc[mt][nt][half * 2 + 1];
                if (mode == 0) {
                    *(float2*)(out + (size_t)r * 384 + col) =
                        make_float2(v0 + b0, v1 + b1);
                } else {
                    int br = r / E_N, e = r - br * E_N;
                    float fl = g_flag[r];
                    *(float2*)(out + (size_t)e * 384 + 128 + br * 128 + col) =
                        make_float2(v0 + b0 * fl, v1 + b1 * fl);
                }
            }
        }
    }
}

// ---------------------------------------------------------------------------
// k_branch: 128 threads, 4 cols/thread; LDG.64 gathers; packed f32x2.
// ---------------------------------------------------------------------------
__global__ void __launch_bounds__(128) k_branch(
    const float* __restrict__ sel_dt, const float* __restrict__ sel_w,
    const float* __restrict__ fc1_b,
    const float* __restrict__ ln1_g, const float* __restrict__ ln1_b,
    const int* __restrict__ sel_nodes, const int* __restrict__ sel_edges) {
    const int e = blockIdx.x, br = blockIdx.y;
    const int tid = threadIdx.x;
    __shared__ float ctd[KSEL][PCH * 2];   // duplicated pairs (T_p, T_p)
    __shared__ float wn[KSEL];
    __shared__ int   nd_s[KSEL], ed_s[KSEL];
    __shared__ float red_s[KSEL][4], red_q[KSEL][4];
    __shared__ float mu_s[KSEL], rs_s[KSEL];
    __shared__ float flag_s;

    const size_t base = ((size_t)br * E_N + e) * KSEL;
    if (tid < KSEL) {
        int k = tid;
        float dt = sel_dt[base + k];
        wn[k]   = sel_w[base + k];
        nd_s[k] = sel_nodes[base + k];
        ed_s[k] = sel_edges[base + k];
        float x = 2.f * dt - 1.f;
        float t0 = 1.f, t1 = x;
        ctd[k][0] = t0; ctd[k][1] = t0;
        ctd[k][2] = t1; ctd[k][3] = t1;
#pragma unroll
        for (int p = 2; p < PCH; p++) {
            float t2 = 2.f * x * t1 - t0;
            ctd[k][2 * p] = t2; ctd[k][2 * p + 1] = t2;
            t0 = t1; t1 = t2;
        }
    }
    __syncthreads();
    if (tid == 0) {
        float ws = 0.f;
#pragma unroll
        for (int k = 0; k < KSEL; k++) ws += wn[k];
        float fl = (ws > 0.f) ? 1.f : 0.f;
        flag_s = fl;
        float inv = fl > 0.f ? 1.f / ws : 0.f;
#pragma unroll
        for (int k = 0; k < KSEL; k++) wn[k] *= inv;
    }

    const int c0 = tid * 4;
    unsigned long long acc[KSEL][2];
    const float4 bv = *(const float4*)(fc1_b + c0);
#pragma unroll
    for (int k = 0; k < KSEL; k++) {
        uint2 vn = *(const uint2*)(g_Pn + (size_t)nd_s[k] * 512 + c0);
        uint2 ve = *(const uint2*)(g_Pe + (size_t)ed_s[k] * 512 + c0);
        float2 n0 = __half22float2(*(__half2*)&vn.x);
        float2 n1 = __half22float2(*(__half2*)&vn.y);
        float2 e0 = __half22float2(*(__half2*)&ve.x);
        float2 e1 = __half22float2(*(__half2*)&ve.y);
        acc[k][0] = pk2(n0.x + e0.x + bv.x, n0.y + e0.y + bv.y);
        acc[k][1] = pk2(n1.x + e1.x + bv.z, n1.y + e1.y + bv.w);
    }
    const uint32_t ctd_base = smem_u32(ctd);
#pragma unroll
    for (int half = 0; half < 2; half++) {
        unsigned long long Gd[8][2];
#pragma unroll
        for (int p = 0; p < 8; p++) {
            float4 gv = *(const float4*)(g_G + (half * 8 + p) * 512 + c0);
            Gd[p][0] = pk2(gv.x, gv.y);
            Gd[p][1] = pk2(gv.z, gv.w);
        }
#pragma unroll
        for (int k = 0; k < KSEL; k++) {
            uint32_t row = ctd_base + k * 128 + half * 64;
#pragma unroll
            for (int p = 0; p < 8; p += 2) {
                unsigned long long t0, t1;
                asm("ld.shared.v2.b64 {%0, %1}, [%2];"
                    : "=l"(t0), "=l"(t1) : "r"(row + p * 8));
                asm("fma.rn.f32x2 %0, %1, %2, %0;" : "+l"(acc[k][0]) : "l"(t0), "l"(Gd[p][0]));
                asm("fma.rn.f32x2 %0, %1, %2, %0;" : "+l"(acc[k][1]) : "l"(t0), "l"(Gd[p][1]));
                asm("fma.rn.f32x2 %0, %1, %2, %0;" : "+l"(acc[k][0]) : "l"(t1), "l"(Gd[p + 1][0]));
                asm("fma.rn.f32x2 %0, %1, %2, %0;" : "+l"(acc[k][1]) : "l"(t1), "l"(Gd[p + 1][1]));
            }
        }
    }
    const int lane = tid & 31, warp = tid >> 5;
#pragma unroll
    for (int k = 0; k < KSEL; k++) {
        float2 a0 = *(float2*)&acc[k][0];
        float2 a1 = *(float2*)&acc[k][1];
        float s = a0.x + a0.y + a1.x + a1.y;
        float q = a0.x * a0.x + a0.y * a0.y + a1.x * a1.x + a1.y * a1.y;
#pragma unroll
        for (int o = 16; o > 0; o >>= 1) {
            s += __shfl_down_sync(0xffffffffu, s, o);
            q += __shfl_down_sync(0xffffffffu, q, o);
        }
        if (lane == 0) { red_s[k][warp] = s; red_q[k][warp] = q; }
    }
    __syncthreads();
    if (tid < KSEL) {
        float s = 0.f, q = 0.f;
#pragma unroll
        for (int w = 0; w < 4; w++) { s += red_s[tid][w]; q += red_q[tid][w]; }
        float mu = s * (1.f / 512.f);
        float var = q * (1.f / 512.f) - mu * mu;
        mu_s[tid] = mu;
        rs_s[tid] = rsqrtf(var + EPSV);
    }
    __syncthreads();
    const float4 lg = *(const float4*)(ln1_g + c0);
    const float4 lb = *(const float4*)(ln1_b + c0);
    float o0 = 0.f, o1 = 0.f, o2 = 0.f, o3 = 0.f;
#pragma unroll
    for (int k = 0; k < KSEL; k++) {
        float2 a0 = *(float2*)&acc[k][0];
        float2 a1 = *(float2*)&acc[k][1];
        float mu = mu_s[k], rs = rs_s[k], w = wn[k];
        o0 += w * fmaxf((a0.x - mu) * rs * lg.x + lb.x, 0.f);
        o1 += w * fmaxf((a0.y - mu) * rs * lg.y + lb.y, 0.f);
        o2 += w * fmaxf((a1.x - mu) * rs * lg.z + lb.z, 0.f);
        o3 += w * fmaxf((a1.y - mu) * rs * lg.w + lb.w, 0.f);
    }
    __half2 h01 = __floats2half2_rn(o0, o1);
    __half2 h23 = __floats2half2_rn(o2, o3);
    *(uint2*)(g_g + ((size_t)br * E_N + e) * 512 + c0) =
        make_uint2(*(uint32_t*)&h01, *(uint32_t*)&h23);
    if (tid == 0) g_flag[br * E_N + e] = flag_s;
}

// ---------------------------------------------------------------------------
extern "C" void kernel_launch(void* const* d_in, const int* in_sizes, int n_in,
                              void* d_out, int out_size) {
    const float* memory    = (const float*)d_in[0];
    const float* edge_feat = (const float*)d_in[1];
    const float* sel_dt    = (const float*)d_in[2];
    const float* sel_w     = (const float*)d_in[3];
    const float* time_w    = (const float*)d_in[4];
    const float* time_b    = (const float*)d_in[5];
    const float* fc1_w     = (const float*)d_in[6];
    const float* fc1_b     = (const float*)d_in[7];
    const float* ln1_g     = (const float*)d_in[8];
    const float* ln1_b     = (const float*)d_in[9];
    const float* fc2_w     = (const float*)d_in[10];
    const float* fc2_b     = (const float*)d_in[11];
    const float* fc1s_w    = (const float*)d_in[12];
    const float* fc1s_b    = (const float*)d_in[13];
    const float* bn_g      = (const float*)d_in[14];
    const float* bn_b      = (const float*)d_in[15];
    const float* bn_m      = (const float*)d_in[16];
    const float* bn_v      = (const float*)d_in[17];
    const float* fc2s_w    = (const float*)d_in[18];
    const float* fc2s_b    = (const float*)d_in[19];
    const int* source_nodes = (const int*)d_in[20];
    const int* sel_nodes    = (const int*)d_in[21];
    const int* sel_edges    = (const int*)d_in[22];
    float* out = (float*)d_out;

    cudaFuncSetAttribute(k_pre_h,   cudaFuncAttributeMaxDynamicSharedMemorySize, SMEM_128);
    cudaFuncSetAttribute(k_src1_h,  cudaFuncAttributeMaxDynamicSharedMemorySize, SMEM_64);
    cudaFuncSetAttribute(k_gemm2_h, cudaFuncAttributeMaxDynamicSharedMemorySize, SMEM_64);

    k_prep<<<1280, 256>>>(fc1_w, fc1s_w, fc2s_w, fc2_w);
    k_cheb<<<1, 512>>>(time_w, time_b, fc1_w);
    k_pre_h<<<(NNODES + 127) / 128, 256, SMEM_128>>>(memory, NNODES, 0);
    k_pre_h<<<(NEDGES + 127) / 128, 256, SMEM_128>>>(edge_feat, NEDGES, 1);
    k_src1_h<<<dim3((E_N + 63) / 64, 4), 256, SMEM_64>>>(
        memory, fc1s_b, bn_g, bn_b, bn_m, bn_v, source_nodes);
    k_gemm2_h<<<(E_N + 63) / 64, 256, SMEM_64>>>(fc2s_b, out, E_N, 0);
    k_branch<<<dim3(E_N, NT_), 128>>>(sel_dt, sel_w, fc1_b, ln1_g, ln1_b,
                                      sel_nodes, sel_edges);
    k_gemm2_h<<<(NT_ * E_N + 63) / 64, 256, SMEM_64>>>(fc2_b, out, NT_ * E_N, 1);
}

// round 11
// speedup vs baseline: 4.8115x; 1.0621x over previous
#include <cuda_runtime.h>
#include <cuda_fp16.h>
#include <math.h>
#include <cstdint>

#define E_N     20000
#define KSEL    20
#define D_      128
#define F1_     512
#define F2_     128
#define NT_     2
#define NNODES  200000
#define NEDGES  500000
#define EPSV    1e-5f
#define PCH     16

// Scratch (allocation-free rule: __device__ globals)
static __device__ __half g_Pn[(size_t)NNODES * F1_];
static __device__ __half g_Pe[(size_t)NEDGES * F1_];
static __device__ __half g_g [(size_t)NT_ * E_N * F1_];
static __device__ __half g_H [(size_t)E_N * F1_];
static __device__ float  g_flag[NT_ * E_N];
static __device__ float  g_G[PCH * F1_];
#define PANEL_H 17408
static __device__ __align__(16) __half g_img[5][4][PANEL_H];

__device__ __forceinline__ void mma_f16(float* c, const uint32_t* a, const uint32_t* b) {
    asm volatile("mma.sync.aligned.m16n8k16.row.col.f32.f16.f16.f32 "
                 "{%0,%1,%2,%3}, {%4,%5,%6,%7}, {%8,%9}, {%0,%1,%2,%3};"
                 : "+f"(c[0]), "+f"(c[1]), "+f"(c[2]), "+f"(c[3])
                 : "r"(a[0]), "r"(a[1]), "r"(a[2]), "r"(a[3]),
                   "r"(b[0]), "r"(b[1]));
}
__device__ __forceinline__ void ldsm_x4(uint32_t& r0, uint32_t& r1, uint32_t& r2,
                                        uint32_t& r3, uint32_t addr) {
    asm volatile("ldmatrix.sync.aligned.m8n8.x4.shared.b16 {%0,%1,%2,%3}, [%4];"
                 : "=r"(r0), "=r"(r1), "=r"(r2), "=r"(r3) : "r"(addr));
}
__device__ __forceinline__ uint32_t smem_u32(const void* p) {
    uint32_t a;
    asm("{ .reg .u64 t; cvta.to.shared.u64 t, %1; cvt.u32.u64 %0, t; }" : "=r"(a) : "l"(p));
    return a;
}
__device__ __forceinline__ unsigned long long pk2(float x, float y) {
    unsigned long long r;
    asm("mov.b64 %0, {%1, %2};" : "=l"(r) : "f"(x), "f"(y));
    return r;
}
__device__ __forceinline__ void cp_async16(uint32_t dst, const void* src) {
    asm volatile("cp.async.ca.shared.global [%0], [%1], 16;"
                 :: "r"(dst), "l"(__cvta_generic_to_global(src)) : "memory");
}
__device__ __forceinline__ void cp_async_wait_all() {
    asm volatile("cp.async.commit_group;" ::: "memory");
    asm volatile("cp.async.wait_group 0;" ::: "memory");
}

// ---------------------------------------------------------------------------
// Weight prep (unchanged)
// ---------------------------------------------------------------------------
__global__ void k_prep(const float* __restrict__ fc1_w,
                       const float* __restrict__ fc1s_w,
                       const float* __restrict__ fc2s_w,
                       const float* __restrict__ fc2_w) {
    int idx = blockIdx.x * 256 + threadIdx.x;
    int k = idx & 127;
    int n = (idx >> 7) & 127;
    int p = (idx >> 14) & 3;
    int m = idx >> 16;
    float v;
    if      (m == 0) v = fc1_w [(size_t)k          * 512 + p * 128 + n];
    else if (m == 1) v = fc1_w [(size_t)(128 + k)  * 512 + p * 128 + n];
    else if (m == 2) v = fc1s_w[(size_t)k          * 512 + p * 128 + n];
    else if (m == 3) v = fc2s_w[(size_t)(p * 128 + k) * 128 + n];
    else             v = fc2_w [(size_t)(p * 128 + k) * 128 + n];
    g_img[m][p][n * 136 + k] = __float2half(v);
}

// ---------------------------------------------------------------------------
// Chebyshev prolog (unchanged)
// ---------------------------------------------------------------------------
__global__ void __launch_bounds__(512) k_cheb(const float* __restrict__ time_w,
                                              const float* __restrict__ time_b,
                                              const float* __restrict__ fc1_w) {
    __shared__ float teq[PCH][100];
    const int tid = threadIdx.x;
    for (int i = tid; i < PCH * 100; i += 512) {
        int q = i / 100, j = i - q * 100;
        float xq  = cospif((q + 0.5f) / (float)PCH);
        float dtq = 0.5f * (xq + 1.0f);
        teq[q][j] = cosf(dtq * time_w[j] + time_b[j]);
    }
    __syncthreads();
    const float* __restrict__ W1t = fc1_w + (size_t)256 * 512;
    float M[PCH];
#pragma unroll
    for (int q = 0; q < PCH; q++) M[q] = 0.f;
    for (int j = 0; j < 100; j++) {
        float w = W1t[(size_t)j * 512 + tid];
#pragma unroll
        for (int q = 0; q < PCH; q++) M[q] += teq[q][j] * w;
    }
#pragma unroll
    for (int p = 0; p < PCH; p++) {
        float s = 0.f;
#pragma unroll
        for (int q = 0; q < PCH; q++)
            s += cospif(p * (q + 0.5f) / (float)PCH) * M[q];
        g_G[p * 512 + tid] = s * ((p == 0 ? 1.0f : 2.0f) / (float)PCH);
    }
}

// ===========================================================================
// fp16 mma machinery (ldmatrix fragment loads)
// ===========================================================================
#define SMEM_64   (64 * 136 * 2 + 128 * 136 * 2)
#define SMEM_128  (3 * 128 * 136 * 2)            // As + Bs + Stage

// 8 warps as 2(M) x 4(N); warp tile 32x32; ldmatrix fragments.
#define FP16_MAINLOOP_LDSM(AsU, BsU, acc, wm, wn)                              \
    {                                                                          \
        const int lane_ = threadIdx.x & 31;                                    \
        uint32_t a_ad[2], b_ad[2];                                             \
        _Pragma("unroll")                                                      \
        for (int mt = 0; mt < 2; mt++)                                         \
            a_ad[mt] = (AsU) + ((wm) * 32 + mt * 16 + (lane_ & 15)) * 272      \
                       + ((lane_ >> 4) & 1) * 16;                              \
        _Pragma("unroll")                                                      \
        for (int j = 0; j < 2; j++)                                            \
            b_ad[j] = (BsU) + ((wn) * 32 + j * 16 + ((lane_ >> 4) << 3)        \
                       + (lane_ & 7)) * 272 + ((lane_ >> 3) & 1) * 16;         \
        _Pragma("unroll")                                                      \
        for (int ks = 0; ks < 8; ks++) {                                       \
            const int kb = ks * 32;                                            \
            uint32_t af[2][4], bf[4][2];                                       \
            _Pragma("unroll")                                                  \
            for (int mt = 0; mt < 2; mt++)                                     \
                ldsm_x4(af[mt][0], af[mt][1], af[mt][2], af[mt][3],            \
                        a_ad[mt] + kb);                                        \
            _Pragma("unroll")                                                  \
            for (int j = 0; j < 2; j++)                                        \
                ldsm_x4(bf[2 * j][0], bf[2 * j][1], bf[2 * j + 1][0],          \
                        bf[2 * j + 1][1], b_ad[j] + kb);                       \
            _Pragma("unroll")                                                  \
            for (int mt = 0; mt < 2; mt++)                                     \
                _Pragma("unroll")                                              \
                for (int nt = 0; nt < 4; nt++)                                 \
                    mma_f16(acc[mt][nt], af[mt], bf[nt]);                      \
        }                                                                      \
    }

// ---------------------------------------------------------------------------
// k_pre: one CTA = 128 rows x 512 cols; 8 warps as 4(M) x 2(N), tile 32x64.
// cp.async B-panel copy + smem-staged coalesced fp16 epilogue.
// ---------------------------------------------------------------------------
__global__ void __launch_bounds__(256, 2) k_pre_h(const float* __restrict__ A,
                                                  int N, int which) {
    extern __shared__ char smem[];
    __half (*As)[136] = (__half(*)[136])smem;
    __half (*Bs)[136] = (__half(*)[136])(smem + 128 * 136 * 2);
    __half (*St)[136] = (__half(*)[136])(smem + 2 * 128 * 136 * 2);
    __half* __restrict__ C = which ? g_Pe : g_Pn;
    const int tid = threadIdx.x;
    const int m0 = blockIdx.x * 128;

    // A tile 128x128 fp32 -> fp16 (loaded once, reused across all 4 panels)
#pragma unroll
    for (int it = 0; it < 16; it++) {
        int idx = tid + it * 256;
        int r = idx >> 5, q = idx & 31;
        float4 v = make_float4(0.f, 0.f, 0.f, 0.f);
        if (m0 + r < N) v = *(const float4*)(A + (size_t)(m0 + r) * 128 + q * 4);
        __half2 h01 = __floats2half2_rn(v.x, v.y);
        __half2 h23 = __floats2half2_rn(v.z, v.w);
        *(uint2*)&As[r][q * 4] = make_uint2(*(uint32_t*)&h01, *(uint32_t*)&h23);
    }

    const int lane = tid & 31, wid = tid >> 5;
    const int wm = wid >> 1, wn = wid & 1;       // 4(M) x 2(N)
    const int g = lane >> 2, c = lane & 3;
    const uint32_t AsU = smem_u32(As), BsU = smem_u32(Bs);

    uint32_t a_ad[2], b_ad[4];
#pragma unroll
    for (int mt = 0; mt < 2; mt++)
        a_ad[mt] = AsU + (wm * 32 + mt * 16 + (lane & 15)) * 272
                   + ((lane >> 4) & 1) * 16;
#pragma unroll
    for (int j = 0; j < 4; j++)
        b_ad[j] = BsU + (wn * 64 + j * 16 + ((lane >> 4) << 3) + (lane & 7)) * 272
                  + ((lane >> 3) & 1) * 16;

    for (int p = 0; p < 4; p++) {
        // B panel via cp.async (no register round trip)
        {
            const __half* srcp = g_img[which][p];
            for (int i = tid; i < PANEL_H / 8; i += 256)
                cp_async16(BsU + i * 16, srcp + i * 8);
            cp_async_wait_all();
        }
        __syncthreads();

        float acc[2][8][4] = {};
#pragma unroll
        for (int ks = 0; ks < 8; ks++) {
            const int kb = ks * 32;
            uint32_t af[2][4], bf[8][2];
#pragma unroll
            for (int mt = 0; mt < 2; mt++)
                ldsm_x4(af[mt][0], af[mt][1], af[mt][2], af[mt][3], a_ad[mt] + kb);
#pragma unroll
            for (int j = 0; j < 4; j++)
                ldsm_x4(bf[2 * j][0], bf[2 * j][1], bf[2 * j + 1][0],
                        bf[2 * j + 1][1], b_ad[j] + kb);
#pragma unroll
            for (int mt = 0; mt < 2; mt++)
#pragma unroll
                for (int nt = 0; nt < 8; nt++)
                    mma_f16(acc[mt][nt], af[mt], bf[nt]);
        }

        // Stage fragments in smem (conflict-free STS.32)
#pragma unroll
        for (int mt = 0; mt < 2; mt++) {
#pragma unroll
            for (int nt = 0; nt < 8; nt++) {
                int rl = wm * 32 + mt * 16 + g;
                int cl = wn * 64 + nt * 8 + c * 2;
                *(__half2*)&St[rl][cl] =
                    __floats2half2_rn(acc[mt][nt][0], acc[mt][nt][1]);
                *(__half2*)&St[rl + 8][cl] =
                    __floats2half2_rn(acc[mt][nt][2], acc[mt][nt][3]);
            }
        }
        __syncthreads();

        // Coalesced write-out: full 256B rows via STG.128
        const int n0 = p * 128;
#pragma unroll
        for (int it = 0; it < 8; it++) {
            int idx = tid + it * 256;
            int r = idx >> 4, q = idx & 15;
            if (m0 + r < N)
                *(uint4*)(C + (size_t)(m0 + r) * 512 + n0 + q * 8) =
                    *(const uint4*)&St[r][q * 8];
        }
        // Next panel's cp.async writes Bs (mainloop done); St reuse is guarded
        // by the __syncthreads after the next B-copy wait.
    }
}

// ---------------------------------------------------------------------------
// Src GEMM1: g_H = relu(BN(memory[src] @ fc1s_w + b)).
// ---------------------------------------------------------------------------
__global__ void __launch_bounds__(256, 3) k_src1_h(
    const float* __restrict__ memory, const float* __restrict__ fc1s_b,
    const float* __restrict__ bn_g, const float* __restrict__ bn_b,
    const float* __restrict__ bn_m, const float* __restrict__ bn_v,
    const int* __restrict__ src) {
    extern __shared__ char smem[];
    __half (*As)[136] = (__half(*)[136])smem;
    __half (*Bs)[136] = (__half(*)[136])(smem + 64 * 136 * 2);
    __shared__ int nd[64];
    const int tid = threadIdx.x;
    const int m0 = blockIdx.x * 64;

    if (tid < 64) nd[tid] = (m0 + tid < E_N) ? src[m0 + tid] : 0;
    __syncthreads();
#pragma unroll
    for (int it = 0; it < 8; it++) {
        int idx = tid + it * 256;
        int r = idx >> 5, q = idx & 31;
        float4 v = make_float4(0.f, 0.f, 0.f, 0.f);
        if (m0 + r < E_N) v = *(const float4*)(memory + (size_t)nd[r] * 128 + q * 4);
        __half2 h01 = __floats2half2_rn(v.x, v.y);
        __half2 h23 = __floats2half2_rn(v.z, v.w);
        *(uint2*)&As[r][q * 4] = make_uint2(*(uint32_t*)&h01, *(uint32_t*)&h23);
    }
    {
        const __half* srcp = g_img[2][blockIdx.y];
        uint32_t BsA = smem_u32(Bs);
        for (int i = tid; i < PANEL_H / 8; i += 256)
            cp_async16(BsA + i * 16, srcp + i * 8);
        cp_async_wait_all();
    }
    __syncthreads();

    const int lane = tid & 31, wid = tid >> 5;
    const int wm = wid >> 2, wn = wid & 3;
    const int g = lane >> 2, c = lane & 3;
    const uint32_t AsU = smem_u32(As), BsU = smem_u32(Bs);
    float acc[2][4][4] = {};
    FP16_MAINLOOP_LDSM(AsU, BsU, acc, wm, wn)

    const int n0 = blockIdx.y * 128;
#pragma unroll
    for (int nt = 0; nt < 4; nt++) {
        int col = n0 + wn * 32 + nt * 8 + c * 2;
        float s0 = bn_g[col]     * rsqrtf(bn_v[col]     + EPSV);
        float s1 = bn_g[col + 1] * rsqrtf(bn_v[col + 1] + EPSV);
        float o0 = fc1s_b[col]     - bn_m[col];
        float o1 = fc1s_b[col + 1] - bn_m[col + 1];
        float bb0 = bn_b[col], bb1 = bn_b[col + 1];
#pragma unroll
        for (int mt = 0; mt < 2; mt++) {
            int r = m0 + wm * 32 + mt * 16 + g;
            if (r < E_N)
                *(__half2*)(g_H + (size_t)r * 512 + col) = __floats2half2_rn(
                    fmaxf((acc[mt][nt][0] + o0) * s0 + bb0, 0.f),
                    fmaxf((acc[mt][nt][1] + o1) * s1 + bb1, 0.f));
            if (r + 8 < E_N)
                *(__half2*)(g_H + (size_t)(r + 8) * 512 + col) = __floats2half2_rn(
                    fmaxf((acc[mt][nt][2] + o0) * s0 + bb0, 0.f),
                    fmaxf((acc[mt][nt][3] + o1) * s1 + bb1, 0.f));
        }
    }
}

// ---------------------------------------------------------------------------
// Second GEMM: C[R,128] = A[R,512](fp16) @ W[512,128] + bias.
// ---------------------------------------------------------------------------
__global__ void __launch_bounds__(256, 3) k_gemm2_h(
    const float* __restrict__ bias, float* __restrict__ out, int R, int mode) {
    extern __shared__ char smem[];
    __half (*As)[136] = (__half(*)[136])smem;
    __half (*Bs)[136] = (__half(*)[136])(smem + 64 * 136 * 2);
    const __half* __restrict__ A = mode ? g_g : g_H;
    const int wimg = mode ? 4 : 3;
    const int tid = threadIdx.x;
    const int m0 = blockIdx.x * 64;

    const int lane = tid & 31, wid = tid >> 5;
    const int wm = wid >> 2, wn = wid & 3;
    const int g = lane >> 2, c = lane & 3;
    const uint32_t AsU = smem_u32(As), BsU = smem_u32(Bs);
    float acc[2][4][4] = {};

    for (int kc = 0; kc < 4; kc++) {
#pragma unroll
        for (int it = 0; it < 8; it++) {
            int idx = tid + it * 256;
            int r = idx >> 5, q = idx & 31;
            uint2 v = make_uint2(0u, 0u);
            if (m0 + r < R)
                v = *(const uint2*)(A + (size_t)(m0 + r) * 512 + kc * 128 + q * 4);
            *(uint2*)&As[r][q * 4] = v;
        }
        {
            const __half* srcp = g_img[wimg][kc];
            for (int i = tid; i < PANEL_H / 8; i += 256)
                cp_async16(BsU + i * 16, srcp + i * 8);
            cp_async_wait_all();
        }
        __syncthreads();
        FP16_MAINLOOP_LDSM(AsU, BsU, acc, wm, wn)
        __syncthreads();
    }

#pragma unroll
    for (int mt = 0; mt < 2; mt++) {
#pragma unroll
        for (int nt = 0; nt < 4; nt++) {
            int col = wn * 32 + nt * 8 + c * 2;
            float b0 = bias[col], b1 = bias[col + 1];
#pragma unroll
            for (int half = 0; half < 2; half++) {
                int r = m0 + wm * 32 + mt * 16 + g + half * 8;
                if (r >= R) continue;
                float v0 = acc[mt][nt][half * 2 + 0];
                float v1 = acc[mt][nt][half * 2 + 1];
                if (mode == 0) {
                    *(float2*)(out + (size_t)r * 384 + col) =
                        make_float2(v0 + b0, v1 + b1);
                } else {
                    int br = r / E_N, e = r - br * E_N;
                    float fl = g_flag[r];
                    *(float2*)(out + (size_t)e * 384 + 128 + br * 128 + col) =
                        make_float2(v0 + b0 * fl, v1 + b1 * fl);
                }
            }
        }
    }
}

// ---------------------------------------------------------------------------
// k_branch: 128 threads, 4 cols/thread; LDG.64 gathers; packed f32x2.
// ---------------------------------------------------------------------------
__global__ void __launch_bounds__(128) k_branch(
    const float* __restrict__ sel_dt, const float* __restrict__ sel_w,
    const float* __restrict__ fc1_b,
    const float* __restrict__ ln1_g, const float* __restrict__ ln1_b,
    const int* __restrict__ sel_nodes, const int* __restrict__ sel_edges) {
    const int e = blockIdx.x, br = blockIdx.y;
    const int tid = threadIdx.x;
    __shared__ float ctd[KSEL][PCH * 2];
    __shared__ float wn[KSEL];
    __shared__ int   nd_s[KSEL], ed_s[KSEL];
    __shared__ float red_s[KSEL][4], red_q[KSEL][4];
    __shared__ float mu_s[KSEL], rs_s[KSEL];
    __shared__ float flag_s;

    const size_t base = ((size_t)br * E_N + e) * KSEL;
    if (tid < KSEL) {
        int k = tid;
        float dt = sel_dt[base + k];
        wn[k]   = sel_w[base + k];
        nd_s[k] = sel_nodes[base + k];
        ed_s[k] = sel_edges[base + k];
        float x = 2.f * dt - 1.f;
        float t0 = 1.f, t1 = x;
        ctd[k][0] = t0; ctd[k][1] = t0;
        ctd[k][2] = t1; ctd[k][3] = t1;
#pragma unroll
        for (int p = 2; p < PCH; p++) {
            float t2 = 2.f * x * t1 - t0;
            ctd[k][2 * p] = t2; ctd[k][2 * p + 1] = t2;
            t0 = t1; t1 = t2;
        }
    }
    __syncthreads();
    if (tid == 0) {
        float ws = 0.f;
#pragma unroll
        for (int k = 0; k < KSEL; k++) ws += wn[k];
        float fl = (ws > 0.f) ? 1.f : 0.f;
        flag_s = fl;
        float inv = fl > 0.f ? 1.f / ws : 0.f;
#pragma unroll
        for (int k = 0; k < KSEL; k++) wn[k] *= inv;
    }

    const int c0 = tid * 4;
    unsigned long long acc[KSEL][2];
    const float4 bv = *(const float4*)(fc1_b + c0);
#pragma unroll
    for (int k = 0; k < KSEL; k++) {
        uint2 vn = *(const uint2*)(g_Pn + (size_t)nd_s[k] * 512 + c0);
        uint2 ve = *(const uint2*)(g_Pe + (size_t)ed_s[k] * 512 + c0);
        float2 n0 = __half22float2(*(__half2*)&vn.x);
        float2 n1 = __half22float2(*(__half2*)&vn.y);
        float2 e0 = __half22float2(*(__half2*)&ve.x);
        float2 e1 = __half22float2(*(__half2*)&ve.y);
        acc[k][0] = pk2(n0.x + e0.x + bv.x, n0.y + e0.y + bv.y);
        acc[k][1] = pk2(n1.x + e1.x + bv.z, n1.y + e1.y + bv.w);
    }
    const uint32_t ctd_base = smem_u32(ctd);
#pragma unroll
    for (int half = 0; half < 2; half++) {
        unsigned long long Gd[8][2];
#pragma unroll
        for (int p = 0; p < 8; p++) {
            float4 gv = *(const float4*)(g_G + (half * 8 + p) * 512 + c0);
            Gd[p][0] = pk2(gv.x, gv.y);
            Gd[p][1] = pk2(gv.z, gv.w);
        }
#pragma unroll
        for (int k = 0; k < KSEL; k++) {
            uint32_t row = ctd_base + k * 128 + half * 64;
#pragma unroll
            for (int p = 0; p < 8; p += 2) {
                unsigned long long t0, t1;
                asm("ld.shared.v2.b64 {%0, %1}, [%2];"
                    : "=l"(t0), "=l"(t1) : "r"(row + p * 8));
                asm("fma.rn.f32x2 %0, %1, %2, %0;" : "+l"(acc[k][0]) : "l"(t0), "l"(Gd[p][0]));
                asm("fma.rn.f32x2 %0, %1, %2, %0;" : "+l"(acc[k][1]) : "l"(t0), "l"(Gd[p][1]));
                asm("fma.rn.f32x2 %0, %1, %2, %0;" : "+l"(acc[k][0]) : "l"(t1), "l"(Gd[p + 1][0]));
                asm("fma.rn.f32x2 %0, %1, %2, %0;" : "+l"(acc[k][1]) : "l"(t1), "l"(Gd[p + 1][1]));
            }
        }
    }
    const int lane = tid & 31, warp = tid >> 5;
#pragma unroll
    for (int k = 0; k < KSEL; k++) {
        float2 a0 = *(float2*)&acc[k][0];
        float2 a1 = *(float2*)&acc[k][1];
        float s = a0.x + a0.y + a1.x + a1.y;
        float q = a0.x * a0.x + a0.y * a0.y + a1.x * a1.x + a1.y * a1.y;
#pragma unroll
        for (int o = 16; o > 0; o >>= 1) {
            s += __shfl_down_sync(0xffffffffu, s, o);
            q += __shfl_down_sync(0xffffffffu, q, o);
        }
        if (lane == 0) { red_s[k][warp] = s; red_q[k][warp] = q; }
    }
    __syncthreads();
    if (tid < KSEL) {
        float s = 0.f, q = 0.f;
#pragma unroll
        for (int w = 0; w < 4; w++) { s += red_s[tid][w]; q += red_q[tid][w]; }
        float mu = s * (1.f / 512.f);
        float var = q * (1.f / 512.f) - mu * mu;
        mu_s[tid] = mu;
        rs_s[tid] = rsqrtf(var + EPSV);
    }
    __syncthreads();
    const float4 lg = *(const float4*)(ln1_g + c0);
    const float4 lb = *(const float4*)(ln1_b + c0);
    float o0 = 0.f, o1 = 0.f, o2 = 0.f, o3 = 0.f;
#pragma unroll
    for (int k = 0; k < KSEL; k++) {
        float2 a0 = *(float2*)&acc[k][0];
        float2 a1 = *(float2*)&acc[k][1];
        float mu = mu_s[k], rs = rs_s[k], w = wn[k];
        o0 += w * fmaxf((a0.x - mu) * rs * lg.x + lb.x, 0.f);
        o1 += w * fmaxf((a0.y - mu) * rs * lg.y + lb.y, 0.f);
        o2 += w * fmaxf((a1.x - mu) * rs * lg.z + lb.z, 0.f);
        o3 += w * fmaxf((a1.y - mu) * rs * lg.w + lb.w, 0.f);
    }
    __half2 h01 = __floats2half2_rn(o0, o1);
    __half2 h23 = __floats2half2_rn(o2, o3);
    *(uint2*)(g_g + ((size_t)br * E_N + e) * 512 + c0) =
        make_uint2(*(uint32_t*)&h01, *(uint32_t*)&h23);
    if (tid == 0) g_flag[br * E_N + e] = flag_s;
}

// ---------------------------------------------------------------------------
extern "C" void kernel_launch(void* const* d_in, const int* in_sizes, int n_in,
                              void* d_out, int out_size) {
    const float* memory    = (const float*)d_in[0];
    const float* edge_feat = (const float*)d_in[1];
    const float* sel_dt    = (const float*)d_in[2];
    const float* sel_w     = (const float*)d_in[3];
    const float* time_w    = (const float*)d_in[4];
    const float* time_b    = (const float*)d_in[5];
    const float* fc1_w     = (const float*)d_in[6];
    const float* fc1_b     = (const float*)d_in[7];
    const float* ln1_g     = (const float*)d_in[8];
    const float* ln1_b     = (const float*)d_in[9];
    const float* fc2_w     = (const float*)d_in[10];
    const float* fc2_b     = (const float*)d_in[11];
    const float* fc1s_w    = (const float*)d_in[12];
    const float* fc1s_b    = (const float*)d_in[13];
    const float* bn_g      = (const float*)d_in[14];
    const float* bn_b      = (const float*)d_in[15];
    const float* bn_m      = (const float*)d_in[16];
    const float* bn_v      = (const float*)d_in[17];
    const float* fc2s_w    = (const float*)d_in[18];
    const float* fc2s_b    = (const float*)d_in[19];
    const int* source_nodes = (const int*)d_in[20];
    const int* sel_nodes    = (const int*)d_in[21];
    const int* sel_edges    = (const int*)d_in[22];
    float* out = (float*)d_out;

    cudaFuncSetAttribute(k_pre_h,   cudaFuncAttributeMaxDynamicSharedMemorySize, SMEM_128);
    cudaFuncSetAttribute(k_src1_h,  cudaFuncAttributeMaxDynamicSharedMemorySize, SMEM_64);
    cudaFuncSetAttribute(k_gemm2_h, cudaFuncAttributeMaxDynamicSharedMemorySize, SMEM_64);

    k_prep<<<1280, 256>>>(fc1_w, fc1s_w, fc2s_w, fc2_w);
    k_cheb<<<1, 512>>>(time_w, time_b, fc1_w);
    k_pre_h<<<(NNODES + 127) / 128, 256, SMEM_128>>>(memory, NNODES, 0);
    k_pre_h<<<(NEDGES + 127) / 128, 256, SMEM_128>>>(edge_feat, NEDGES, 1);
    k_src1_h<<<dim3((E_N + 63) / 64, 4), 256, SMEM_64>>>(
        memory, fc1s_b, bn_g, bn_b, bn_m, bn_v, source_nodes);
    k_gemm2_h<<<(E_N + 63) / 64, 256, SMEM_64>>>(fc2s_b, out, E_N, 0);
    k_branch<<<dim3(E_N, NT_), 128>>>(sel_dt, sel_w, fc1_b, ln1_g, ln1_b,
                                      sel_nodes, sel_edges);
    k_gemm2_h<<<(NT_ * E_N + 63) / 64, 256, SMEM_64>>>(fc2_b, out, NT_ * E_N, 1);
}

// round 12
// speedup vs baseline: 5.1731x; 1.0752x over previous
#include <cuda_runtime.h>
#include <cuda_fp16.h>
#include <math.h>
#include <cstdint>

#define E_N     20000
#define KSEL    20
#define D_      128
#define F1_     512
#define F2_     128
#define NT_     2
#define NNODES  200000
#define NEDGES  500000
#define EPSV    1e-5f
#define PCH     12

// Scratch (allocation-free rule: __device__ globals)
static __device__ __half g_Pn[(size_t)NNODES * F1_];
static __device__ __half g_Pe[(size_t)NEDGES * F1_];
static __device__ __half g_g [(size_t)NT_ * E_N * F1_];
static __device__ __half g_H [(size_t)E_N * F1_];
static __device__ float  g_flag[NT_ * E_N];
static __device__ float  g_G[PCH * F1_];
#define PANEL_H 17408
#define PANEL_B (PANEL_H * 2)       // 34816 bytes
static __device__ __align__(16) __half g_img[5][4][PANEL_H];

__device__ __forceinline__ void mma_f16(float* c, const uint32_t* a, const uint32_t* b) {
    asm volatile("mma.sync.aligned.m16n8k16.row.col.f32.f16.f16.f32 "
                 "{%0,%1,%2,%3}, {%4,%5,%6,%7}, {%8,%9}, {%0,%1,%2,%3};"
                 : "+f"(c[0]), "+f"(c[1]), "+f"(c[2]), "+f"(c[3])
                 : "r"(a[0]), "r"(a[1]), "r"(a[2]), "r"(a[3]),
                   "r"(b[0]), "r"(b[1]));
}
__device__ __forceinline__ void ldsm_x4(uint32_t& r0, uint32_t& r1, uint32_t& r2,
                                        uint32_t& r3, uint32_t addr) {
    asm volatile("ldmatrix.sync.aligned.m8n8.x4.shared.b16 {%0,%1,%2,%3}, [%4];"
                 : "=r"(r0), "=r"(r1), "=r"(r2), "=r"(r3) : "r"(addr));
}
__device__ __forceinline__ uint32_t smem_u32(const void* p) {
    uint32_t a;
    asm("{ .reg .u64 t; cvta.to.shared.u64 t, %1; cvt.u32.u64 %0, t; }" : "=r"(a) : "l"(p));
    return a;
}
__device__ __forceinline__ unsigned long long pk2(float x, float y) {
    unsigned long long r;
    asm("mov.b64 %0, {%1, %2};" : "=l"(r) : "f"(x), "f"(y));
    return r;
}
__device__ __forceinline__ void cp_async16(uint32_t dst, const void* src) {
    asm volatile("cp.async.ca.shared.global [%0], [%1], 16;"
                 :: "r"(dst), "l"(__cvta_generic_to_global(src)) : "memory");
}
__device__ __forceinline__ void cp_commit() {
    asm volatile("cp.async.commit_group;" ::: "memory");
}
__device__ __forceinline__ void cp_wait0() {
    asm volatile("cp.async.wait_group 0;" ::: "memory");
}

// ---------------------------------------------------------------------------
// Weight prep (unchanged)
// ---------------------------------------------------------------------------
__global__ void k_prep(const float* __restrict__ fc1_w,
                       const float* __restrict__ fc1s_w,
                       const float* __restrict__ fc2s_w,
                       const float* __restrict__ fc2_w) {
    int idx = blockIdx.x * 256 + threadIdx.x;
    int k = idx & 127;
    int n = (idx >> 7) & 127;
    int p = (idx >> 14) & 3;
    int m = idx >> 16;
    float v;
    if      (m == 0) v = fc1_w [(size_t)k          * 512 + p * 128 + n];
    else if (m == 1) v = fc1_w [(size_t)(128 + k)  * 512 + p * 128 + n];
    else if (m == 2) v = fc1s_w[(size_t)k          * 512 + p * 128 + n];
    else if (m == 3) v = fc2s_w[(size_t)(p * 128 + k) * 128 + n];
    else             v = fc2_w [(size_t)(p * 128 + k) * 128 + n];
    g_img[m][p][n * 136 + k] = __float2half(v);
}

// ---------------------------------------------------------------------------
// Chebyshev prolog, degree 12
// ---------------------------------------------------------------------------
__global__ void __launch_bounds__(512) k_cheb(const float* __restrict__ time_w,
                                              const float* __restrict__ time_b,
                                              const float* __restrict__ fc1_w) {
    __shared__ float teq[PCH][100];
    const int tid = threadIdx.x;
    for (int i = tid; i < PCH * 100; i += 512) {
        int q = i / 100, j = i - q * 100;
        float xq  = cospif((q + 0.5f) / (float)PCH);
        float dtq = 0.5f * (xq + 1.0f);
        teq[q][j] = cosf(dtq * time_w[j] + time_b[j]);
    }
    __syncthreads();
    const float* __restrict__ W1t = fc1_w + (size_t)256 * 512;
    float M[PCH];
#pragma unroll
    for (int q = 0; q < PCH; q++) M[q] = 0.f;
    for (int j = 0; j < 100; j++) {
        float w = W1t[(size_t)j * 512 + tid];
#pragma unroll
        for (int q = 0; q < PCH; q++) M[q] += teq[q][j] * w;
    }
#pragma unroll
    for (int p = 0; p < PCH; p++) {
        float s = 0.f;
#pragma unroll
        for (int q = 0; q < PCH; q++)
            s += cospif(p * (q + 0.5f) / (float)PCH) * M[q];
        g_G[p * 512 + tid] = s * ((p == 0 ? 1.0f : 2.0f) / (float)PCH);
    }
}

// ===========================================================================
// fp16 mma machinery (ldmatrix fragment loads)
// ===========================================================================
#define SMEM_64   (64 * 136 * 2 + 128 * 136 * 2)
#define SMEM_128  (3 * 128 * 136 * 2)            // As + B0 + B1 (stage aliases B)

// 8 warps as 2(M) x 4(N); warp tile 32x32; ldmatrix fragments.
#define FP16_MAINLOOP_LDSM(AsU, BsU, acc, wm, wn)                              \
    {                                                                          \
        const int lane_ = threadIdx.x & 31;                                    \
        uint32_t a_ad[2], b_ad[2];                                             \
        _Pragma("unroll")                                                      \
        for (int mt = 0; mt < 2; mt++)                                         \
            a_ad[mt] = (AsU) + ((wm) * 32 + mt * 16 + (lane_ & 15)) * 272      \
                       + ((lane_ >> 4) & 1) * 16;                              \
        _Pragma("unroll")                                                      \
        for (int j = 0; j < 2; j++)                                            \
            b_ad[j] = (BsU) + ((wn) * 32 + j * 16 + ((lane_ >> 4) << 3)        \
                       + (lane_ & 7)) * 272 + ((lane_ >> 3) & 1) * 16;         \
        _Pragma("unroll")                                                      \
        for (int ks = 0; ks < 8; ks++) {                                       \
            const int kb = ks * 32;                                            \
            uint32_t af[2][4], bf[4][2];                                       \
            _Pragma("unroll")                                                  \
            for (int mt = 0; mt < 2; mt++)                                     \
                ldsm_x4(af[mt][0], af[mt][1], af[mt][2], af[mt][3],            \
                        a_ad[mt] + kb);                                        \
            _Pragma("unroll")                                                  \
            for (int j = 0; j < 2; j++)                                        \
                ldsm_x4(bf[2 * j][0], bf[2 * j][1], bf[2 * j + 1][0],          \
                        bf[2 * j + 1][1], b_ad[j] + kb);                       \
            _Pragma("unroll")                                                  \
            for (int mt = 0; mt < 2; mt++)                                     \
                _Pragma("unroll")                                              \
                for (int nt = 0; nt < 4; nt++)                                 \
                    mma_f16(acc[mt][nt], af[mt], bf[nt]);                      \
        }                                                                      \
    }

// ---------------------------------------------------------------------------
// k_pre: one CTA = 128 rows x 512 cols; 8 warps as 4(M) x 2(N), tile 32x64.
// Double-buffered B with the stage buffer ALIASED onto the consumed panel;
// next-panel cp.async overlaps staging + store-out.
// ---------------------------------------------------------------------------
__global__ void __launch_bounds__(256, 2) k_pre_h(const float* __restrict__ A,
                                                  int N, int which) {
    extern __shared__ char smem[];
    __half (*As)[136] = (__half(*)[136])smem;
    __half* __restrict__ C = which ? g_Pe : g_Pn;
    const int tid = threadIdx.x;
    const int m0 = blockIdx.x * 128;
    const uint32_t AsU = smem_u32(smem);
    const uint32_t Bbase[2] = {AsU + PANEL_B, AsU + 2 * PANEL_B};

    // Prefetch panel 0 into B0
    {
        const __half* srcp = g_img[which][0];
        for (int i = tid; i < PANEL_H / 8; i += 256)
            cp_async16(Bbase[0] + i * 16, srcp + i * 8);
        cp_commit();
    }
    // A tile 128x128 fp32 -> fp16 (loaded once, reused across all 4 panels)
#pragma unroll
    for (int it = 0; it < 16; it++) {
        int idx = tid + it * 256;
        int r = idx >> 5, q = idx & 31;
        float4 v = make_float4(0.f, 0.f, 0.f, 0.f);
        if (m0 + r < N) v = *(const float4*)(A + (size_t)(m0 + r) * 128 + q * 4);
        __half2 h01 = __floats2half2_rn(v.x, v.y);
        __half2 h23 = __floats2half2_rn(v.z, v.w);
        *(uint2*)&As[r][q * 4] = make_uint2(*(uint32_t*)&h01, *(uint32_t*)&h23);
    }

    const int lane = tid & 31, wid = tid >> 5;
    const int wm = wid >> 1, wn = wid & 1;       // 4(M) x 2(N)
    const int g = lane >> 2, c = lane & 3;

    uint32_t a_ad[2], b_off[4];
#pragma unroll
    for (int mt = 0; mt < 2; mt++)
        a_ad[mt] = AsU + (wm * 32 + mt * 16 + (lane & 15)) * 272
                   + ((lane >> 4) & 1) * 16;
#pragma unroll
    for (int j = 0; j < 4; j++)
        b_off[j] = (wn * 64 + j * 16 + ((lane >> 4) << 3) + (lane & 7)) * 272
                   + ((lane >> 3) & 1) * 16;

    for (int p = 0; p < 4; p++) {
        const uint32_t Bcur = Bbase[p & 1];
        cp_wait0();
        __syncthreads();                          // panel p ready, all loads done

        float acc[2][8][4] = {};
#pragma unroll
        for (int ks = 0; ks < 8; ks++) {
            const int kb = ks * 32;
            uint32_t af[2][4], bf[8][2];
#pragma unroll
            for (int mt = 0; mt < 2; mt++)
                ldsm_x4(af[mt][0], af[mt][1], af[mt][2], af[mt][3], a_ad[mt] + kb);
#pragma unroll
            for (int j = 0; j < 4; j++)
                ldsm_x4(bf[2 * j][0], bf[2 * j][1], bf[2 * j + 1][0],
                        bf[2 * j + 1][1], Bcur + b_off[j] + kb);
#pragma unroll
            for (int mt = 0; mt < 2; mt++)
#pragma unroll
                for (int nt = 0; nt < 8; nt++)
                    mma_f16(acc[mt][nt], af[mt], bf[nt]);
        }
        __syncthreads();                          // all warps done reading Bcur

        // Prefetch next panel into the OTHER buffer (overlaps stage + STG)
        if (p < 3) {
            const __half* srcp = g_img[which][p + 1];
            const uint32_t Bnext = Bbase[(p + 1) & 1];
            for (int i = tid; i < PANEL_H / 8; i += 256)
                cp_async16(Bnext + i * 16, srcp + i * 8);
            cp_commit();
        }

        // Stage fragments into the just-consumed panel buffer (alias)
        __half (*St)[136] = (__half(*)[136])(smem + (size_t)(Bcur - AsU));
#pragma unroll
        for (int mt = 0; mt < 2; mt++) {
#pragma unroll
            for (int nt = 0; nt < 8; nt++) {
                int rl = wm * 32 + mt * 16 + g;
                int cl = wn * 64 + nt * 8 + c * 2;
                *(__half2*)&St[rl][cl] =
                    __floats2half2_rn(acc[mt][nt][0], acc[mt][nt][1]);
                *(__half2*)&St[rl + 8][cl] =
                    __floats2half2_rn(acc[mt][nt][2], acc[mt][nt][3]);
            }
        }
        __syncthreads();

        // Coalesced write-out: full 256B rows via STG.128
        const int n0 = p * 128;
#pragma unroll
        for (int it = 0; it < 8; it++) {
            int idx = tid + it * 256;
            int r = idx >> 4, q = idx & 15;
            if (m0 + r < N)
                *(uint4*)(C + (size_t)(m0 + r) * 512 + n0 + q * 8) =
                    *(const uint4*)&St[r][q * 8];
        }
    }
}

// ---------------------------------------------------------------------------
// Src GEMM1: g_H = relu(BN(memory[src] @ fc1s_w + b)).
// ---------------------------------------------------------------------------
__global__ void __launch_bounds__(256, 3) k_src1_h(
    const float* __restrict__ memory, const float* __restrict__ fc1s_b,
    const float* __restrict__ bn_g, const float* __restrict__ bn_b,
    const float* __restrict__ bn_m, const float* __restrict__ bn_v,
    const int* __restrict__ src) {
    extern __shared__ char smem[];
    __half (*As)[136] = (__half(*)[136])smem;
    __half (*Bs)[136] = (__half(*)[136])(smem + 64 * 136 * 2);
    __shared__ int nd[64];
    const int tid = threadIdx.x;
    const int m0 = blockIdx.x * 64;

    {
        const __half* srcp = g_img[2][blockIdx.y];
        uint32_t BsA = smem_u32(Bs);
        for (int i = tid; i < PANEL_H / 8; i += 256)
            cp_async16(BsA + i * 16, srcp + i * 8);
        cp_commit();
    }
    if (tid < 64) nd[tid] = (m0 + tid < E_N) ? src[m0 + tid] : 0;
    __syncthreads();
#pragma unroll
    for (int it = 0; it < 8; it++) {
        int idx = tid + it * 256;
        int r = idx >> 5, q = idx & 31;
        float4 v = make_float4(0.f, 0.f, 0.f, 0.f);
        if (m0 + r < E_N) v = *(const float4*)(memory + (size_t)nd[r] * 128 + q * 4);
        __half2 h01 = __floats2half2_rn(v.x, v.y);
        __half2 h23 = __floats2half2_rn(v.z, v.w);
        *(uint2*)&As[r][q * 4] = make_uint2(*(uint32_t*)&h01, *(uint32_t*)&h23);
    }
    cp_wait0();
    __syncthreads();

    const int lane = tid & 31, wid = tid >> 5;
    const int wm = wid >> 2, wn = wid & 3;
    const int g = lane >> 2, c = lane & 3;
    const uint32_t AsU = smem_u32(As), BsU = smem_u32(Bs);
    float acc[2][4][4] = {};
    FP16_MAINLOOP_LDSM(AsU, BsU, acc, wm, wn)

    const int n0 = blockIdx.y * 128;
#pragma unroll
    for (int nt = 0; nt < 4; nt++) {
        int col = n0 + wn * 32 + nt * 8 + c * 2;
        float s0 = bn_g[col]     * rsqrtf(bn_v[col]     + EPSV);
        float s1 = bn_g[col + 1] * rsqrtf(bn_v[col + 1] + EPSV);
        float o0 = fc1s_b[col]     - bn_m[col];
        float o1 = fc1s_b[col + 1] - bn_m[col + 1];
        float bb0 = bn_b[col], bb1 = bn_b[col + 1];
#pragma unroll
        for (int mt = 0; mt < 2; mt++) {
            int r = m0 + wm * 32 + mt * 16 + g;
            if (r < E_N)
                *(__half2*)(g_H + (size_t)r * 512 + col) = __floats2half2_rn(
                    fmaxf((acc[mt][nt][0] + o0) * s0 + bb0, 0.f),
                    fmaxf((acc[mt][nt][1] + o1) * s1 + bb1, 0.f));
            if (r + 8 < E_N)
                *(__half2*)(g_H + (size_t)(r + 8) * 512 + col) = __floats2half2_rn(
                    fmaxf((acc[mt][nt][2] + o0) * s0 + bb0, 0.f),
                    fmaxf((acc[mt][nt][3] + o1) * s1 + bb1, 0.f));
        }
    }
}

// ---------------------------------------------------------------------------
// Merged second GEMM: blocks [0,313) do src (g_H @ fc2s_w + fc2s_b),
// blocks [313, 938) do branches (g_g @ fc2_w + fc2_b * flag).
// ---------------------------------------------------------------------------
#define GEMM2_SRC_BLOCKS 313
__global__ void __launch_bounds__(256, 3) k_gemm2_h(
    const float* __restrict__ fc2s_b, const float* __restrict__ fc2_b,
    float* __restrict__ out) {
    extern __shared__ char smem[];
    __half (*As)[136] = (__half(*)[136])smem;
    __half (*Bs)[136] = (__half(*)[136])(smem + 64 * 136 * 2);
    const int tid = threadIdx.x;
    const int mode = (blockIdx.x >= GEMM2_SRC_BLOCKS) ? 1 : 0;
    const int blk  = mode ? (blockIdx.x - GEMM2_SRC_BLOCKS) : blockIdx.x;
    const int m0 = blk * 64;
    const int R  = mode ? NT_ * E_N : E_N;
    const __half* __restrict__ A = mode ? g_g : g_H;
    const float* __restrict__ bias = mode ? fc2_b : fc2s_b;
    const int wimg = mode ? 4 : 3;

    const int lane = tid & 31, wid = tid >> 5;
    const int wm = wid >> 2, wn = wid & 3;
    const int g = lane >> 2, c = lane & 3;
    const uint32_t AsU = smem_u32(As), BsU = smem_u32(Bs);
    float acc[2][4][4] = {};

    for (int kc = 0; kc < 4; kc++) {
        {
            const __half* srcp = g_img[wimg][kc];
            for (int i = tid; i < PANEL_H / 8; i += 256)
                cp_async16(BsU + i * 16, srcp + i * 8);
            cp_commit();
        }
#pragma unroll
        for (int it = 0; it < 8; it++) {
            int idx = tid + it * 256;
            int r = idx >> 5, q = idx & 31;
            uint2 v = make_uint2(0u, 0u);
            if (m0 + r < R)
                v = *(const uint2*)(A + (size_t)(m0 + r) * 512 + kc * 128 + q * 4);
            *(uint2*)&As[r][q * 4] = v;
        }
        cp_wait0();
        __syncthreads();
        FP16_MAINLOOP_LDSM(AsU, BsU, acc, wm, wn)
        __syncthreads();
    }

#pragma unroll
    for (int mt = 0; mt < 2; mt++) {
#pragma unroll
        for (int nt = 0; nt < 4; nt++) {
            int col = wn * 32 + nt * 8 + c * 2;
            float b0 = bias[col], b1 = bias[col + 1];
#pragma unroll
            for (int half = 0; half < 2; half++) {
                int r = m0 + wm * 32 + mt * 16 + g + half * 8;
                if (r >= R) continue;
                float v0 = acc[mt][nt][half * 2 + 0];
                float v1 = acc[mt][nt][half * 2 + 1];
                if (mode == 0) {
                    *(float2*)(out + (size_t)r * 384 + col) =
                        make_float2(v0 + b0, v1 + b1);
                } else {
                    int br = r / E_N, e = r - br * E_N;
                    float fl = g_flag[r];
                    *(float2*)(out + (size_t)e * 384 + 128 + br * 128 + col) =
                        make_float2(v0 + b0 * fl, v1 + b1 * fl);
                }
            }
        }
    }
}

// ---------------------------------------------------------------------------
// k_branch: 128 threads, 4 cols/thread; LDG.64 gathers; packed f32x2; PCH=12.
// ---------------------------------------------------------------------------
__global__ void __launch_bounds__(128) k_branch(
    const float* __restrict__ sel_dt, const float* __restrict__ sel_w,
    const float* __restrict__ fc1_b,
    const float* __restrict__ ln1_g, const float* __restrict__ ln1_b,
    const int* __restrict__ sel_nodes, const int* __restrict__ sel_edges) {
    const int e = blockIdx.x, br = blockIdx.y;
    const int tid = threadIdx.x;
    __shared__ float ctd[KSEL][PCH * 2];   // duplicated pairs (T_p, T_p); 96B rows
    __shared__ float wn[KSEL];
    __shared__ int   nd_s[KSEL], ed_s[KSEL];
    __shared__ float red_s[KSEL][4], red_q[KSEL][4];
    __shared__ float mu_s[KSEL], rs_s[KSEL];
    __shared__ float flag_s;

    const size_t base = ((size_t)br * E_N + e) * KSEL;
    if (tid < KSEL) {
        int k = tid;
        float dt = sel_dt[base + k];
        wn[k]   = sel_w[base + k];
        nd_s[k] = sel_nodes[base + k];
        ed_s[k] = sel_edges[base + k];
        float x = 2.f * dt - 1.f;
        float t0 = 1.f, t1 = x;
        ctd[k][0] = t0; ctd[k][1] = t0;
        ctd[k][2] = t1; ctd[k][3] = t1;
#pragma unroll
        for (int p = 2; p < PCH; p++) {
            float t2 = 2.f * x * t1 - t0;
            ctd[k][2 * p] = t2; ctd[k][2 * p + 1] = t2;
            t0 = t1; t1 = t2;
        }
    }
    __syncthreads();
    if (tid == 0) {
        float ws = 0.f;
#pragma unroll
        for (int k = 0; k < KSEL; k++) ws += wn[k];
        float fl = (ws > 0.f) ? 1.f : 0.f;
        flag_s = fl;
        float inv = fl > 0.f ? 1.f / ws : 0.f;
#pragma unroll
        for (int k = 0; k < KSEL; k++) wn[k] *= inv;
    }

    const int c0 = tid * 4;
    unsigned long long acc[KSEL][2];
    const float4 bv = *(const float4*)(fc1_b + c0);
#pragma unroll
    for (int k = 0; k < KSEL; k++) {
        uint2 vn = *(const uint2*)(g_Pn + (size_t)nd_s[k] * 512 + c0);
        uint2 ve = *(const uint2*)(g_Pe + (size_t)ed_s[k] * 512 + c0);
        float2 n0 = __half22float2(*(__half2*)&vn.x);
        float2 n1 = __half22float2(*(__half2*)&vn.y);
        float2 e0 = __half22float2(*(__half2*)&ve.x);
        float2 e1 = __half22float2(*(__half2*)&ve.y);
        acc[k][0] = pk2(n0.x + e0.x + bv.x, n0.y + e0.y + bv.y);
        acc[k][1] = pk2(n1.x + e1.x + bv.z, n1.y + e1.y + bv.w);
    }
    const uint32_t ctd_base = smem_u32(ctd);
#pragma unroll
    for (int half = 0; half < 2; half++) {
        unsigned long long Gd[6][2];
#pragma unroll
        for (int p = 0; p < 6; p++) {
            float4 gv = *(const float4*)(g_G + (half * 6 + p) * 512 + c0);
            Gd[p][0] = pk2(gv.x, gv.y);
            Gd[p][1] = pk2(gv.z, gv.w);
        }
#pragma unroll
        for (int k = 0; k < KSEL; k++) {
            uint32_t row = ctd_base + k * (PCH * 2 * 4) + half * 48;
#pragma unroll
            for (int p = 0; p < 6; p += 2) {
                unsigned long long t0, t1;
                asm("ld.shared.v2.b64 {%0, %1}, [%2];"
                    : "=l"(t0), "=l"(t1) : "r"(row + p * 8));
                asm("fma.rn.f32x2 %0, %1, %2, %0;" : "+l"(acc[k][0]) : "l"(t0), "l"(Gd[p][0]));
                asm("fma.rn.f32x2 %0, %1, %2, %0;" : "+l"(acc[k][1]) : "l"(t0), "l"(Gd[p][1]));
                asm("fma.rn.f32x2 %0, %1, %2, %0;" : "+l"(acc[k][0]) : "l"(t1), "l"(Gd[p + 1][0]));
                asm("fma.rn.f32x2 %0, %1, %2, %0;" : "+l"(acc[k][1]) : "l"(t1), "l"(Gd[p + 1][1]));
            }
        }
    }
    const int lane = tid & 31, warp = tid >> 5;
#pragma unroll
    for (int k = 0; k < KSEL; k++) {
        float2 a0 = *(float2*)&acc[k][0];
        float2 a1 = *(float2*)&acc[k][1];
        float s = a0.x + a0.y + a1.x + a1.y;
        float q = a0.x * a0.x + a0.y * a0.y + a1.x * a1.x + a1.y * a1.y;
#pragma unroll
        for (int o = 16; o > 0; o >>= 1) {
            s += __shfl_down_sync(0xffffffffu, s, o);
            q += __shfl_down_sync(0xffffffffu, q, o);
        }
        if (lane == 0) { red_s[k][warp] = s; red_q[k][warp] = q; }
    }
    __syncthreads();
    if (tid < KSEL) {
        float s = 0.f, q = 0.f;
#pragma unroll
        for (int w = 0; w < 4; w++) { s += red_s[tid][w]; q += red_q[tid][w]; }
        float mu = s * (1.f / 512.f);
        float var = q * (1.f / 512.f) - mu * mu;
        mu_s[tid] = mu;
        rs_s[tid] = rsqrtf(var + EPSV);
    }
    __syncthreads();
    const float4 lg = *(const float4*)(ln1_g + c0);
    const float4 lb = *(const float4*)(ln1_b + c0);
    float o0 = 0.f, o1 = 0.f, o2 = 0.f, o3 = 0.f;
#pragma unroll
    for (int k = 0; k < KSEL; k++) {
        float2 a0 = *(float2*)&acc[k][0];
        float2 a1 = *(float2*)&acc[k][1];
        float mu = mu_s[k], rs = rs_s[k], w = wn[k];
        o0 += w * fmaxf((a0.x - mu) * rs * lg.x + lb.x, 0.f);
        o1 += w * fmaxf((a0.y - mu) * rs * lg.y + lb.y, 0.f);
        o2 += w * fmaxf((a1.x - mu) * rs * lg.z + lb.z, 0.f);
        o3 += w * fmaxf((a1.y - mu) * rs * lg.w + lb.w, 0.f);
    }
    __half2 h01 = __floats2half2_rn(o0, o1);
    __half2 h23 = __floats2half2_rn(o2, o3);
    *(uint2*)(g_g + ((size_t)br * E_N + e) * 512 + c0) =
        make_uint2(*(uint32_t*)&h01, *(uint32_t*)&h23);
    if (tid == 0) g_flag[br * E_N + e] = flag_s;
}

// ---------------------------------------------------------------------------
extern "C" void kernel_launch(void* const* d_in, const int* in_sizes, int n_in,
                              void* d_out, int out_size) {
    const float* memory    = (const float*)d_in[0];
    const float* edge_feat = (const float*)d_in[1];
    const float* sel_dt    = (const float*)d_in[2];
    const float* sel_w     = (const float*)d_in[3];
    const float* time_w    = (const float*)d_in[4];
    const float* time_b    = (const float*)d_in[5];
    const float* fc1_w     = (const float*)d_in[6];
    const float* fc1_b     = (const float*)d_in[7];
    const float* ln1_g     = (const float*)d_in[8];
    const float* ln1_b     = (const float*)d_in[9];
    const float* fc2_w     = (const float*)d_in[10];
    const float* fc2_b     = (const float*)d_in[11];
    const float* fc1s_w    = (const float*)d_in[12];
    const float* fc1s_b    = (const float*)d_in[13];
    const float* bn_g      = (const float*)d_in[14];
    const float* bn_b      = (const float*)d_in[15];
    const float* bn_m      = (const float*)d_in[16];
    const float* bn_v      = (const float*)d_in[17];
    const float* fc2s_w    = (const float*)d_in[18];
    const float* fc2s_b    = (const float*)d_in[19];
    const int* source_nodes = (const int*)d_in[20];
    const int* sel_nodes    = (const int*)d_in[21];
    const int* sel_edges    = (const int*)d_in[22];
    float* out = (float*)d_out;

    cudaFuncSetAttribute(k_pre_h,   cudaFuncAttributeMaxDynamicSharedMemorySize, SMEM_128);
    cudaFuncSetAttribute(k_src1_h,  cudaFuncAttributeMaxDynamicSharedMemorySize, SMEM_64);
    cudaFuncSetAttribute(k_gemm2_h, cudaFuncAttributeMaxDynamicSharedMemorySize, SMEM_64);

    k_prep<<<1280, 256>>>(fc1_w, fc1s_w, fc2s_w, fc2_w);
    k_cheb<<<1, 512>>>(time_w, time_b, fc1_w);
    k_pre_h<<<(NNODES + 127) / 128, 256, SMEM_128>>>(memory, NNODES, 0);
    k_pre_h<<<(NEDGES + 127) / 128, 256, SMEM_128>>>(edge_feat, NEDGES, 1);
    k_src1_h<<<dim3((E_N + 63) / 64, 4), 256, SMEM_64>>>(
        memory, fc1s_b, bn_g, bn_b, bn_m, bn_v, source_nodes);
    k_branch<<<dim3(E_N, NT_), 128>>>(sel_dt, sel_w, fc1_b, ln1_g, ln1_b,
                                      sel_nodes, sel_edges);
    k_gemm2_h<<<GEMM2_SRC_BLOCKS + (NT_ * E_N) / 64, 256, SMEM_64>>>(
        fc2s_b, fc2_b, out);
}